// round 2
// baseline (speedup 1.0000x reference)
#include <cuda_runtime.h>
#include <math.h>

#define BB   2
#define TT   2048
#define HH   1024
#define HPP  64
#define NHM  8
#define NHD  8
#define KSEL 256           // TT / SPARSITY
#define QKV3 192           // 3*HP
#define NEGINF (-3.0e38f)

// ---------------- scratch (static __device__, no allocations) ----------------
__device__ __align__(16) float d_scores[BB*NHM*TT];
__device__ __align__(16) int   d_idx   [BB*NHM*KSEL];
__device__ __align__(16) float d_gates [BB*NHM*KSEL];
__device__ __align__(16) float d_mqkv  [BB*NHM*KSEL*QKV3];
__device__ __align__(16) float d_dqkv  [(size_t)BB*TT*NHD*QKV3];
__device__ __align__(16) float d_Y     [(size_t)BB*TT*1024];

// ---------------- zero Y ----------------
__global__ void zeroY_kernel() {
    size_t n4 = (size_t)BB*TT*1024/4;
    float4* p = (float4*)d_Y;
    float4 z = make_float4(0.f,0.f,0.f,0.f);
    for (size_t i = blockIdx.x*(size_t)blockDim.x + threadIdx.x; i < n4;
         i += (size_t)gridDim.x*blockDim.x)
        p[i] = z;
}

// ---------------- router scores: scores[b,n,t] = X[b,t,:] . rw[:,n] ----------
__global__ void router_kernel(const float* __restrict__ X,
                              const float* __restrict__ rw) {
    __shared__ float Xs[HH];
    int t = blockIdx.x, b = blockIdx.y;
    const float* xr = X + ((size_t)b*TT + t)*HH;
    for (int i = threadIdx.x; i < HH; i += blockDim.x) Xs[i] = xr[i];
    __syncthreads();
    int w = threadIdx.x >> 5, lane = threadIdx.x & 31;
    float s = 0.f;
    for (int h = lane; h < HH; h += 32) s += Xs[h] * rw[h*NHM + w];
    #pragma unroll
    for (int o = 16; o; o >>= 1) s += __shfl_down_sync(0xffffffffu, s, o);
    if (lane == 0) d_scores[((size_t)b*NHM + w)*TT + t] = s;
}

// ---------------- top-k (k=256 of 2048) + ascending index sort + gates -------
__global__ void topk_kernel() {
    __shared__ float vals[TT];
    __shared__ int   inds[TT];
    int bn = blockIdx.x, tid = threadIdx.x;
    const float* sc = d_scores + (size_t)bn*TT;
    for (int t = tid; t < TT; t += blockDim.x) { vals[t] = sc[t]; inds[t] = t; }
    __syncthreads();
    // full bitonic sort, descending by value (ties: smaller index first)
    for (int k = 2; k <= TT; k <<= 1)
        for (int j = k >> 1; j > 0; j >>= 1) {
            for (int t = tid; t < TT; t += blockDim.x) {
                int p = t ^ j;
                if (p > t) {
                    float va = vals[t], vb = vals[p];
                    int ia = inds[t], ib = inds[p];
                    bool a_first = (va > vb) || (va == vb && ia < ib);
                    bool desc = ((t & k) == 0);
                    if (desc ? !a_first : a_first) {
                        vals[t] = vb; vals[p] = va; inds[t] = ib; inds[p] = ia;
                    }
                }
            }
            __syncthreads();
        }
    // ascending sort of the 256 surviving indices
    for (int k = 2; k <= KSEL; k <<= 1)
        for (int j = k >> 1; j > 0; j >>= 1) {
            for (int t = tid; t < KSEL; t += blockDim.x) {
                int p = t ^ j;
                if (p > t) {
                    int ia = inds[t], ib = inds[p];
                    bool asc = ((t & k) == 0);
                    if (asc ? (ia > ib) : (ia < ib)) { inds[t] = ib; inds[p] = ia; }
                }
            }
            __syncthreads();
        }
    for (int kk = tid; kk < KSEL; kk += blockDim.x) {
        int id = inds[kk];
        d_idx[bn*KSEL + kk] = id;
        float s = sc[id];
        d_gates[bn*KSEL + kk] = 1.f / (1.f + expf(-s));
    }
}

// ---------------- MoSA qkv: per (b,n)  (256x1024 gathered) @ (1024x192) ------
__global__ __launch_bounds__(256) void mosa_qkv_kernel(
        const float* __restrict__ X, const float* __restrict__ W) {
    __shared__ float As[16][68];
    __shared__ float Bs[16][68];
    int bn = blockIdx.z, b = bn >> 3, n = bn & 7;
    int mt = blockIdx.y, nt = blockIdx.x;
    int tid = threadIdx.x, tx = tid & 15, ty = tid >> 4;
    int arow = tid >> 2, a4 = tid & 3;
    int brow = tid >> 4, b4 = tid & 15;
    int tok = d_idx[bn*KSEL + mt*64 + arow];
    const float* Ap = X + ((size_t)b*TT + tok)*HH + a4*4;
    const float* Bp = W + (size_t)n*QKV3 + nt*64 + b4*4;
    float acc[4][4] = {};
    for (int k0 = 0; k0 < HH; k0 += 16) {
        float4 av = *(const float4*)(Ap + k0);
        As[a4*4+0][arow] = av.x; As[a4*4+1][arow] = av.y;
        As[a4*4+2][arow] = av.z; As[a4*4+3][arow] = av.w;
        *(float4*)&Bs[brow][b4*4] =
            *(const float4*)(Bp + (size_t)(k0 + brow)*(NHM*QKV3));
        __syncthreads();
        #pragma unroll
        for (int kk = 0; kk < 16; kk++) {
            float4 a = *(const float4*)&As[kk][ty*4];
            float4 c = *(const float4*)&Bs[kk][tx*4];
            float ar[4] = {a.x,a.y,a.z,a.w};
            float br[4] = {c.x,c.y,c.z,c.w};
            #pragma unroll
            for (int i = 0; i < 4; i++)
                #pragma unroll
                for (int j = 0; j < 4; j++) acc[i][j] += ar[i]*br[j];
        }
        __syncthreads();
    }
    float* Op = d_mqkv + ((size_t)bn*KSEL + mt*64)*QKV3 + nt*64;
    #pragma unroll
    for (int i = 0; i < 4; i++)
        #pragma unroll
        for (int j = 0; j < 4; j++)
            Op[(size_t)(ty*4+i)*QKV3 + tx*4+j] = acc[i][j];
}

// ---------------- dense qkv: (4096x1024) @ (1024x1536) -----------------------
__global__ __launch_bounds__(256) void dense_qkv_kernel(
        const float* __restrict__ X, const float* __restrict__ W) {
    __shared__ float As[16][68];
    __shared__ float Bs[16][68];
    int col0 = blockIdx.x*64, row0 = blockIdx.y*64;
    int tid = threadIdx.x, tx = tid & 15, ty = tid >> 4;
    int arow = tid >> 2, a4 = tid & 3;
    int brow = tid >> 4, b4 = tid & 15;
    const float* Ap = X + (size_t)(row0 + arow)*HH + a4*4;
    const float* Bp = W + col0 + b4*4;
    float acc[4][4] = {};
    for (int k0 = 0; k0 < HH; k0 += 16) {
        float4 av = *(const float4*)(Ap + k0);
        As[a4*4+0][arow] = av.x; As[a4*4+1][arow] = av.y;
        As[a4*4+2][arow] = av.z; As[a4*4+3][arow] = av.w;
        *(float4*)&Bs[brow][b4*4] =
            *(const float4*)(Bp + (size_t)(k0 + brow)*(NHD*QKV3));
        __syncthreads();
        #pragma unroll
        for (int kk = 0; kk < 16; kk++) {
            float4 a = *(const float4*)&As[kk][ty*4];
            float4 c = *(const float4*)&Bs[kk][tx*4];
            float ar[4] = {a.x,a.y,a.z,a.w};
            float br[4] = {c.x,c.y,c.z,c.w};
            #pragma unroll
            for (int i = 0; i < 4; i++)
                #pragma unroll
                for (int j = 0; j < 4; j++) acc[i][j] += ar[i]*br[j];
        }
        __syncthreads();
    }
    float* Op = d_dqkv + (size_t)(row0)*(NHD*QKV3) + col0;
    #pragma unroll
    for (int i = 0; i < 4; i++)
        #pragma unroll
        for (int j = 0; j < 4; j++)
            Op[(size_t)(arow*0 + ty*4+i)*(NHD*QKV3) + tx*4+j] = acc[i][j];
}

// ---------------- RoPE ----------------
__device__ __forceinline__ float inv_freq(int j) {
    return (float)exp(-(double)j * (9.210340371976184 / 16.0)); // 10000^{-j/16}
}

__global__ void mosa_rope_kernel() {
    int g = blockIdx.x*blockDim.x + threadIdx.x;   // 65536 total
    int j  = g & 15;
    int kk = (g >> 4) & 255;
    int bn = g >> 12;
    float pos = (float)d_idx[bn*KSEL + kk];
    float ang = pos * inv_freq(j);
    float s, c; sincosf(ang, &s, &c);
    float* p = d_mqkv + ((size_t)bn*KSEL + kk)*QKV3;
    float x1 = p[j], x2 = p[16+j];
    p[j] = x1*c - x2*s;  p[16+j] = x1*s + x2*c;     // Q
    x1 = p[64+j]; x2 = p[80+j];
    p[64+j] = x1*c - x2*s; p[80+j] = x1*s + x2*c;   // K
}

__global__ void dense_rope_kernel() {
    int g = blockIdx.x*blockDim.x + threadIdx.x;   // 524288 total
    int j = g & 15;
    int n = (g >> 4) & 7;
    int t = (g >> 7) & 2047;
    int b = g >> 18;
    float ang = (float)t * inv_freq(j);
    float s, c; sincosf(ang, &s, &c);
    float* p = d_dqkv + ((size_t)(b*TT + t))*(NHD*QKV3) + n*QKV3;
    float x1 = p[j], x2 = p[16+j];
    p[j] = x1*c - x2*s;  p[16+j] = x1*s + x2*c;
    x1 = p[64+j]; x2 = p[80+j];
    p[64+j] = x1*c - x2*s; p[80+j] = x1*s + x2*c;
}

// ---------------- flash attention (shared body constants) --------------------
#define FA_STRIDE 68
#define FA_SMEM_FLOATS (4*64*FA_STRIDE + 3*64 + 256)
#define FA_SMEM_BYTES  (FA_SMEM_FLOATS*4)

__device__ __forceinline__ float fmax4(float a, float b, float c, float d) {
    return fmaxf(fmaxf(a,b), fmaxf(c,d));
}

// dense: grid (32, NHD, BB), 256 thr
__global__ __launch_bounds__(256) void dense_flash_kernel() {
    extern __shared__ float sm[];
    float* Qt = sm;                       // [d][row]
    float* Kt = Qt + 64*FA_STRIDE;        // [d][col]
    float* Vs = Kt + 64*FA_STRIDE;        // [kk][c]
    float* St = Vs + 64*FA_STRIDE;        // [col][row]
    float* msh = St + 64*FA_STRIDE;
    float* lsh = msh + 64;
    float* ash = lsh + 64;
    float* red = ash + 64;                // [64][4]

    int qt = blockIdx.x, n = blockIdx.y, b = blockIdx.z;
    int tid = threadIdx.x, tx = tid & 15, ty = tid >> 4;
    const int RS = NHD*QKV3;

    for (int s = tid; s < 1024; s += 256) {
        int r = s >> 4, c4 = s & 15;
        float4 v = *(const float4*)(d_dqkv +
            ((size_t)(b*TT + qt*64 + r))*RS + n*QKV3 + c4*4);
        Qt[(c4*4+0)*FA_STRIDE + r] = v.x; Qt[(c4*4+1)*FA_STRIDE + r] = v.y;
        Qt[(c4*4+2)*FA_STRIDE + r] = v.z; Qt[(c4*4+3)*FA_STRIDE + r] = v.w;
    }
    if (tid < 64) { msh[tid] = NEGINF; lsh[tid] = 0.f; }
    float o[4][4] = {};

    for (int kt = 0; kt <= qt; kt++) {
        __syncthreads();
        for (int s = tid; s < 1024; s += 256) {
            int r = s >> 4, c4 = s & 15;
            size_t base = ((size_t)(b*TT + kt*64 + r))*RS + n*QKV3;
            float4 kv = *(const float4*)(d_dqkv + base + 64 + c4*4);
            Kt[(c4*4+0)*FA_STRIDE + r] = kv.x; Kt[(c4*4+1)*FA_STRIDE + r] = kv.y;
            Kt[(c4*4+2)*FA_STRIDE + r] = kv.z; Kt[(c4*4+3)*FA_STRIDE + r] = kv.w;
            *(float4*)&Vs[r*FA_STRIDE + c4*4] =
                *(const float4*)(d_dqkv + base + 128 + c4*4);
        }
        __syncthreads();
        // S = Q K^T
        float s4[4][4] = {};
        #pragma unroll 8
        for (int d = 0; d < 64; d++) {
            float4 a = *(const float4*)&Qt[d*FA_STRIDE + ty*4];
            float4 c = *(const float4*)&Kt[d*FA_STRIDE + tx*4];
            float ar[4] = {a.x,a.y,a.z,a.w};
            float br[4] = {c.x,c.y,c.z,c.w};
            #pragma unroll
            for (int i = 0; i < 4; i++)
                #pragma unroll
                for (int j = 0; j < 4; j++) s4[i][j] += ar[i]*br[j];
        }
        bool diag = (kt == qt);
        #pragma unroll
        for (int i = 0; i < 4; i++)
            #pragma unroll
            for (int j = 0; j < 4; j++) {
                float sv = s4[i][j]*0.125f;
                if (diag && (tx*4+j) > (ty*4+i)) sv = NEGINF;
                St[(tx*4+j)*FA_STRIDE + ty*4+i] = sv;
            }
        __syncthreads();
        // online softmax
        int row = tid >> 2, seg = tid & 3;
        float mx = NEGINF;
        #pragma unroll
        for (int c = seg*16; c < seg*16+16; c++)
            mx = fmaxf(mx, St[c*FA_STRIDE + row]);
        red[row*4+seg] = mx;
        __syncthreads();
        if (seg == 0) {
            float mt_ = fmax4(red[row*4], red[row*4+1], red[row*4+2], red[row*4+3]);
            float mo = msh[row];
            float mn = fmaxf(mo, mt_);
            ash[row] = expf(mo - mn);
            msh[row] = mn;
        }
        __syncthreads();
        float mn = msh[row], ps = 0.f;
        #pragma unroll
        for (int c = seg*16; c < seg*16+16; c++) {
            float p = expf(St[c*FA_STRIDE + row] - mn);
            St[c*FA_STRIDE + row] = p;
            ps += p;
        }
        red[row*4+seg] = ps;
        __syncthreads();
        if (seg == 0)
            lsh[row] = lsh[row]*ash[row] +
                       red[row*4] + red[row*4+1] + red[row*4+2] + red[row*4+3];
        __syncthreads();
        // O = O*alpha + P V
        float al[4];
        #pragma unroll
        for (int i = 0; i < 4; i++) al[i] = ash[ty*4+i];
        #pragma unroll
        for (int i = 0; i < 4; i++)
            #pragma unroll
            for (int j = 0; j < 4; j++) o[i][j] *= al[i];
        #pragma unroll 8
        for (int kk = 0; kk < 64; kk++) {
            float4 a = *(const float4*)&St[kk*FA_STRIDE + ty*4];
            float4 c = *(const float4*)&Vs[kk*FA_STRIDE + tx*4];
            float ar[4] = {a.x,a.y,a.z,a.w};
            float br[4] = {c.x,c.y,c.z,c.w};
            #pragma unroll
            for (int i = 0; i < 4; i++)
                #pragma unroll
                for (int j = 0; j < 4; j++) o[i][j] += ar[i]*br[j];
        }
    }
    float li[4];
    #pragma unroll
    for (int i = 0; i < 4; i++) li[i] = 1.f/lsh[ty*4+i];
    #pragma unroll
    for (int i = 0; i < 4; i++)
        #pragma unroll
        for (int j = 0; j < 4; j++)
            d_Y[((size_t)(b*TT + qt*64 + ty*4+i))*1024 + 512 + n*64 + tx*4+j] =
                o[i][j]*li[i];
}

// mosa: grid (4, NHM, BB), 256 thr  — same body, different IO + gate + scatter
__global__ __launch_bounds__(256) void mosa_flash_kernel() {
    extern __shared__ float sm[];
    float* Qt = sm;
    float* Kt = Qt + 64*FA_STRIDE;
    float* Vs = Kt + 64*FA_STRIDE;
    float* St = Vs + 64*FA_STRIDE;
    float* msh = St + 64*FA_STRIDE;
    float* lsh = msh + 64;
    float* ash = lsh + 64;
    float* red = ash + 64;

    int qt = blockIdx.x, n = blockIdx.y, b = blockIdx.z;
    int bn = b*NHM + n;
    int tid = threadIdx.x, tx = tid & 15, ty = tid >> 4;

    for (int s = tid; s < 1024; s += 256) {
        int r = s >> 4, c4 = s & 15;
        float4 v = *(const float4*)(d_mqkv +
            ((size_t)(bn*KSEL + qt*64 + r))*QKV3 + c4*4);
        Qt[(c4*4+0)*FA_STRIDE + r] = v.x; Qt[(c4*4+1)*FA_STRIDE + r] = v.y;
        Qt[(c4*4+2)*FA_STRIDE + r] = v.z; Qt[(c4*4+3)*FA_STRIDE + r] = v.w;
    }
    if (tid < 64) { msh[tid] = NEGINF; lsh[tid] = 0.f; }
    float o[4][4] = {};

    for (int kt = 0; kt <= qt; kt++) {
        __syncthreads();
        for (int s = tid; s < 1024; s += 256) {
            int r = s >> 4, c4 = s & 15;
            size_t base = ((size_t)(bn*KSEL + kt*64 + r))*QKV3;
            float4 kv = *(const float4*)(d_mqkv + base + 64 + c4*4);
            Kt[(c4*4+0)*FA_STRIDE + r] = kv.x; Kt[(c4*4+1)*FA_STRIDE + r] = kv.y;
            Kt[(c4*4+2)*FA_STRIDE + r] = kv.z; Kt[(c4*4+3)*FA_STRIDE + r] = kv.w;
            *(float4*)&Vs[r*FA_STRIDE + c4*4] =
                *(const float4*)(d_mqkv + base + 128 + c4*4);
        }
        __syncthreads();
        float s4[4][4] = {};
        #pragma unroll 8
        for (int d = 0; d < 64; d++) {
            float4 a = *(const float4*)&Qt[d*FA_STRIDE + ty*4];
            float4 c = *(const float4*)&Kt[d*FA_STRIDE + tx*4];
            float ar[4] = {a.x,a.y,a.z,a.w};
            float br[4] = {c.x,c.y,c.z,c.w};
            #pragma unroll
            for (int i = 0; i < 4; i++)
                #pragma unroll
                for (int j = 0; j < 4; j++) s4[i][j] += ar[i]*br[j];
        }
        bool diag = (kt == qt);
        #pragma unroll
        for (int i = 0; i < 4; i++)
            #pragma unroll
            for (int j = 0; j < 4; j++) {
                float sv = s4[i][j]*0.125f;
                if (diag && (tx*4+j) > (ty*4+i)) sv = NEGINF;
                St[(tx*4+j)*FA_STRIDE + ty*4+i] = sv;
            }
        __syncthreads();
        int row = tid >> 2, seg = tid & 3;
        float mx = NEGINF;
        #pragma unroll
        for (int c = seg*16; c < seg*16+16; c++)
            mx = fmaxf(mx, St[c*FA_STRIDE + row]);
        red[row*4+seg] = mx;
        __syncthreads();
        if (seg == 0) {
            float mt_ = fmax4(red[row*4], red[row*4+1], red[row*4+2], red[row*4+3]);
            float mo = msh[row];
            float mn = fmaxf(mo, mt_);
            ash[row] = expf(mo - mn);
            msh[row] = mn;
        }
        __syncthreads();
        float mn = msh[row], ps = 0.f;
        #pragma unroll
        for (int c = seg*16; c < seg*16+16; c++) {
            float p = expf(St[c*FA_STRIDE + row] - mn);
            St[c*FA_STRIDE + row] = p;
            ps += p;
        }
        red[row*4+seg] = ps;
        __syncthreads();
        if (seg == 0)
            lsh[row] = lsh[row]*ash[row] +
                       red[row*4] + red[row*4+1] + red[row*4+2] + red[row*4+3];
        __syncthreads();
        float al[4];
        #pragma unroll
        for (int i = 0; i < 4; i++) al[i] = ash[ty*4+i];
        #pragma unroll
        for (int i = 0; i < 4; i++)
            #pragma unroll
            for (int j = 0; j < 4; j++) o[i][j] *= al[i];
        #pragma unroll 8
        for (int kk = 0; kk < 64; kk++) {
            float4 a = *(const float4*)&St[kk*FA_STRIDE + ty*4];
            float4 c = *(const float4*)&Vs[kk*FA_STRIDE + tx*4];
            float ar[4] = {a.x,a.y,a.z,a.w};
            float br[4] = {c.x,c.y,c.z,c.w};
            #pragma unroll
            for (int i = 0; i < 4; i++)
                #pragma unroll
                for (int j = 0; j < 4; j++) o[i][j] += ar[i]*br[j];
        }
    }
    #pragma unroll
    for (int i = 0; i < 4; i++) {
        int q = qt*64 + ty*4 + i;
        int tok = d_idx[bn*KSEL + q];
        float g = d_gates[bn*KSEL + q];
        float scale = g / lsh[ty*4+i];
        #pragma unroll
        for (int j = 0; j < 4; j++)
            d_Y[((size_t)(b*TT + tok))*1024 + n*64 + tx*4+j] = o[i][j]*scale;
    }
}

// ---------------- final GEMM: out = Y(4096x1024) @ [mosa_wo; dense_wo] -------
__global__ __launch_bounds__(256) void final_gemm_kernel(
        const float* __restrict__ mwo, const float* __restrict__ dwo,
        float* __restrict__ out) {
    __shared__ float As[16][68];
    __shared__ float Bs[16][68];
    int col0 = blockIdx.x*64, row0 = blockIdx.y*64;
    int tid = threadIdx.x, tx = tid & 15, ty = tid >> 4;
    int arow = tid >> 2, a4 = tid & 3;
    int brow = tid >> 4, b4 = tid & 15;
    const float* Ap = d_Y + (size_t)(row0 + arow)*1024 + a4*4;
    float acc[4][4] = {};
    for (int k0 = 0; k0 < 1024; k0 += 16) {
        float4 av = *(const float4*)(Ap + k0);
        As[a4*4+0][arow] = av.x; As[a4*4+1][arow] = av.y;
        As[a4*4+2][arow] = av.z; As[a4*4+3][arow] = av.w;
        int r = k0 + brow;
        const float* bp = (r < 512) ? (mwo + (size_t)r*1024)
                                    : (dwo + (size_t)(r-512)*1024);
        *(float4*)&Bs[brow][b4*4] = *(const float4*)(bp + col0 + b4*4);
        __syncthreads();
        #pragma unroll
        for (int kk = 0; kk < 16; kk++) {
            float4 a = *(const float4*)&As[kk][ty*4];
            float4 c = *(const float4*)&Bs[kk][tx*4];
            float ar[4] = {a.x,a.y,a.z,a.w};
            float br[4] = {c.x,c.y,c.z,c.w};
            #pragma unroll
            for (int i = 0; i < 4; i++)
                #pragma unroll
                for (int j = 0; j < 4; j++) acc[i][j] += ar[i]*br[j];
        }
        __syncthreads();
    }
    #pragma unroll
    for (int i = 0; i < 4; i++)
        #pragma unroll
        for (int j = 0; j < 4; j++)
            out[(size_t)(row0 + ty*4+i)*1024 + col0 + tx*4+j] = acc[i][j];
}

// ---------------- launch ----------------
extern "C" void kernel_launch(void* const* d_in, const int* in_sizes, int n_in,
                              void* d_out, int out_size) {
    const float* X     = (const float*)d_in[0];
    const float* rw    = (const float*)d_in[1];
    const float* mwqkv = (const float*)d_in[2];
    const float* mwo   = (const float*)d_in[3];
    const float* dwqkv = (const float*)d_in[4];
    const float* dwo   = (const float*)d_in[5];
    float* out = (float*)d_out;

    cudaFuncSetAttribute(dense_flash_kernel,
        cudaFuncAttributeMaxDynamicSharedMemorySize, FA_SMEM_BYTES);
    cudaFuncSetAttribute(mosa_flash_kernel,
        cudaFuncAttributeMaxDynamicSharedMemorySize, FA_SMEM_BYTES);

    zeroY_kernel<<<1024, 256>>>();
    router_kernel<<<dim3(TT, BB), 256>>>(X, rw);
    topk_kernel<<<BB*NHM, 1024>>>();
    mosa_qkv_kernel<<<dim3(3, 4, BB*NHM), 256>>>(X, mwqkv);
    mosa_rope_kernel<<<256, 256>>>();
    mosa_flash_kernel<<<dim3(4, NHM, BB), 256, FA_SMEM_BYTES>>>();
    dense_qkv_kernel<<<dim3(24, 64), 256>>>(X, dwqkv);
    dense_rope_kernel<<<2048, 256>>>();
    dense_flash_kernel<<<dim3(32, NHD, BB), 256, FA_SMEM_BYTES>>>();
    final_gemm_kernel<<<dim3(16, 64), 256>>>(mwo, dwo, out);
}

// round 5
// speedup vs baseline: 1.0989x; 1.0989x over previous
#include <cuda_runtime.h>
#include <mma.h>
#include <math.h>

using namespace nvcuda;

#define BB   2
#define TT   2048
#define HH   1024
#define HPP  64
#define NHM  8
#define NHD  8
#define KSEL 256           // TT / SPARSITY
#define QKV3 192           // 3*HP
#define NEGINF (-3.0e38f)

// ---------------- scratch (static __device__, no allocations) ----------------
__device__ __align__(128) float d_scores[BB*NHM*TT];
__device__ __align__(128) int   d_idx   [BB*NHM*KSEL];
__device__ __align__(128) float d_gates [BB*NHM*KSEL];
__device__ __align__(128) float d_mqkv  [BB*NHM*KSEL*QKV3];
__device__ __align__(128) float d_dqkv  [(size_t)BB*TT*NHD*QKV3];
__device__ __align__(128) float d_Y     [(size_t)BB*TT*1024];

// ---------------- zero Y ----------------
__global__ void zeroY_kernel() {
    size_t n4 = (size_t)BB*TT*1024/4;
    float4* p = (float4*)d_Y;
    float4 z = make_float4(0.f,0.f,0.f,0.f);
    for (size_t i = blockIdx.x*(size_t)blockDim.x + threadIdx.x; i < n4;
         i += (size_t)gridDim.x*blockDim.x)
        p[i] = z;
}

// ---------------- router scores: scores[b,n,t] = X[b,t,:] . rw[:,n] ----------
__global__ void router_kernel(const float* __restrict__ X,
                              const float* __restrict__ rw) {
    __shared__ float Xs[HH];
    int t = blockIdx.x, b = blockIdx.y;
    const float* xr = X + ((size_t)b*TT + t)*HH;
    for (int i = threadIdx.x; i < HH; i += blockDim.x) Xs[i] = xr[i];
    __syncthreads();
    int w = threadIdx.x >> 5, lane = threadIdx.x & 31;
    float s = 0.f;
    for (int h = lane; h < HH; h += 32) s += Xs[h] * rw[h*NHM + w];
    #pragma unroll
    for (int o = 16; o; o >>= 1) s += __shfl_down_sync(0xffffffffu, s, o);
    if (lane == 0) d_scores[((size_t)b*NHM + w)*TT + t] = s;
}

// ---------------- top-k (k=256 of 2048) + ascending index sort + gates -------
__global__ void topk_kernel() {
    __shared__ float vals[TT];
    __shared__ int   inds[TT];
    int bn = blockIdx.x, tid = threadIdx.x;
    const float* sc = d_scores + (size_t)bn*TT;
    for (int t = tid; t < TT; t += blockDim.x) { vals[t] = sc[t]; inds[t] = t; }
    __syncthreads();
    for (int k = 2; k <= TT; k <<= 1)
        for (int j = k >> 1; j > 0; j >>= 1) {
            for (int t = tid; t < TT; t += blockDim.x) {
                int p = t ^ j;
                if (p > t) {
                    float va = vals[t], vb = vals[p];
                    int ia = inds[t], ib = inds[p];
                    bool a_first = (va > vb) || (va == vb && ia < ib);
                    bool desc = ((t & k) == 0);
                    if (desc ? !a_first : a_first) {
                        vals[t] = vb; vals[p] = va; inds[t] = ib; inds[p] = ia;
                    }
                }
            }
            __syncthreads();
        }
    for (int k = 2; k <= KSEL; k <<= 1)
        for (int j = k >> 1; j > 0; j >>= 1) {
            for (int t = tid; t < KSEL; t += blockDim.x) {
                int p = t ^ j;
                if (p > t) {
                    int ia = inds[t], ib = inds[p];
                    bool asc = ((t & k) == 0);
                    if (asc ? (ia > ib) : (ia < ib)) { inds[t] = ib; inds[p] = ia; }
                }
            }
            __syncthreads();
        }
    for (int kk = tid; kk < KSEL; kk += blockDim.x) {
        int id = inds[kk];
        d_idx[bn*KSEL + kk] = id;
        float s = sc[id];
        d_gates[bn*KSEL + kk] = 1.f / (1.f + expf(-s));
    }
}

// ---------------- MoSA qkv: per (b,n)  (256x1024 gathered) @ (1024x192) ------
__global__ __launch_bounds__(256) void mosa_qkv_kernel(
        const float* __restrict__ X, const float* __restrict__ W) {
    __shared__ float As[16][68];
    __shared__ float Bs[16][68];
    int bn = blockIdx.z, b = bn >> 3, n = bn & 7;
    int mt = blockIdx.y, nt = blockIdx.x;
    int tid = threadIdx.x, tx = tid & 15, ty = tid >> 4;
    int arow = tid >> 2, a4 = tid & 3;
    int brow = tid >> 4, b4 = tid & 15;
    int tok = d_idx[bn*KSEL + mt*64 + arow];
    const float* Ap = X + ((size_t)b*TT + tok)*HH + a4*4;
    const float* Bp = W + (size_t)n*QKV3 + nt*64 + b4*4;
    float acc[4][4] = {};
    for (int k0 = 0; k0 < HH; k0 += 16) {
        float4 av = *(const float4*)(Ap + k0);
        As[a4*4+0][arow] = av.x; As[a4*4+1][arow] = av.y;
        As[a4*4+2][arow] = av.z; As[a4*4+3][arow] = av.w;
        *(float4*)&Bs[brow][b4*4] =
            *(const float4*)(Bp + (size_t)(k0 + brow)*(NHM*QKV3));
        __syncthreads();
        #pragma unroll
        for (int kk = 0; kk < 16; kk++) {
            float4 a = *(const float4*)&As[kk][ty*4];
            float4 c = *(const float4*)&Bs[kk][tx*4];
            float ar[4] = {a.x,a.y,a.z,a.w};
            float br[4] = {c.x,c.y,c.z,c.w};
            #pragma unroll
            for (int i = 0; i < 4; i++)
                #pragma unroll
                for (int j = 0; j < 4; j++) acc[i][j] += ar[i]*br[j];
        }
        __syncthreads();
    }
    float* Op = d_mqkv + ((size_t)bn*KSEL + mt*64)*QKV3 + nt*64;
    #pragma unroll
    for (int i = 0; i < 4; i++)
        #pragma unroll
        for (int j = 0; j < 4; j++)
            Op[(size_t)(ty*4+i)*QKV3 + tx*4+j] = acc[i][j];
}

// ---------------- dense qkv: (4096x1024) @ (1024x1536)  [fp32, known-good] ---
__global__ __launch_bounds__(256) void dense_qkv_kernel(
        const float* __restrict__ X, const float* __restrict__ W) {
    __shared__ float As[16][68];
    __shared__ float Bs[16][68];
    int col0 = blockIdx.x*64, row0 = blockIdx.y*64;
    int tid = threadIdx.x, tx = tid & 15, ty = tid >> 4;
    int arow = tid >> 2, a4 = tid & 3;
    int brow = tid >> 4, b4 = tid & 15;
    const float* Ap = X + (size_t)(row0 + arow)*HH + a4*4;
    const float* Bp = W + col0 + b4*4;
    float acc[4][4] = {};
    for (int k0 = 0; k0 < HH; k0 += 16) {
        float4 av = *(const float4*)(Ap + k0);
        As[a4*4+0][arow] = av.x; As[a4*4+1][arow] = av.y;
        As[a4*4+2][arow] = av.z; As[a4*4+3][arow] = av.w;
        *(float4*)&Bs[brow][b4*4] =
            *(const float4*)(Bp + (size_t)(k0 + brow)*(NHD*QKV3));
        __syncthreads();
        #pragma unroll
        for (int kk = 0; kk < 16; kk++) {
            float4 a = *(const float4*)&As[kk][ty*4];
            float4 c = *(const float4*)&Bs[kk][tx*4];
            float ar[4] = {a.x,a.y,a.z,a.w};
            float br[4] = {c.x,c.y,c.z,c.w};
            #pragma unroll
            for (int i = 0; i < 4; i++)
                #pragma unroll
                for (int j = 0; j < 4; j++) acc[i][j] += ar[i]*br[j];
        }
        __syncthreads();
    }
    float* Op = d_dqkv + (size_t)(row0)*(NHD*QKV3) + col0;
    #pragma unroll
    for (int i = 0; i < 4; i++)
        #pragma unroll
        for (int j = 0; j < 4; j++)
            Op[(size_t)(ty*4+i)*(NHD*QKV3) + tx*4+j] = acc[i][j];
}

// ================= final GEMM via tf32 WMMA ==================================
// out[4096,1024] = Y[4096,1024] @ W[1024,1024], W = [mwo(512x1024); dwo(512x1024)]
// 128x128 block tile, BK=16, 256 threads (8 warps, 4x2), warp tile 32x64.
#define AS_STRIDE 20
#define BS_STRIDE 136

__global__ __launch_bounds__(256) void final_wmma_kernel(
        const float* __restrict__ mwo, const float* __restrict__ dwo,
        float* __restrict__ out)
{
    __shared__ __align__(32) float As[128*AS_STRIDE];
    __shared__ __align__(32) float Bs[16*BS_STRIDE];
    const int K = 1024, lda = 1024, ldb = 1024, ldc = 1024;
    int tid = threadIdx.x;
    int warp = tid >> 5;
    int wm = warp >> 1;          // 0..3
    int wn = warp & 1;           // 0..1
    int row0 = blockIdx.y*128;
    int col0 = blockIdx.x*128;

    int arow = tid >> 2;         // 0..63  (rows arow, arow+64)
    int acol = (tid & 3) * 4;
    int brow = tid >> 5;         // 0..7   (rows brow, brow+8)
    int bcol = (tid & 31) * 4;

    const float* Ag = d_Y + (size_t)(row0 + arow)*lda + acol;

    float4 a_stage0, a_stage1, b_stage0, b_stage1;

    auto load_tile = [&](int k0) {
        a_stage0 = *(const float4*)(Ag + k0);
        a_stage1 = *(const float4*)(Ag + (size_t)64*lda + k0);
        int r0 = k0 + brow, r1 = k0 + brow + 8;
        const float* p0 = (r0 < 512) ? (mwo + (size_t)r0*ldb)
                                     : (dwo + (size_t)(r0 - 512)*ldb);
        const float* p1 = (r1 < 512) ? (mwo + (size_t)r1*ldb)
                                     : (dwo + (size_t)(r1 - 512)*ldb);
        b_stage0 = *(const float4*)(p0 + col0 + bcol);
        b_stage1 = *(const float4*)(p1 + col0 + bcol);
    };
    auto store_tile = [&]() {
        *(float4*)&As[arow*AS_STRIDE + acol] = a_stage0;
        *(float4*)&As[(arow+64)*AS_STRIDE + acol] = a_stage1;
        *(float4*)&Bs[brow*BS_STRIDE + bcol] = b_stage0;
        *(float4*)&Bs[(brow+8)*BS_STRIDE + bcol] = b_stage1;
    };

    wmma::fragment<wmma::accumulator, 16, 16, 8, float> acc[2][4];
    #pragma unroll
    for (int mi = 0; mi < 2; mi++)
        #pragma unroll
        for (int ni = 0; ni < 4; ni++)
            wmma::fill_fragment(acc[mi][ni], 0.0f);

    load_tile(0);
    store_tile();
    __syncthreads();

    const int ktiles = K/16;
    #pragma unroll 1
    for (int kt = 0; kt < ktiles; kt++) {
        bool more = (kt + 1 < ktiles);
        if (more) load_tile((kt+1)*16);
        #pragma unroll
        for (int ks = 0; ks < 2; ks++) {
            wmma::fragment<wmma::matrix_a, 16, 16, 8,
                           wmma::precision::tf32, wmma::row_major> af[2];
            wmma::fragment<wmma::matrix_b, 16, 16, 8,
                           wmma::precision::tf32, wmma::row_major> bf[4];
            #pragma unroll
            for (int mi = 0; mi < 2; mi++) {
                wmma::load_matrix_sync(af[mi],
                    &As[(wm*32 + mi*16)*AS_STRIDE + ks*8], AS_STRIDE);
                #pragma unroll
                for (int e = 0; e < af[mi].num_elements; e++)
                    af[mi].x[e] = wmma::__float_to_tf32(af[mi].x[e]);
            }
            #pragma unroll
            for (int ni = 0; ni < 4; ni++) {
                wmma::load_matrix_sync(bf[ni],
                    &Bs[(ks*8)*BS_STRIDE + wn*64 + ni*16], BS_STRIDE);
                #pragma unroll
                for (int e = 0; e < bf[ni].num_elements; e++)
                    bf[ni].x[e] = wmma::__float_to_tf32(bf[ni].x[e]);
            }
            #pragma unroll
            for (int mi = 0; mi < 2; mi++)
                #pragma unroll
                for (int ni = 0; ni < 4; ni++)
                    wmma::mma_sync(acc[mi][ni], af[mi], bf[ni], acc[mi][ni]);
        }
        if (more) {
            __syncthreads();
            store_tile();
            __syncthreads();
        }
    }

    #pragma unroll
    for (int mi = 0; mi < 2; mi++)
        #pragma unroll
        for (int ni = 0; ni < 4; ni++)
            wmma::store_matrix_sync(
                &out[(size_t)(row0 + wm*32 + mi*16)*ldc + col0 + wn*64 + ni*16],
                acc[mi][ni], ldc, wmma::mem_row_major);
}

// ---------------- RoPE ----------------
__device__ __forceinline__ float inv_freq(int j) {
    return (float)exp(-(double)j * (9.210340371976184 / 16.0)); // 10000^{-j/16}
}

__global__ void mosa_rope_kernel() {
    int g = blockIdx.x*blockDim.x + threadIdx.x;
    int j  = g & 15;
    int kk = (g >> 4) & 255;
    int bn = g >> 12;
    float pos = (float)d_idx[bn*KSEL + kk];
    float ang = pos * inv_freq(j);
    float s, c; sincosf(ang, &s, &c);
    float* p = d_mqkv + ((size_t)bn*KSEL + kk)*QKV3;
    float x1 = p[j], x2 = p[16+j];
    p[j] = x1*c - x2*s;  p[16+j] = x1*s + x2*c;
    x1 = p[64+j]; x2 = p[80+j];
    p[64+j] = x1*c - x2*s; p[80+j] = x1*s + x2*c;
}

__global__ void dense_rope_kernel() {
    int g = blockIdx.x*blockDim.x + threadIdx.x;
    int j = g & 15;
    int n = (g >> 4) & 7;
    int t = (g >> 7) & 2047;
    int b = g >> 18;
    float ang = (float)t * inv_freq(j);
    float s, c; sincosf(ang, &s, &c);
    float* p = d_dqkv + ((size_t)(b*TT + t))*(NHD*QKV3) + n*QKV3;
    float x1 = p[j], x2 = p[16+j];
    p[j] = x1*c - x2*s;  p[16+j] = x1*s + x2*c;
    x1 = p[64+j]; x2 = p[80+j];
    p[64+j] = x1*c - x2*s; p[80+j] = x1*s + x2*c;
}

// ---------------- flash attention ----------------
#define FA_STRIDE 68
#define FA_SMEM_FLOATS (4*64*FA_STRIDE + 3*64 + 256)
#define FA_SMEM_BYTES  (FA_SMEM_FLOATS*4)

__device__ __forceinline__ float fmax4(float a, float b, float c, float d) {
    return fmaxf(fmaxf(a,b), fmaxf(c,d));
}

__global__ __launch_bounds__(256) void dense_flash_kernel() {
    extern __shared__ float sm[];
    float* Qt = sm;
    float* Kt = Qt + 64*FA_STRIDE;
    float* Vs = Kt + 64*FA_STRIDE;
    float* St = Vs + 64*FA_STRIDE;
    float* msh = St + 64*FA_STRIDE;
    float* lsh = msh + 64;
    float* ash = lsh + 64;
    float* red = ash + 64;

    int qt = blockIdx.x, n = blockIdx.y, b = blockIdx.z;
    int tid = threadIdx.x, tx = tid & 15, ty = tid >> 4;
    const int RS = NHD*QKV3;

    for (int s = tid; s < 1024; s += 256) {
        int r = s >> 4, c4 = s & 15;
        float4 v = *(const float4*)(d_dqkv +
            ((size_t)(b*TT + qt*64 + r))*RS + n*QKV3 + c4*4);
        Qt[(c4*4+0)*FA_STRIDE + r] = v.x; Qt[(c4*4+1)*FA_STRIDE + r] = v.y;
        Qt[(c4*4+2)*FA_STRIDE + r] = v.z; Qt[(c4*4+3)*FA_STRIDE + r] = v.w;
    }
    if (tid < 64) { msh[tid] = NEGINF; lsh[tid] = 0.f; }
    float o[4][4] = {};

    for (int kt = 0; kt <= qt; kt++) {
        __syncthreads();
        for (int s = tid; s < 1024; s += 256) {
            int r = s >> 4, c4 = s & 15;
            size_t base = ((size_t)(b*TT + kt*64 + r))*RS + n*QKV3;
            float4 kv = *(const float4*)(d_dqkv + base + 64 + c4*4);
            Kt[(c4*4+0)*FA_STRIDE + r] = kv.x; Kt[(c4*4+1)*FA_STRIDE + r] = kv.y;
            Kt[(c4*4+2)*FA_STRIDE + r] = kv.z; Kt[(c4*4+3)*FA_STRIDE + r] = kv.w;
            *(float4*)&Vs[r*FA_STRIDE + c4*4] =
                *(const float4*)(d_dqkv + base + 128 + c4*4);
        }
        __syncthreads();
        float s4[4][4] = {};
        #pragma unroll 8
        for (int d = 0; d < 64; d++) {
            float4 a = *(const float4*)&Qt[d*FA_STRIDE + ty*4];
            float4 c = *(const float4*)&Kt[d*FA_STRIDE + tx*4];
            float ar[4] = {a.x,a.y,a.z,a.w};
            float br[4] = {c.x,c.y,c.z,c.w};
            #pragma unroll
            for (int i = 0; i < 4; i++)
                #pragma unroll
                for (int j = 0; j < 4; j++) s4[i][j] += ar[i]*br[j];
        }
        bool diag = (kt == qt);
        #pragma unroll
        for (int i = 0; i < 4; i++)
            #pragma unroll
            for (int j = 0; j < 4; j++) {
                float sv = s4[i][j]*0.125f;
                if (diag && (tx*4+j) > (ty*4+i)) sv = NEGINF;
                St[(tx*4+j)*FA_STRIDE + ty*4+i] = sv;
            }
        __syncthreads();
        int row = tid >> 2, seg = tid & 3;
        float mx = NEGINF;
        #pragma unroll
        for (int c = seg*16; c < seg*16+16; c++)
            mx = fmaxf(mx, St[c*FA_STRIDE + row]);
        red[row*4+seg] = mx;
        __syncthreads();
        if (seg == 0) {
            float mt_ = fmax4(red[row*4], red[row*4+1], red[row*4+2], red[row*4+3]);
            float mo = msh[row];
            float mn = fmaxf(mo, mt_);
            ash[row] = expf(mo - mn);
            msh[row] = mn;
        }
        __syncthreads();
        float mn = msh[row], ps = 0.f;
        #pragma unroll
        for (int c = seg*16; c < seg*16+16; c++) {
            float p = expf(St[c*FA_STRIDE + row] - mn);
            St[c*FA_STRIDE + row] = p;
            ps += p;
        }
        red[row*4+seg] = ps;
        __syncthreads();
        if (seg == 0)
            lsh[row] = lsh[row]*ash[row] +
                       red[row*4] + red[row*4+1] + red[row*4+2] + red[row*4+3];
        __syncthreads();
        float al[4];
        #pragma unroll
        for (int i = 0; i < 4; i++) al[i] = ash[ty*4+i];
        #pragma unroll
        for (int i = 0; i < 4; i++)
            #pragma unroll
            for (int j = 0; j < 4; j++) o[i][j] *= al[i];
        #pragma unroll 8
        for (int kk = 0; kk < 64; kk++) {
            float4 a = *(const float4*)&St[kk*FA_STRIDE + ty*4];
            float4 c = *(const float4*)&Vs[kk*FA_STRIDE + tx*4];
            float ar[4] = {a.x,a.y,a.z,a.w};
            float br[4] = {c.x,c.y,c.z,c.w};
            #pragma unroll
            for (int i = 0; i < 4; i++)
                #pragma unroll
                for (int j = 0; j < 4; j++) o[i][j] += ar[i]*br[j];
        }
    }
    float li[4];
    #pragma unroll
    for (int i = 0; i < 4; i++) li[i] = 1.f/lsh[ty*4+i];
    #pragma unroll
    for (int i = 0; i < 4; i++)
        #pragma unroll
        for (int j = 0; j < 4; j++)
            d_Y[((size_t)(b*TT + qt*64 + ty*4+i))*1024 + 512 + n*64 + tx*4+j] =
                o[i][j]*li[i];
}

__global__ __launch_bounds__(256) void mosa_flash_kernel() {
    extern __shared__ float sm[];
    float* Qt = sm;
    float* Kt = Qt + 64*FA_STRIDE;
    float* Vs = Kt + 64*FA_STRIDE;
    float* St = Vs + 64*FA_STRIDE;
    float* msh = St + 64*FA_STRIDE;
    float* lsh = msh + 64;
    float* ash = lsh + 64;
    float* red = ash + 64;

    int qt = blockIdx.x, n = blockIdx.y, b = blockIdx.z;
    int bn = b*NHM + n;
    int tid = threadIdx.x, tx = tid & 15, ty = tid >> 4;

    for (int s = tid; s < 1024; s += 256) {
        int r = s >> 4, c4 = s & 15;
        float4 v = *(const float4*)(d_mqkv +
            ((size_t)(bn*KSEL + qt*64 + r))*QKV3 + c4*4);
        Qt[(c4*4+0)*FA_STRIDE + r] = v.x; Qt[(c4*4+1)*FA_STRIDE + r] = v.y;
        Qt[(c4*4+2)*FA_STRIDE + r] = v.z; Qt[(c4*4+3)*FA_STRIDE + r] = v.w;
    }
    if (tid < 64) { msh[tid] = NEGINF; lsh[tid] = 0.f; }
    float o[4][4] = {};

    for (int kt = 0; kt <= qt; kt++) {
        __syncthreads();
        for (int s = tid; s < 1024; s += 256) {
            int r = s >> 4, c4 = s & 15;
            size_t base = ((size_t)(bn*KSEL + kt*64 + r))*QKV3;
            float4 kv = *(const float4*)(d_mqkv + base + 64 + c4*4);
            Kt[(c4*4+0)*FA_STRIDE + r] = kv.x; Kt[(c4*4+1)*FA_STRIDE + r] = kv.y;
            Kt[(c4*4+2)*FA_STRIDE + r] = kv.z; Kt[(c4*4+3)*FA_STRIDE + r] = kv.w;
            *(float4*)&Vs[r*FA_STRIDE + c4*4] =
                *(const float4*)(d_mqkv + base + 128 + c4*4);
        }
        __syncthreads();
        float s4[4][4] = {};
        #pragma unroll 8
        for (int d = 0; d < 64; d++) {
            float4 a = *(const float4*)&Qt[d*FA_STRIDE + ty*4];
            float4 c = *(const float4*)&Kt[d*FA_STRIDE + tx*4];
            float ar[4] = {a.x,a.y,a.z,a.w};
            float br[4] = {c.x,c.y,c.z,c.w};
            #pragma unroll
            for (int i = 0; i < 4; i++)
                #pragma unroll
                for (int j = 0; j < 4; j++) s4[i][j] += ar[i]*br[j];
        }
        bool diag = (kt == qt);
        #pragma unroll
        for (int i = 0; i < 4; i++)
            #pragma unroll
            for (int j = 0; j < 4; j++) {
                float sv = s4[i][j]*0.125f;
                if (diag && (tx*4+j) > (ty*4+i)) sv = NEGINF;
                St[(tx*4+j)*FA_STRIDE + ty*4+i] = sv;
            }
        __syncthreads();
        int row = tid >> 2, seg = tid & 3;
        float mx = NEGINF;
        #pragma unroll
        for (int c = seg*16; c < seg*16+16; c++)
            mx = fmaxf(mx, St[c*FA_STRIDE + row]);
        red[row*4+seg] = mx;
        __syncthreads();
        if (seg == 0) {
            float mt_ = fmax4(red[row*4], red[row*4+1], red[row*4+2], red[row*4+3]);
            float mo = msh[row];
            float mn = fmaxf(mo, mt_);
            ash[row] = expf(mo - mn);
            msh[row] = mn;
        }
        __syncthreads();
        float mn = msh[row], ps = 0.f;
        #pragma unroll
        for (int c = seg*16; c < seg*16+16; c++) {
            float p = expf(St[c*FA_STRIDE + row] - mn);
            St[c*FA_STRIDE + row] = p;
            ps += p;
        }
        red[row*4+seg] = ps;
        __syncthreads();
        if (seg == 0)
            lsh[row] = lsh[row]*ash[row] +
                       red[row*4] + red[row*4+1] + red[row*4+2] + red[row*4+3];
        __syncthreads();
        float al[4];
        #pragma unroll
        for (int i = 0; i < 4; i++) al[i] = ash[ty*4+i];
        #pragma unroll
        for (int i = 0; i < 4; i++)
            #pragma unroll
            for (int j = 0; j < 4; j++) o[i][j] *= al[i];
        #pragma unroll 8
        for (int kk = 0; kk < 64; kk++) {
            float4 a = *(const float4*)&St[kk*FA_STRIDE + ty*4];
            float4 c = *(const float4*)&Vs[kk*FA_STRIDE + tx*4];
            float ar[4] = {a.x,a.y,a.z,a.w};
            float br[4] = {c.x,c.y,c.z,c.w};
            #pragma unroll
            for (int i = 0; i < 4; i++)
                #pragma unroll
                for (int j = 0; j < 4; j++) o[i][j] += ar[i]*br[j];
        }
    }
    #pragma unroll
    for (int i = 0; i < 4; i++) {
        int q = qt*64 + ty*4 + i;
        int tok = d_idx[bn*KSEL + q];
        float g = d_gates[bn*KSEL + q];
        float scale = g / lsh[ty*4+i];
        #pragma unroll
        for (int j = 0; j < 4; j++)
            d_Y[((size_t)(b*TT + tok))*1024 + n*64 + tx*4+j] = o[i][j]*scale;
    }
}

// ---------------- launch ----------------
extern "C" void kernel_launch(void* const* d_in, const int* in_sizes, int n_in,
                              void* d_out, int out_size) {
    const float* X     = (const float*)d_in[0];
    const float* rw    = (const float*)d_in[1];
    const float* mwqkv = (const float*)d_in[2];
    const float* mwo   = (const float*)d_in[3];
    const float* dwqkv = (const float*)d_in[4];
    const float* dwo   = (const float*)d_in[5];
    float* out = (float*)d_out;

    cudaFuncSetAttribute(dense_flash_kernel,
        cudaFuncAttributeMaxDynamicSharedMemorySize, FA_SMEM_BYTES);
    cudaFuncSetAttribute(mosa_flash_kernel,
        cudaFuncAttributeMaxDynamicSharedMemorySize, FA_SMEM_BYTES);

    zeroY_kernel<<<1024, 256>>>();
    router_kernel<<<dim3(TT, BB), 256>>>(X, rw);
    topk_kernel<<<BB*NHM, 1024>>>();
    mosa_qkv_kernel<<<dim3(3, 4, BB*NHM), 256>>>(X, mwqkv);
    mosa_rope_kernel<<<256, 256>>>();
    mosa_flash_kernel<<<dim3(4, NHM, BB), 256, FA_SMEM_BYTES>>>();
    dense_qkv_kernel<<<dim3(24, 64), 256>>>(X, dwqkv);   // fp32, known-good
    dense_rope_kernel<<<2048, 256>>>();
    dense_flash_kernel<<<dim3(32, NHD, BB), 256, FA_SMEM_BYTES>>>();
    final_wmma_kernel<<<dim3(8, 32), 256>>>(mwo, dwo, out);  // tf32 wmma bisect
}

// round 6
// speedup vs baseline: 1.2587x; 1.1454x over previous
#include <cuda_runtime.h>
#include <mma.h>
#include <math.h>

using namespace nvcuda;

#define BB   2
#define TT   2048
#define HH   1024
#define HPP  64
#define NHM  8
#define NHD  8
#define KSEL 256           // TT / SPARSITY
#define QKV3 192           // 3*HP
#define NEGINF (-3.0e38f)

// ---------------- scratch (static __device__, no allocations) ----------------
__device__ __align__(128) float d_scores[BB*NHM*TT];
__device__ __align__(128) int   d_idx   [BB*NHM*KSEL];
__device__ __align__(128) float d_gates [BB*NHM*KSEL];
__device__ __align__(128) float d_mqkv  [BB*NHM*KSEL*QKV3];
__device__ __align__(128) float d_dqkv  [(size_t)BB*TT*NHD*QKV3];
__device__ __align__(128) float d_Y     [(size_t)BB*TT*1024];

// ---------------- zero Y ----------------
__global__ void zeroY_kernel() {
    size_t n4 = (size_t)BB*TT*1024/4;
    float4* p = (float4*)d_Y;
    float4 z = make_float4(0.f,0.f,0.f,0.f);
    for (size_t i = blockIdx.x*(size_t)blockDim.x + threadIdx.x; i < n4;
         i += (size_t)gridDim.x*blockDim.x)
        p[i] = z;
}

// ---------------- router scores: scores[b,n,t] = X[b,t,:] . rw[:,n] ----------
__global__ void router_kernel(const float* __restrict__ X,
                              const float* __restrict__ rw) {
    __shared__ float Xs[HH];
    int t = blockIdx.x, b = blockIdx.y;
    const float* xr = X + ((size_t)b*TT + t)*HH;
    for (int i = threadIdx.x; i < HH; i += blockDim.x) Xs[i] = xr[i];
    __syncthreads();
    int w = threadIdx.x >> 5, lane = threadIdx.x & 31;
    float s = 0.f;
    for (int h = lane; h < HH; h += 32) s += Xs[h] * rw[h*NHM + w];
    #pragma unroll
    for (int o = 16; o; o >>= 1) s += __shfl_down_sync(0xffffffffu, s, o);
    if (lane == 0) d_scores[((size_t)b*NHM + w)*TT + t] = s;
}

// ---------------- top-k (k=256 of 2048) + ascending index sort + gates -------
__global__ void topk_kernel() {
    __shared__ float vals[TT];
    __shared__ int   inds[TT];
    int bn = blockIdx.x, tid = threadIdx.x;
    const float* sc = d_scores + (size_t)bn*TT;
    for (int t = tid; t < TT; t += blockDim.x) { vals[t] = sc[t]; inds[t] = t; }
    __syncthreads();
    for (int k = 2; k <= TT; k <<= 1)
        for (int j = k >> 1; j > 0; j >>= 1) {
            for (int t = tid; t < TT; t += blockDim.x) {
                int p = t ^ j;
                if (p > t) {
                    float va = vals[t], vb = vals[p];
                    int ia = inds[t], ib = inds[p];
                    bool a_first = (va > vb) || (va == vb && ia < ib);
                    bool desc = ((t & k) == 0);
                    if (desc ? !a_first : a_first) {
                        vals[t] = vb; vals[p] = va; inds[t] = ib; inds[p] = ia;
                    }
                }
            }
            __syncthreads();
        }
    for (int k = 2; k <= KSEL; k <<= 1)
        for (int j = k >> 1; j > 0; j >>= 1) {
            for (int t = tid; t < KSEL; t += blockDim.x) {
                int p = t ^ j;
                if (p > t) {
                    int ia = inds[t], ib = inds[p];
                    bool asc = ((t & k) == 0);
                    if (asc ? (ia > ib) : (ia < ib)) { inds[t] = ib; inds[p] = ia; }
                }
            }
            __syncthreads();
        }
    for (int kk = tid; kk < KSEL; kk += blockDim.x) {
        int id = inds[kk];
        d_idx[bn*KSEL + kk] = id;
        float s = sc[id];
        d_gates[bn*KSEL + kk] = 1.f / (1.f + expf(-s));
    }
}

// ---------------- MoSA qkv: per (b,n)  (256x1024 gathered) @ (1024x192) ------
__global__ __launch_bounds__(256) void mosa_qkv_kernel(
        const float* __restrict__ X, const float* __restrict__ W) {
    __shared__ float As[16][68];
    __shared__ float Bs[16][68];
    int bn = blockIdx.z, b = bn >> 3, n = bn & 7;
    int mt = blockIdx.y, nt = blockIdx.x;
    int tid = threadIdx.x, tx = tid & 15, ty = tid >> 4;
    int arow = tid >> 2, a4 = tid & 3;
    int brow = tid >> 4, b4 = tid & 15;
    int tok = d_idx[bn*KSEL + mt*64 + arow];
    const float* Ap = X + ((size_t)b*TT + tok)*HH + a4*4;
    const float* Bp = W + (size_t)n*QKV3 + nt*64 + b4*4;
    float acc[4][4] = {};
    for (int k0 = 0; k0 < HH; k0 += 16) {
        float4 av = *(const float4*)(Ap + k0);
        As[a4*4+0][arow] = av.x; As[a4*4+1][arow] = av.y;
        As[a4*4+2][arow] = av.z; As[a4*4+3][arow] = av.w;
        *(float4*)&Bs[brow][b4*4] =
            *(const float4*)(Bp + (size_t)(k0 + brow)*(NHM*QKV3));
        __syncthreads();
        #pragma unroll
        for (int kk = 0; kk < 16; kk++) {
            float4 a = *(const float4*)&As[kk][ty*4];
            float4 c = *(const float4*)&Bs[kk][tx*4];
            float ar[4] = {a.x,a.y,a.z,a.w};
            float br[4] = {c.x,c.y,c.z,c.w};
            #pragma unroll
            for (int i = 0; i < 4; i++)
                #pragma unroll
                for (int j = 0; j < 4; j++) acc[i][j] += ar[i]*br[j];
        }
        __syncthreads();
    }
    float* Op = d_mqkv + ((size_t)bn*KSEL + mt*64)*QKV3 + nt*64;
    #pragma unroll
    for (int i = 0; i < 4; i++)
        #pragma unroll
        for (int j = 0; j < 4; j++)
            Op[(size_t)(ty*4+i)*QKV3 + tx*4+j] = acc[i][j];
}

// ================= tf32 WMMA GEMM core (device pointers only) ================
// 128x128 block tile, BK=16, 256 threads (8 warps, 4x2), warp tile 32x64.
#define AS_STRIDE 20
#define BS_STRIDE 136

// dense qkv: d_dqkv[4096,1536] = X[4096,1024] @ dwqkv[1024,1536]
// NOTE: output is the device global d_dqkv, referenced in DEVICE code
// (passing a __device__ global's address from host is invalid — round-3/4 bug).
__global__ __launch_bounds__(256) void dense_qkv_wmma_kernel(
        const float* __restrict__ A, const float* __restrict__ B)
{
    __shared__ __align__(32) float As[128*AS_STRIDE];
    __shared__ __align__(32) float Bs[16*BS_STRIDE];
    const int K = HH, lda = HH, ldb = NHD*QKV3, ldc = NHD*QKV3;
    int tid = threadIdx.x;
    int warp = tid >> 5;
    int wm = warp >> 1;          // 0..3
    int wn = warp & 1;           // 0..1
    int row0 = blockIdx.y*128;
    int col0 = blockIdx.x*128;

    int arow = tid >> 2;         // 0..63  (rows arow, arow+64)
    int acol = (tid & 3) * 4;
    int brow = tid >> 5;         // 0..7   (rows brow, brow+8)
    int bcol = (tid & 31) * 4;

    const float* Ag = A + (size_t)(row0 + arow)*lda + acol;
    const float* Bg = B + col0 + bcol;

    float4 a_stage0, a_stage1, b_stage0, b_stage1;

    auto load_tile = [&](int k0) {
        a_stage0 = *(const float4*)(Ag + k0);
        a_stage1 = *(const float4*)(Ag + (size_t)64*lda + k0);
        b_stage0 = *(const float4*)(Bg + (size_t)(k0 + brow)*ldb);
        b_stage1 = *(const float4*)(Bg + (size_t)(k0 + brow + 8)*ldb);
    };
    auto store_tile = [&]() {
        *(float4*)&As[arow*AS_STRIDE + acol] = a_stage0;
        *(float4*)&As[(arow+64)*AS_STRIDE + acol] = a_stage1;
        *(float4*)&Bs[brow*BS_STRIDE + bcol] = b_stage0;
        *(float4*)&Bs[(brow+8)*BS_STRIDE + bcol] = b_stage1;
    };

    wmma::fragment<wmma::accumulator, 16, 16, 8, float> acc[2][4];
    #pragma unroll
    for (int mi = 0; mi < 2; mi++)
        #pragma unroll
        for (int ni = 0; ni < 4; ni++)
            wmma::fill_fragment(acc[mi][ni], 0.0f);

    load_tile(0);
    store_tile();
    __syncthreads();

    const int ktiles = K/16;
    #pragma unroll 1
    for (int kt = 0; kt < ktiles; kt++) {
        bool more = (kt + 1 < ktiles);
        if (more) load_tile((kt+1)*16);
        #pragma unroll
        for (int ks = 0; ks < 2; ks++) {
            wmma::fragment<wmma::matrix_a, 16, 16, 8,
                           wmma::precision::tf32, wmma::row_major> af[2];
            wmma::fragment<wmma::matrix_b, 16, 16, 8,
                           wmma::precision::tf32, wmma::row_major> bf[4];
            #pragma unroll
            for (int mi = 0; mi < 2; mi++) {
                wmma::load_matrix_sync(af[mi],
                    &As[(wm*32 + mi*16)*AS_STRIDE + ks*8], AS_STRIDE);
                #pragma unroll
                for (int e = 0; e < af[mi].num_elements; e++)
                    af[mi].x[e] = wmma::__float_to_tf32(af[mi].x[e]);
            }
            #pragma unroll
            for (int ni = 0; ni < 4; ni++) {
                wmma::load_matrix_sync(bf[ni],
                    &Bs[(ks*8)*BS_STRIDE + wn*64 + ni*16], BS_STRIDE);
                #pragma unroll
                for (int e = 0; e < bf[ni].num_elements; e++)
                    bf[ni].x[e] = wmma::__float_to_tf32(bf[ni].x[e]);
            }
            #pragma unroll
            for (int mi = 0; mi < 2; mi++)
                #pragma unroll
                for (int ni = 0; ni < 4; ni++)
                    wmma::mma_sync(acc[mi][ni], af[mi], bf[ni], acc[mi][ni]);
        }
        if (more) {
            __syncthreads();
            store_tile();
            __syncthreads();
        }
    }

    #pragma unroll
    for (int mi = 0; mi < 2; mi++)
        #pragma unroll
        for (int ni = 0; ni < 4; ni++)
            wmma::store_matrix_sync(
                &d_dqkv[(size_t)(row0 + wm*32 + mi*16)*ldc + col0 + wn*64 + ni*16],
                acc[mi][ni], ldc, wmma::mem_row_major);
}

// final GEMM: out[4096,1024] = d_Y[4096,1024] @ [mwo(512x1024); dwo(512x1024)]
__global__ __launch_bounds__(256) void final_wmma_kernel(
        const float* __restrict__ mwo, const float* __restrict__ dwo,
        float* __restrict__ out)
{
    __shared__ __align__(32) float As[128*AS_STRIDE];
    __shared__ __align__(32) float Bs[16*BS_STRIDE];
    const int K = 1024, lda = 1024, ldb = 1024, ldc = 1024;
    int tid = threadIdx.x;
    int warp = tid >> 5;
    int wm = warp >> 1;
    int wn = warp & 1;
    int row0 = blockIdx.y*128;
    int col0 = blockIdx.x*128;

    int arow = tid >> 2;
    int acol = (tid & 3) * 4;
    int brow = tid >> 5;
    int bcol = (tid & 31) * 4;

    const float* Ag = d_Y + (size_t)(row0 + arow)*lda + acol;

    float4 a_stage0, a_stage1, b_stage0, b_stage1;

    auto load_tile = [&](int k0) {
        a_stage0 = *(const float4*)(Ag + k0);
        a_stage1 = *(const float4*)(Ag + (size_t)64*lda + k0);
        int r0 = k0 + brow, r1 = k0 + brow + 8;
        const float* p0 = (r0 < 512) ? (mwo + (size_t)r0*ldb)
                                     : (dwo + (size_t)(r0 - 512)*ldb);
        const float* p1 = (r1 < 512) ? (mwo + (size_t)r1*ldb)
                                     : (dwo + (size_t)(r1 - 512)*ldb);
        b_stage0 = *(const float4*)(p0 + col0 + bcol);
        b_stage1 = *(const float4*)(p1 + col0 + bcol);
    };
    auto store_tile = [&]() {
        *(float4*)&As[arow*AS_STRIDE + acol] = a_stage0;
        *(float4*)&As[(arow+64)*AS_STRIDE + acol] = a_stage1;
        *(float4*)&Bs[brow*BS_STRIDE + bcol] = b_stage0;
        *(float4*)&Bs[(brow+8)*BS_STRIDE + bcol] = b_stage1;
    };

    wmma::fragment<wmma::accumulator, 16, 16, 8, float> acc[2][4];
    #pragma unroll
    for (int mi = 0; mi < 2; mi++)
        #pragma unroll
        for (int ni = 0; ni < 4; ni++)
            wmma::fill_fragment(acc[mi][ni], 0.0f);

    load_tile(0);
    store_tile();
    __syncthreads();

    const int ktiles = K/16;
    #pragma unroll 1
    for (int kt = 0; kt < ktiles; kt++) {
        bool more = (kt + 1 < ktiles);
        if (more) load_tile((kt+1)*16);
        #pragma unroll
        for (int ks = 0; ks < 2; ks++) {
            wmma::fragment<wmma::matrix_a, 16, 16, 8,
                           wmma::precision::tf32, wmma::row_major> af[2];
            wmma::fragment<wmma::matrix_b, 16, 16, 8,
                           wmma::precision::tf32, wmma::row_major> bf[4];
            #pragma unroll
            for (int mi = 0; mi < 2; mi++) {
                wmma::load_matrix_sync(af[mi],
                    &As[(wm*32 + mi*16)*AS_STRIDE + ks*8], AS_STRIDE);
                #pragma unroll
                for (int e = 0; e < af[mi].num_elements; e++)
                    af[mi].x[e] = wmma::__float_to_tf32(af[mi].x[e]);
            }
            #pragma unroll
            for (int ni = 0; ni < 4; ni++) {
                wmma::load_matrix_sync(bf[ni],
                    &Bs[(ks*8)*BS_STRIDE + wn*64 + ni*16], BS_STRIDE);
                #pragma unroll
                for (int e = 0; e < bf[ni].num_elements; e++)
                    bf[ni].x[e] = wmma::__float_to_tf32(bf[ni].x[e]);
            }
            #pragma unroll
            for (int mi = 0; mi < 2; mi++)
                #pragma unroll
                for (int ni = 0; ni < 4; ni++)
                    wmma::mma_sync(acc[mi][ni], af[mi], bf[ni], acc[mi][ni]);
        }
        if (more) {
            __syncthreads();
            store_tile();
            __syncthreads();
        }
    }

    #pragma unroll
    for (int mi = 0; mi < 2; mi++)
        #pragma unroll
        for (int ni = 0; ni < 4; ni++)
            wmma::store_matrix_sync(
                &out[(size_t)(row0 + wm*32 + mi*16)*ldc + col0 + wn*64 + ni*16],
                acc[mi][ni], ldc, wmma::mem_row_major);
}

// ---------------- RoPE ----------------
__device__ __forceinline__ float inv_freq(int j) {
    return (float)exp(-(double)j * (9.210340371976184 / 16.0)); // 10000^{-j/16}
}

__global__ void mosa_rope_kernel() {
    int g = blockIdx.x*blockDim.x + threadIdx.x;
    int j  = g & 15;
    int kk = (g >> 4) & 255;
    int bn = g >> 12;
    float pos = (float)d_idx[bn*KSEL + kk];
    float ang = pos * inv_freq(j);
    float s, c; sincosf(ang, &s, &c);
    float* p = d_mqkv + ((size_t)bn*KSEL + kk)*QKV3;
    float x1 = p[j], x2 = p[16+j];
    p[j] = x1*c - x2*s;  p[16+j] = x1*s + x2*c;
    x1 = p[64+j]; x2 = p[80+j];
    p[64+j] = x1*c - x2*s; p[80+j] = x1*s + x2*c;
}

__global__ void dense_rope_kernel() {
    int g = blockIdx.x*blockDim.x + threadIdx.x;
    int j = g & 15;
    int n = (g >> 4) & 7;
    int t = (g >> 7) & 2047;
    int b = g >> 18;
    float ang = (float)t * inv_freq(j);
    float s, c; sincosf(ang, &s, &c);
    float* p = d_dqkv + ((size_t)(b*TT + t))*(NHD*QKV3) + n*QKV3;
    float x1 = p[j], x2 = p[16+j];
    p[j] = x1*c - x2*s;  p[16+j] = x1*s + x2*c;
    x1 = p[64+j]; x2 = p[80+j];
    p[64+j] = x1*c - x2*s; p[80+j] = x1*s + x2*c;
}

// ---------------- flash attention ----------------
#define FA_STRIDE 68
#define FA_SMEM_FLOATS (4*64*FA_STRIDE + 3*64 + 256)
#define FA_SMEM_BYTES  (FA_SMEM_FLOATS*4)

__device__ __forceinline__ float fmax4(float a, float b, float c, float d) {
    return fmaxf(fmaxf(a,b), fmaxf(c,d));
}

__global__ __launch_bounds__(256) void dense_flash_kernel() {
    extern __shared__ float sm[];
    float* Qt = sm;
    float* Kt = Qt + 64*FA_STRIDE;
    float* Vs = Kt + 64*FA_STRIDE;
    float* St = Vs + 64*FA_STRIDE;
    float* msh = St + 64*FA_STRIDE;
    float* lsh = msh + 64;
    float* ash = lsh + 64;
    float* red = ash + 64;

    int qt = blockIdx.x, n = blockIdx.y, b = blockIdx.z;
    int tid = threadIdx.x, tx = tid & 15, ty = tid >> 4;
    const int RS = NHD*QKV3;

    for (int s = tid; s < 1024; s += 256) {
        int r = s >> 4, c4 = s & 15;
        float4 v = *(const float4*)(d_dqkv +
            ((size_t)(b*TT + qt*64 + r))*RS + n*QKV3 + c4*4);
        Qt[(c4*4+0)*FA_STRIDE + r] = v.x; Qt[(c4*4+1)*FA_STRIDE + r] = v.y;
        Qt[(c4*4+2)*FA_STRIDE + r] = v.z; Qt[(c4*4+3)*FA_STRIDE + r] = v.w;
    }
    if (tid < 64) { msh[tid] = NEGINF; lsh[tid] = 0.f; }
    float o[4][4] = {};

    for (int kt = 0; kt <= qt; kt++) {
        __syncthreads();
        for (int s = tid; s < 1024; s += 256) {
            int r = s >> 4, c4 = s & 15;
            size_t base = ((size_t)(b*TT + kt*64 + r))*RS + n*QKV3;
            float4 kv = *(const float4*)(d_dqkv + base + 64 + c4*4);
            Kt[(c4*4+0)*FA_STRIDE + r] = kv.x; Kt[(c4*4+1)*FA_STRIDE + r] = kv.y;
            Kt[(c4*4+2)*FA_STRIDE + r] = kv.z; Kt[(c4*4+3)*FA_STRIDE + r] = kv.w;
            *(float4*)&Vs[r*FA_STRIDE + c4*4] =
                *(const float4*)(d_dqkv + base + 128 + c4*4);
        }
        __syncthreads();
        float s4[4][4] = {};
        #pragma unroll 8
        for (int d = 0; d < 64; d++) {
            float4 a = *(const float4*)&Qt[d*FA_STRIDE + ty*4];
            float4 c = *(const float4*)&Kt[d*FA_STRIDE + tx*4];
            float ar[4] = {a.x,a.y,a.z,a.w};
            float br[4] = {c.x,c.y,c.z,c.w};
            #pragma unroll
            for (int i = 0; i < 4; i++)
                #pragma unroll
                for (int j = 0; j < 4; j++) s4[i][j] += ar[i]*br[j];
        }
        bool diag = (kt == qt);
        #pragma unroll
        for (int i = 0; i < 4; i++)
            #pragma unroll
            for (int j = 0; j < 4; j++) {
                float sv = s4[i][j]*0.125f;
                if (diag && (tx*4+j) > (ty*4+i)) sv = NEGINF;
                St[(tx*4+j)*FA_STRIDE + ty*4+i] = sv;
            }
        __syncthreads();
        int row = tid >> 2, seg = tid & 3;
        float mx = NEGINF;
        #pragma unroll
        for (int c = seg*16; c < seg*16+16; c++)
            mx = fmaxf(mx, St[c*FA_STRIDE + row]);
        red[row*4+seg] = mx;
        __syncthreads();
        if (seg == 0) {
            float mt_ = fmax4(red[row*4], red[row*4+1], red[row*4+2], red[row*4+3]);
            float mo = msh[row];
            float mn = fmaxf(mo, mt_);
            ash[row] = expf(mo - mn);
            msh[row] = mn;
        }
        __syncthreads();
        float mn = msh[row], ps = 0.f;
        #pragma unroll
        for (int c = seg*16; c < seg*16+16; c++) {
            float p = expf(St[c*FA_STRIDE + row] - mn);
            St[c*FA_STRIDE + row] = p;
            ps += p;
        }
        red[row*4+seg] = ps;
        __syncthreads();
        if (seg == 0)
            lsh[row] = lsh[row]*ash[row] +
                       red[row*4] + red[row*4+1] + red[row*4+2] + red[row*4+3];
        __syncthreads();
        float al[4];
        #pragma unroll
        for (int i = 0; i < 4; i++) al[i] = ash[ty*4+i];
        #pragma unroll
        for (int i = 0; i < 4; i++)
            #pragma unroll
            for (int j = 0; j < 4; j++) o[i][j] *= al[i];
        #pragma unroll 8
        for (int kk = 0; kk < 64; kk++) {
            float4 a = *(const float4*)&St[kk*FA_STRIDE + ty*4];
            float4 c = *(const float4*)&Vs[kk*FA_STRIDE + tx*4];
            float ar[4] = {a.x,a.y,a.z,a.w};
            float br[4] = {c.x,c.y,c.z,c.w};
            #pragma unroll
            for (int i = 0; i < 4; i++)
                #pragma unroll
                for (int j = 0; j < 4; j++) o[i][j] += ar[i]*br[j];
        }
    }
    float li[4];
    #pragma unroll
    for (int i = 0; i < 4; i++) li[i] = 1.f/lsh[ty*4+i];
    #pragma unroll
    for (int i = 0; i < 4; i++)
        #pragma unroll
        for (int j = 0; j < 4; j++)
            d_Y[((size_t)(b*TT + qt*64 + ty*4+i))*1024 + 512 + n*64 + tx*4+j] =
                o[i][j]*li[i];
}

__global__ __launch_bounds__(256) void mosa_flash_kernel() {
    extern __shared__ float sm[];
    float* Qt = sm;
    float* Kt = Qt + 64*FA_STRIDE;
    float* Vs = Kt + 64*FA_STRIDE;
    float* St = Vs + 64*FA_STRIDE;
    float* msh = St + 64*FA_STRIDE;
    float* lsh = msh + 64;
    float* ash = lsh + 64;
    float* red = ash + 64;

    int qt = blockIdx.x, n = blockIdx.y, b = blockIdx.z;
    int bn = b*NHM + n;
    int tid = threadIdx.x, tx = tid & 15, ty = tid >> 4;

    for (int s = tid; s < 1024; s += 256) {
        int r = s >> 4, c4 = s & 15;
        float4 v = *(const float4*)(d_mqkv +
            ((size_t)(bn*KSEL + qt*64 + r))*QKV3 + c4*4);
        Qt[(c4*4+0)*FA_STRIDE + r] = v.x; Qt[(c4*4+1)*FA_STRIDE + r] = v.y;
        Qt[(c4*4+2)*FA_STRIDE + r] = v.z; Qt[(c4*4+3)*FA_STRIDE + r] = v.w;
    }
    if (tid < 64) { msh[tid] = NEGINF; lsh[tid] = 0.f; }
    float o[4][4] = {};

    for (int kt = 0; kt <= qt; kt++) {
        __syncthreads();
        for (int s = tid; s < 1024; s += 256) {
            int r = s >> 4, c4 = s & 15;
            size_t base = ((size_t)(bn*KSEL + kt*64 + r))*QKV3;
            float4 kv = *(const float4*)(d_mqkv + base + 64 + c4*4);
            Kt[(c4*4+0)*FA_STRIDE + r] = kv.x; Kt[(c4*4+1)*FA_STRIDE + r] = kv.y;
            Kt[(c4*4+2)*FA_STRIDE + r] = kv.z; Kt[(c4*4+3)*FA_STRIDE + r] = kv.w;
            *(float4*)&Vs[r*FA_STRIDE + c4*4] =
                *(const float4*)(d_mqkv + base + 128 + c4*4);
        }
        __syncthreads();
        float s4[4][4] = {};
        #pragma unroll 8
        for (int d = 0; d < 64; d++) {
            float4 a = *(const float4*)&Qt[d*FA_STRIDE + ty*4];
            float4 c = *(const float4*)&Kt[d*FA_STRIDE + tx*4];
            float ar[4] = {a.x,a.y,a.z,a.w};
            float br[4] = {c.x,c.y,c.z,c.w};
            #pragma unroll
            for (int i = 0; i < 4; i++)
                #pragma unroll
                for (int j = 0; j < 4; j++) s4[i][j] += ar[i]*br[j];
        }
        bool diag = (kt == qt);
        #pragma unroll
        for (int i = 0; i < 4; i++)
            #pragma unroll
            for (int j = 0; j < 4; j++) {
                float sv = s4[i][j]*0.125f;
                if (diag && (tx*4+j) > (ty*4+i)) sv = NEGINF;
                St[(tx*4+j)*FA_STRIDE + ty*4+i] = sv;
            }
        __syncthreads();
        int row = tid >> 2, seg = tid & 3;
        float mx = NEGINF;
        #pragma unroll
        for (int c = seg*16; c < seg*16+16; c++)
            mx = fmaxf(mx, St[c*FA_STRIDE + row]);
        red[row*4+seg] = mx;
        __syncthreads();
        if (seg == 0) {
            float mt_ = fmax4(red[row*4], red[row*4+1], red[row*4+2], red[row*4+3]);
            float mo = msh[row];
            float mn = fmaxf(mo, mt_);
            ash[row] = expf(mo - mn);
            msh[row] = mn;
        }
        __syncthreads();
        float mn = msh[row], ps = 0.f;
        #pragma unroll
        for (int c = seg*16; c < seg*16+16; c++) {
            float p = expf(St[c*FA_STRIDE + row] - mn);
            St[c*FA_STRIDE + row] = p;
            ps += p;
        }
        red[row*4+seg] = ps;
        __syncthreads();
        if (seg == 0)
            lsh[row] = lsh[row]*ash[row] +
                       red[row*4] + red[row*4+1] + red[row*4+2] + red[row*4+3];
        __syncthreads();
        float al[4];
        #pragma unroll
        for (int i = 0; i < 4; i++) al[i] = ash[ty*4+i];
        #pragma unroll
        for (int i = 0; i < 4; i++)
            #pragma unroll
            for (int j = 0; j < 4; j++) o[i][j] *= al[i];
        #pragma unroll 8
        for (int kk = 0; kk < 64; kk++) {
            float4 a = *(const float4*)&St[kk*FA_STRIDE + ty*4];
            float4 c = *(const float4*)&Vs[kk*FA_STRIDE + tx*4];
            float ar[4] = {a.x,a.y,a.z,a.w};
            float br[4] = {c.x,c.y,c.z,c.w};
            #pragma unroll
            for (int i = 0; i < 4; i++)
                #pragma unroll
                for (int j = 0; j < 4; j++) o[i][j] += ar[i]*br[j];
        }
    }
    #pragma unroll
    for (int i = 0; i < 4; i++) {
        int q = qt*64 + ty*4 + i;
        int tok = d_idx[bn*KSEL + q];
        float g = d_gates[bn*KSEL + q];
        float scale = g / lsh[ty*4+i];
        #pragma unroll
        for (int j = 0; j < 4; j++)
            d_Y[((size_t)(b*TT + tok))*1024 + n*64 + tx*4+j] = o[i][j]*scale;
    }
}

// ---------------- launch ----------------
extern "C" void kernel_launch(void* const* d_in, const int* in_sizes, int n_in,
                              void* d_out, int out_size) {
    const float* X     = (const float*)d_in[0];
    const float* rw    = (const float*)d_in[1];
    const float* mwqkv = (const float*)d_in[2];
    const float* mwo   = (const float*)d_in[3];
    const float* dwqkv = (const float*)d_in[4];
    const float* dwo   = (const float*)d_in[5];
    float* out = (float*)d_out;

    cudaFuncSetAttribute(dense_flash_kernel,
        cudaFuncAttributeMaxDynamicSharedMemorySize, FA_SMEM_BYTES);
    cudaFuncSetAttribute(mosa_flash_kernel,
        cudaFuncAttributeMaxDynamicSharedMemorySize, FA_SMEM_BYTES);

    zeroY_kernel<<<1024, 256>>>();
    router_kernel<<<dim3(TT, BB), 256>>>(X, rw);
    topk_kernel<<<BB*NHM, 1024>>>();
    mosa_qkv_kernel<<<dim3(3, 4, BB*NHM), 256>>>(X, mwqkv);
    mosa_rope_kernel<<<256, 256>>>();
    mosa_flash_kernel<<<dim3(4, NHM, BB), 256, FA_SMEM_BYTES>>>();
    // dense qkv via tf32 wmma: d_dqkv = X @ dwqkv   (output is device global)
    dense_qkv_wmma_kernel<<<dim3(12, 32), 256>>>(X, dwqkv);
    dense_rope_kernel<<<2048, 256>>>();
    dense_flash_kernel<<<dim3(32, NHD, BB), 256, FA_SMEM_BYTES>>>();
    final_wmma_kernel<<<dim3(8, 32), 256>>>(mwo, dwo, out);
}

// round 7
// speedup vs baseline: 1.3443x; 1.0680x over previous
#include <cuda_runtime.h>
#include <mma.h>
#include <math.h>

using namespace nvcuda;

#define BB   2
#define TT   2048
#define HH   1024
#define HPP  64
#define NHM  8
#define NHD  8
#define KSEL 256           // TT / SPARSITY
#define QKV3 192           // 3*HP
#define NEGINF (-3.0e38f)

// ---------------- scratch (static __device__, no allocations) ----------------
__device__ __align__(128) float d_scores[BB*NHM*TT];
__device__ __align__(128) int   d_idx   [BB*NHM*KSEL];
__device__ __align__(128) float d_gates [BB*NHM*KSEL];
__device__ __align__(128) float d_mqkv  [BB*NHM*KSEL*QKV3];
__device__ __align__(128) float d_dqkv  [(size_t)BB*TT*NHD*QKV3];
__device__ __align__(128) float d_Y     [(size_t)BB*TT*1024];

// ---------------- zero Y ----------------
__global__ void zeroY_kernel() {
    size_t n4 = (size_t)BB*TT*1024/4;
    float4* p = (float4*)d_Y;
    float4 z = make_float4(0.f,0.f,0.f,0.f);
    for (size_t i = blockIdx.x*(size_t)blockDim.x + threadIdx.x; i < n4;
         i += (size_t)gridDim.x*blockDim.x)
        p[i] = z;
}

// ---------------- router scores: scores[b,n,t] = X[b,t,:] . rw[:,n] ----------
__global__ void router_kernel(const float* __restrict__ X,
                              const float* __restrict__ rw) {
    __shared__ float Xs[HH];
    int t = blockIdx.x, b = blockIdx.y;
    const float* xr = X + ((size_t)b*TT + t)*HH;
    for (int i = threadIdx.x; i < HH; i += blockDim.x) Xs[i] = xr[i];
    __syncthreads();
    int w = threadIdx.x >> 5, lane = threadIdx.x & 31;
    float s = 0.f;
    for (int h = lane; h < HH; h += 32) s += Xs[h] * rw[h*NHM + w];
    #pragma unroll
    for (int o = 16; o; o >>= 1) s += __shfl_down_sync(0xffffffffu, s, o);
    if (lane == 0) d_scores[((size_t)b*NHM + w)*TT + t] = s;
}

// ---------------- top-k (k=256 of 2048) + ascending index sort + gates -------
__global__ void topk_kernel() {
    __shared__ float vals[TT];
    __shared__ int   inds[TT];
    int bn = blockIdx.x, tid = threadIdx.x;
    const float* sc = d_scores + (size_t)bn*TT;
    for (int t = tid; t < TT; t += blockDim.x) { vals[t] = sc[t]; inds[t] = t; }
    __syncthreads();
    for (int k = 2; k <= TT; k <<= 1)
        for (int j = k >> 1; j > 0; j >>= 1) {
            for (int t = tid; t < TT; t += blockDim.x) {
                int p = t ^ j;
                if (p > t) {
                    float va = vals[t], vb = vals[p];
                    int ia = inds[t], ib = inds[p];
                    bool a_first = (va > vb) || (va == vb && ia < ib);
                    bool desc = ((t & k) == 0);
                    if (desc ? !a_first : a_first) {
                        vals[t] = vb; vals[p] = va; inds[t] = ib; inds[p] = ia;
                    }
                }
            }
            __syncthreads();
        }
    for (int k = 2; k <= KSEL; k <<= 1)
        for (int j = k >> 1; j > 0; j >>= 1) {
            for (int t = tid; t < KSEL; t += blockDim.x) {
                int p = t ^ j;
                if (p > t) {
                    int ia = inds[t], ib = inds[p];
                    bool asc = ((t & k) == 0);
                    if (asc ? (ia > ib) : (ia < ib)) { inds[t] = ib; inds[p] = ia; }
                }
            }
            __syncthreads();
        }
    for (int kk = tid; kk < KSEL; kk += blockDim.x) {
        int id = inds[kk];
        d_idx[bn*KSEL + kk] = id;
        float s = sc[id];
        d_gates[bn*KSEL + kk] = 1.f / (1.f + expf(-s));
    }
}

// ---------------- MoSA qkv: per (b,n)  (256x1024 gathered) @ (1024x192) ------
__global__ __launch_bounds__(256) void mosa_qkv_kernel(
        const float* __restrict__ X, const float* __restrict__ W) {
    __shared__ float As[16][68];
    __shared__ float Bs[16][68];
    int bn = blockIdx.z, b = bn >> 3, n = bn & 7;
    int mt = blockIdx.y, nt = blockIdx.x;
    int tid = threadIdx.x, tx = tid & 15, ty = tid >> 4;
    int arow = tid >> 2, a4 = tid & 3;
    int brow = tid >> 4, b4 = tid & 15;
    int tok = d_idx[bn*KSEL + mt*64 + arow];
    const float* Ap = X + ((size_t)b*TT + tok)*HH + a4*4;
    const float* Bp = W + (size_t)n*QKV3 + nt*64 + b4*4;
    float acc[4][4] = {};
    for (int k0 = 0; k0 < HH; k0 += 16) {
        float4 av = *(const float4*)(Ap + k0);
        As[a4*4+0][arow] = av.x; As[a4*4+1][arow] = av.y;
        As[a4*4+2][arow] = av.z; As[a4*4+3][arow] = av.w;
        *(float4*)&Bs[brow][b4*4] =
            *(const float4*)(Bp + (size_t)(k0 + brow)*(NHM*QKV3));
        __syncthreads();
        #pragma unroll
        for (int kk = 0; kk < 16; kk++) {
            float4 a = *(const float4*)&As[kk][ty*4];
            float4 c = *(const float4*)&Bs[kk][tx*4];
            float ar[4] = {a.x,a.y,a.z,a.w};
            float br[4] = {c.x,c.y,c.z,c.w};
            #pragma unroll
            for (int i = 0; i < 4; i++)
                #pragma unroll
                for (int j = 0; j < 4; j++) acc[i][j] += ar[i]*br[j];
        }
        __syncthreads();
    }
    float* Op = d_mqkv + ((size_t)bn*KSEL + mt*64)*QKV3 + nt*64;
    #pragma unroll
    for (int i = 0; i < 4; i++)
        #pragma unroll
        for (int j = 0; j < 4; j++)
            Op[(size_t)(ty*4+i)*QKV3 + tx*4+j] = acc[i][j];
}

// ================= tf32 WMMA GEMM core (device globals in device code) =======
#define AS_STRIDE 20
#define BS_STRIDE 136

// dense qkv: d_dqkv[4096,1536] = X[4096,1024] @ dwqkv[1024,1536]
__global__ __launch_bounds__(256) void dense_qkv_wmma_kernel(
        const float* __restrict__ A, const float* __restrict__ B)
{
    __shared__ __align__(32) float As[128*AS_STRIDE];
    __shared__ __align__(32) float Bs[16*BS_STRIDE];
    const int K = HH, lda = HH, ldb = NHD*QKV3, ldc = NHD*QKV3;
    int tid = threadIdx.x;
    int warp = tid >> 5;
    int wm = warp >> 1;
    int wn = warp & 1;
    int row0 = blockIdx.y*128;
    int col0 = blockIdx.x*128;

    int arow = tid >> 2;
    int acol = (tid & 3) * 4;
    int brow = tid >> 5;
    int bcol = (tid & 31) * 4;

    const float* Ag = A + (size_t)(row0 + arow)*lda + acol;
    const float* Bg = B + col0 + bcol;

    float4 a_stage0, a_stage1, b_stage0, b_stage1;

    auto load_tile = [&](int k0) {
        a_stage0 = *(const float4*)(Ag + k0);
        a_stage1 = *(const float4*)(Ag + (size_t)64*lda + k0);
        b_stage0 = *(const float4*)(Bg + (size_t)(k0 + brow)*ldb);
        b_stage1 = *(const float4*)(Bg + (size_t)(k0 + brow + 8)*ldb);
    };
    auto store_tile = [&]() {
        *(float4*)&As[arow*AS_STRIDE + acol] = a_stage0;
        *(float4*)&As[(arow+64)*AS_STRIDE + acol] = a_stage1;
        *(float4*)&Bs[brow*BS_STRIDE + bcol] = b_stage0;
        *(float4*)&Bs[(brow+8)*BS_STRIDE + bcol] = b_stage1;
    };

    wmma::fragment<wmma::accumulator, 16, 16, 8, float> acc[2][4];
    #pragma unroll
    for (int mi = 0; mi < 2; mi++)
        #pragma unroll
        for (int ni = 0; ni < 4; ni++)
            wmma::fill_fragment(acc[mi][ni], 0.0f);

    load_tile(0);
    store_tile();
    __syncthreads();

    const int ktiles = K/16;
    #pragma unroll 1
    for (int kt = 0; kt < ktiles; kt++) {
        bool more = (kt + 1 < ktiles);
        if (more) load_tile((kt+1)*16);
        #pragma unroll
        for (int ks = 0; ks < 2; ks++) {
            wmma::fragment<wmma::matrix_a, 16, 16, 8,
                           wmma::precision::tf32, wmma::row_major> af[2];
            wmma::fragment<wmma::matrix_b, 16, 16, 8,
                           wmma::precision::tf32, wmma::row_major> bf[4];
            #pragma unroll
            for (int mi = 0; mi < 2; mi++) {
                wmma::load_matrix_sync(af[mi],
                    &As[(wm*32 + mi*16)*AS_STRIDE + ks*8], AS_STRIDE);
                #pragma unroll
                for (int e = 0; e < af[mi].num_elements; e++)
                    af[mi].x[e] = wmma::__float_to_tf32(af[mi].x[e]);
            }
            #pragma unroll
            for (int ni = 0; ni < 4; ni++) {
                wmma::load_matrix_sync(bf[ni],
                    &Bs[(ks*8)*BS_STRIDE + wn*64 + ni*16], BS_STRIDE);
                #pragma unroll
                for (int e = 0; e < bf[ni].num_elements; e++)
                    bf[ni].x[e] = wmma::__float_to_tf32(bf[ni].x[e]);
            }
            #pragma unroll
            for (int mi = 0; mi < 2; mi++)
                #pragma unroll
                for (int ni = 0; ni < 4; ni++)
                    wmma::mma_sync(acc[mi][ni], af[mi], bf[ni], acc[mi][ni]);
        }
        if (more) {
            __syncthreads();
            store_tile();
            __syncthreads();
        }
    }

    #pragma unroll
    for (int mi = 0; mi < 2; mi++)
        #pragma unroll
        for (int ni = 0; ni < 4; ni++)
            wmma::store_matrix_sync(
                &d_dqkv[(size_t)(row0 + wm*32 + mi*16)*ldc + col0 + wn*64 + ni*16],
                acc[mi][ni], ldc, wmma::mem_row_major);
}

// final GEMM: out[4096,1024] = d_Y[4096,1024] @ [mwo(512x1024); dwo(512x1024)]
__global__ __launch_bounds__(256) void final_wmma_kernel(
        const float* __restrict__ mwo, const float* __restrict__ dwo,
        float* __restrict__ out)
{
    __shared__ __align__(32) float As[128*AS_STRIDE];
    __shared__ __align__(32) float Bs[16*BS_STRIDE];
    const int K = 1024, lda = 1024, ldb = 1024, ldc = 1024;
    int tid = threadIdx.x;
    int warp = tid >> 5;
    int wm = warp >> 1;
    int wn = warp & 1;
    int row0 = blockIdx.y*128;
    int col0 = blockIdx.x*128;

    int arow = tid >> 2;
    int acol = (tid & 3) * 4;
    int brow = tid >> 5;
    int bcol = (tid & 31) * 4;

    const float* Ag = d_Y + (size_t)(row0 + arow)*lda + acol;

    float4 a_stage0, a_stage1, b_stage0, b_stage1;

    auto load_tile = [&](int k0) {
        a_stage0 = *(const float4*)(Ag + k0);
        a_stage1 = *(const float4*)(Ag + (size_t)64*lda + k0);
        int r0 = k0 + brow, r1 = k0 + brow + 8;
        const float* p0 = (r0 < 512) ? (mwo + (size_t)r0*ldb)
                                     : (dwo + (size_t)(r0 - 512)*ldb);
        const float* p1 = (r1 < 512) ? (mwo + (size_t)r1*ldb)
                                     : (dwo + (size_t)(r1 - 512)*ldb);
        b_stage0 = *(const float4*)(p0 + col0 + bcol);
        b_stage1 = *(const float4*)(p1 + col0 + bcol);
    };
    auto store_tile = [&]() {
        *(float4*)&As[arow*AS_STRIDE + acol] = a_stage0;
        *(float4*)&As[(arow+64)*AS_STRIDE + acol] = a_stage1;
        *(float4*)&Bs[brow*BS_STRIDE + bcol] = b_stage0;
        *(float4*)&Bs[(brow+8)*BS_STRIDE + bcol] = b_stage1;
    };

    wmma::fragment<wmma::accumulator, 16, 16, 8, float> acc[2][4];
    #pragma unroll
    for (int mi = 0; mi < 2; mi++)
        #pragma unroll
        for (int ni = 0; ni < 4; ni++)
            wmma::fill_fragment(acc[mi][ni], 0.0f);

    load_tile(0);
    store_tile();
    __syncthreads();

    const int ktiles = K/16;
    #pragma unroll 1
    for (int kt = 0; kt < ktiles; kt++) {
        bool more = (kt + 1 < ktiles);
        if (more) load_tile((kt+1)*16);
        #pragma unroll
        for (int ks = 0; ks < 2; ks++) {
            wmma::fragment<wmma::matrix_a, 16, 16, 8,
                           wmma::precision::tf32, wmma::row_major> af[2];
            wmma::fragment<wmma::matrix_b, 16, 16, 8,
                           wmma::precision::tf32, wmma::row_major> bf[4];
            #pragma unroll
            for (int mi = 0; mi < 2; mi++) {
                wmma::load_matrix_sync(af[mi],
                    &As[(wm*32 + mi*16)*AS_STRIDE + ks*8], AS_STRIDE);
                #pragma unroll
                for (int e = 0; e < af[mi].num_elements; e++)
                    af[mi].x[e] = wmma::__float_to_tf32(af[mi].x[e]);
            }
            #pragma unroll
            for (int ni = 0; ni < 4; ni++) {
                wmma::load_matrix_sync(bf[ni],
                    &Bs[(ks*8)*BS_STRIDE + wn*64 + ni*16], BS_STRIDE);
                #pragma unroll
                for (int e = 0; e < bf[ni].num_elements; e++)
                    bf[ni].x[e] = wmma::__float_to_tf32(bf[ni].x[e]);
            }
            #pragma unroll
            for (int mi = 0; mi < 2; mi++)
                #pragma unroll
                for (int ni = 0; ni < 4; ni++)
                    wmma::mma_sync(acc[mi][ni], af[mi], bf[ni], acc[mi][ni]);
        }
        if (more) {
            __syncthreads();
            store_tile();
            __syncthreads();
        }
    }

    #pragma unroll
    for (int mi = 0; mi < 2; mi++)
        #pragma unroll
        for (int ni = 0; ni < 4; ni++)
            wmma::store_matrix_sync(
                &out[(size_t)(row0 + wm*32 + mi*16)*ldc + col0 + wn*64 + ni*16],
                acc[mi][ni], ldc, wmma::mem_row_major);
}

// ---------------- RoPE ----------------
__device__ __forceinline__ float inv_freq(int j) {
    return (float)exp(-(double)j * (9.210340371976184 / 16.0)); // 10000^{-j/16}
}

__global__ void mosa_rope_kernel() {
    int g = blockIdx.x*blockDim.x + threadIdx.x;
    int j  = g & 15;
    int kk = (g >> 4) & 255;
    int bn = g >> 12;
    float pos = (float)d_idx[bn*KSEL + kk];
    float ang = pos * inv_freq(j);
    float s, c; sincosf(ang, &s, &c);
    float* p = d_mqkv + ((size_t)bn*KSEL + kk)*QKV3;
    float x1 = p[j], x2 = p[16+j];
    p[j] = x1*c - x2*s;  p[16+j] = x1*s + x2*c;
    x1 = p[64+j]; x2 = p[80+j];
    p[64+j] = x1*c - x2*s; p[80+j] = x1*s + x2*c;
}

__global__ void dense_rope_kernel() {
    int g = blockIdx.x*blockDim.x + threadIdx.x;
    int j = g & 15;
    int n = (g >> 4) & 7;
    int t = (g >> 7) & 2047;
    int b = g >> 18;
    float ang = (float)t * inv_freq(j);
    float s, c; sincosf(ang, &s, &c);
    float* p = d_dqkv + ((size_t)(b*TT + t))*(NHD*QKV3) + n*QKV3;
    float x1 = p[j], x2 = p[16+j];
    p[j] = x1*c - x2*s;  p[16+j] = x1*s + x2*c;
    x1 = p[64+j]; x2 = p[80+j];
    p[64+j] = x1*c - x2*s; p[80+j] = x1*s + x2*c;
}

// ================= dense flash attention with tf32 WMMA ======================
// Block: 256 thr (8 warps 2x4), q-tile 64, one (b, head). grid (32, NHD, BB).
#define DF_LD 76
#define DF_SMEM_FLOATS (5*64*DF_LD + 3*64 + 256)
#define DF_SMEM_BYTES  (DF_SMEM_FLOATS*4)

__device__ __forceinline__ float fmax4(float a, float b, float c, float d) {
    return fmaxf(fmaxf(a,b), fmaxf(c,d));
}

__global__ __launch_bounds__(256) void dense_flash_wmma_kernel() {
    extern __shared__ float sm[];
    float* Qs = sm;                 // [64][DF_LD] (q, d)   row-major
    float* Ks = Qs + 64*DF_LD;      // [64][DF_LD] (c, d)   row-major
    float* Vs = Ks + 64*DF_LD;      // [64][DF_LD] (c, dd)  row-major
    float* Ss = Vs + 64*DF_LD;      // [64][DF_LD] (q, c)   scores -> P
    float* Os = Ss + 64*DF_LD;      // [64][DF_LD] (q, dd)  fp32 accum
    float* msh = Os + 64*DF_LD;
    float* lsh = msh + 64;
    float* ash = lsh + 64;
    float* red = ash + 64;          // [64][4]

    int qt = blockIdx.x, n = blockIdx.y, b = blockIdx.z;
    int tid = threadIdx.x;
    int warp = tid >> 5;
    int wm = warp >> 2;             // 0..1 : rows [wm*32, wm*32+32)
    int wn = warp & 3;              // 0..3 : cols [wn*16, wn*16+16)
    const int RS = NHD*QKV3;
    int row = tid >> 2, seg = tid & 3;

    // load Q tile (row-major), zero O
    for (int s = tid; s < 1024; s += 256) {
        int r = s >> 4, c4 = s & 15;
        *(float4*)&Qs[r*DF_LD + c4*4] = *(const float4*)(d_dqkv +
            ((size_t)(b*TT + qt*64 + r))*RS + n*QKV3 + c4*4);
        *(float4*)&Os[r*DF_LD + c4*4] = make_float4(0.f,0.f,0.f,0.f);
    }
    if (tid < 64) { msh[tid] = NEGINF; lsh[tid] = 0.f; }

    for (int kt = 0; kt <= qt; kt++) {
        __syncthreads();   // prev-iter users of Ks/Vs/Os done
        for (int s = tid; s < 1024; s += 256) {
            int r = s >> 4, c4 = s & 15;
            size_t base = ((size_t)(b*TT + kt*64 + r))*RS + n*QKV3;
            *(float4*)&Ks[r*DF_LD + c4*4] = *(const float4*)(d_dqkv + base + 64 + c4*4);
            *(float4*)&Vs[r*DF_LD + c4*4] = *(const float4*)(d_dqkv + base + 128 + c4*4);
        }
        __syncthreads();

        // ---- S = Q @ K^T  (warp tile 32x16: mi=0,1) ----
        {
            wmma::fragment<wmma::accumulator, 16, 16, 8, float> sacc[2];
            wmma::fill_fragment(sacc[0], 0.f);
            wmma::fill_fragment(sacc[1], 0.f);
            #pragma unroll
            for (int k0 = 0; k0 < 64; k0 += 8) {
                wmma::fragment<wmma::matrix_b, 16, 16, 8,
                               wmma::precision::tf32, wmma::col_major> bf;
                wmma::load_matrix_sync(bf, &Ks[(wn*16)*DF_LD + k0], DF_LD);
                #pragma unroll
                for (int e = 0; e < bf.num_elements; e++)
                    bf.x[e] = wmma::__float_to_tf32(bf.x[e]);
                #pragma unroll
                for (int mi = 0; mi < 2; mi++) {
                    wmma::fragment<wmma::matrix_a, 16, 16, 8,
                                   wmma::precision::tf32, wmma::row_major> af;
                    wmma::load_matrix_sync(af, &Qs[(wm*32 + mi*16)*DF_LD + k0], DF_LD);
                    #pragma unroll
                    for (int e = 0; e < af.num_elements; e++)
                        af.x[e] = wmma::__float_to_tf32(af.x[e]);
                    wmma::mma_sync(sacc[mi], af, bf, sacc[mi]);
                }
            }
            #pragma unroll
            for (int mi = 0; mi < 2; mi++)
                wmma::store_matrix_sync(&Ss[(wm*32 + mi*16)*DF_LD + wn*16],
                                        sacc[mi], DF_LD, wmma::mem_row_major);
        }
        __syncthreads();

        // ---- online softmax on rows of Ss ----
        bool diag = (kt == qt);
        float mx = NEGINF;
        #pragma unroll
        for (int c = seg*16; c < seg*16+16; c++) {
            float sv = Ss[row*DF_LD + c]*0.125f;
            if (diag && c > row) sv = NEGINF;
            Ss[row*DF_LD + c] = sv;
            mx = fmaxf(mx, sv);
        }
        red[row*4+seg] = mx;
        __syncthreads();
        if (seg == 0) {
            float mt_ = fmax4(red[row*4], red[row*4+1], red[row*4+2], red[row*4+3]);
            float mo = msh[row];
            float mn = fmaxf(mo, mt_);
            ash[row] = expf(mo - mn);
            msh[row] = mn;
        }
        __syncthreads();
        float mn = msh[row], ps = 0.f;
        #pragma unroll
        for (int c = seg*16; c < seg*16+16; c++) {
            float p = expf(Ss[row*DF_LD + c] - mn);
            Ss[row*DF_LD + c] = p;
            ps += p;
        }
        red[row*4+seg] = ps;
        __syncthreads();
        if (seg == 0)
            lsh[row] = lsh[row]*ash[row] +
                       red[row*4] + red[row*4+1] + red[row*4+2] + red[row*4+3];
        float alpha = ash[row];
        #pragma unroll
        for (int c = seg*16; c < seg*16+16; c++)
            Os[row*DF_LD + c] *= alpha;
        __syncthreads();   // P + rescaled O visible to all

        // ---- O += P @ V ----
        {
            wmma::fragment<wmma::accumulator, 16, 16, 8, float> oacc[2];
            #pragma unroll
            for (int mi = 0; mi < 2; mi++)
                wmma::load_matrix_sync(oacc[mi],
                    &Os[(wm*32 + mi*16)*DF_LD + wn*16], DF_LD, wmma::mem_row_major);
            #pragma unroll
            for (int k0 = 0; k0 < 64; k0 += 8) {
                wmma::fragment<wmma::matrix_b, 16, 16, 8,
                               wmma::precision::tf32, wmma::row_major> bf;
                wmma::load_matrix_sync(bf, &Vs[k0*DF_LD + wn*16], DF_LD);
                #pragma unroll
                for (int e = 0; e < bf.num_elements; e++)
                    bf.x[e] = wmma::__float_to_tf32(bf.x[e]);
                #pragma unroll
                for (int mi = 0; mi < 2; mi++) {
                    wmma::fragment<wmma::matrix_a, 16, 16, 8,
                                   wmma::precision::tf32, wmma::row_major> af;
                    wmma::load_matrix_sync(af, &Ss[(wm*32 + mi*16)*DF_LD + k0], DF_LD);
                    #pragma unroll
                    for (int e = 0; e < af.num_elements; e++)
                        af.x[e] = wmma::__float_to_tf32(af.x[e]);
                    wmma::mma_sync(oacc[mi], af, bf, oacc[mi]);
                }
            }
            #pragma unroll
            for (int mi = 0; mi < 2; mi++)
                wmma::store_matrix_sync(&Os[(wm*32 + mi*16)*DF_LD + wn*16],
                                        oacc[mi], DF_LD, wmma::mem_row_major);
        }
    }
    __syncthreads();
    {
        float li = 1.f/lsh[row];
        #pragma unroll
        for (int c = seg*16; c < seg*16+16; c++)
            d_Y[((size_t)(b*TT + qt*64 + row))*1024 + 512 + n*64 + c] =
                Os[row*DF_LD + c]*li;
    }
}

// ---------------- mosa flash attention (fp32, unchanged) ----------------
#define FA_STRIDE 68
#define FA_SMEM_FLOATS (4*64*FA_STRIDE + 3*64 + 256)
#define FA_SMEM_BYTES  (FA_SMEM_FLOATS*4)

__global__ __launch_bounds__(256) void mosa_flash_kernel() {
    extern __shared__ float sm[];
    float* Qt = sm;
    float* Kt = Qt + 64*FA_STRIDE;
    float* Vs = Kt + 64*FA_STRIDE;
    float* St = Vs + 64*FA_STRIDE;
    float* msh = St + 64*FA_STRIDE;
    float* lsh = msh + 64;
    float* ash = lsh + 64;
    float* red = ash + 64;

    int qt = blockIdx.x, n = blockIdx.y, b = blockIdx.z;
    int bn = b*NHM + n;
    int tid = threadIdx.x, tx = tid & 15, ty = tid >> 4;

    for (int s = tid; s < 1024; s += 256) {
        int r = s >> 4, c4 = s & 15;
        float4 v = *(const float4*)(d_mqkv +
            ((size_t)(bn*KSEL + qt*64 + r))*QKV3 + c4*4);
        Qt[(c4*4+0)*FA_STRIDE + r] = v.x; Qt[(c4*4+1)*FA_STRIDE + r] = v.y;
        Qt[(c4*4+2)*FA_STRIDE + r] = v.z; Qt[(c4*4+3)*FA_STRIDE + r] = v.w;
    }
    if (tid < 64) { msh[tid] = NEGINF; lsh[tid] = 0.f; }
    float o[4][4] = {};

    for (int kt = 0; kt <= qt; kt++) {
        __syncthreads();
        for (int s = tid; s < 1024; s += 256) {
            int r = s >> 4, c4 = s & 15;
            size_t base = ((size_t)(bn*KSEL + kt*64 + r))*QKV3;
            float4 kv = *(const float4*)(d_mqkv + base + 64 + c4*4);
            Kt[(c4*4+0)*FA_STRIDE + r] = kv.x; Kt[(c4*4+1)*FA_STRIDE + r] = kv.y;
            Kt[(c4*4+2)*FA_STRIDE + r] = kv.z; Kt[(c4*4+3)*FA_STRIDE + r] = kv.w;
            *(float4*)&Vs[r*FA_STRIDE + c4*4] =
                *(const float4*)(d_mqkv + base + 128 + c4*4);
        }
        __syncthreads();
        float s4[4][4] = {};
        #pragma unroll 8
        for (int d = 0; d < 64; d++) {
            float4 a = *(const float4*)&Qt[d*FA_STRIDE + ty*4];
            float4 c = *(const float4*)&Kt[d*FA_STRIDE + tx*4];
            float ar[4] = {a.x,a.y,a.z,a.w};
            float br[4] = {c.x,c.y,c.z,c.w};
            #pragma unroll
            for (int i = 0; i < 4; i++)
                #pragma unroll
                for (int j = 0; j < 4; j++) s4[i][j] += ar[i]*br[j];
        }
        bool diag = (kt == qt);
        #pragma unroll
        for (int i = 0; i < 4; i++)
            #pragma unroll
            for (int j = 0; j < 4; j++) {
                float sv = s4[i][j]*0.125f;
                if (diag && (tx*4+j) > (ty*4+i)) sv = NEGINF;
                St[(tx*4+j)*FA_STRIDE + ty*4+i] = sv;
            }
        __syncthreads();
        int row = tid >> 2, seg = tid & 3;
        float mx = NEGINF;
        #pragma unroll
        for (int c = seg*16; c < seg*16+16; c++)
            mx = fmaxf(mx, St[c*FA_STRIDE + row]);
        red[row*4+seg] = mx;
        __syncthreads();
        if (seg == 0) {
            float mt_ = fmax4(red[row*4], red[row*4+1], red[row*4+2], red[row*4+3]);
            float mo = msh[row];
            float mn = fmaxf(mo, mt_);
            ash[row] = expf(mo - mn);
            msh[row] = mn;
        }
        __syncthreads();
        float mn = msh[row], ps = 0.f;
        #pragma unroll
        for (int c = seg*16; c < seg*16+16; c++) {
            float p = expf(St[c*FA_STRIDE + row] - mn);
            St[c*FA_STRIDE + row] = p;
            ps += p;
        }
        red[row*4+seg] = ps;
        __syncthreads();
        if (seg == 0)
            lsh[row] = lsh[row]*ash[row] +
                       red[row*4] + red[row*4+1] + red[row*4+2] + red[row*4+3];
        __syncthreads();
        float al[4];
        #pragma unroll
        for (int i = 0; i < 4; i++) al[i] = ash[ty*4+i];
        #pragma unroll
        for (int i = 0; i < 4; i++)
            #pragma unroll
            for (int j = 0; j < 4; j++) o[i][j] *= al[i];
        #pragma unroll 8
        for (int kk = 0; kk < 64; kk++) {
            float4 a = *(const float4*)&St[kk*FA_STRIDE + ty*4];
            float4 c = *(const float4*)&Vs[kk*FA_STRIDE + tx*4];
            float ar[4] = {a.x,a.y,a.z,a.w};
            float br[4] = {c.x,c.y,c.z,c.w};
            #pragma unroll
            for (int i = 0; i < 4; i++)
                #pragma unroll
                for (int j = 0; j < 4; j++) o[i][j] += ar[i]*br[j];
        }
    }
    #pragma unroll
    for (int i = 0; i < 4; i++) {
        int q = qt*64 + ty*4 + i;
        int tok = d_idx[bn*KSEL + q];
        float g = d_gates[bn*KSEL + q];
        float scale = g / lsh[ty*4+i];
        #pragma unroll
        for (int j = 0; j < 4; j++)
            d_Y[((size_t)(b*TT + tok))*1024 + n*64 + tx*4+j] = o[i][j]*scale;
    }
}

// ---------------- launch ----------------
extern "C" void kernel_launch(void* const* d_in, const int* in_sizes, int n_in,
                              void* d_out, int out_size) {
    const float* X     = (const float*)d_in[0];
    const float* rw    = (const float*)d_in[1];
    const float* mwqkv = (const float*)d_in[2];
    const float* mwo   = (const float*)d_in[3];
    const float* dwqkv = (const float*)d_in[4];
    const float* dwo   = (const float*)d_in[5];
    float* out = (float*)d_out;

    cudaFuncSetAttribute(dense_flash_wmma_kernel,
        cudaFuncAttributeMaxDynamicSharedMemorySize, DF_SMEM_BYTES);
    cudaFuncSetAttribute(mosa_flash_kernel,
        cudaFuncAttributeMaxDynamicSharedMemorySize, FA_SMEM_BYTES);

    zeroY_kernel<<<1024, 256>>>();
    router_kernel<<<dim3(TT, BB), 256>>>(X, rw);
    topk_kernel<<<BB*NHM, 1024>>>();
    mosa_qkv_kernel<<<dim3(3, 4, BB*NHM), 256>>>(X, mwqkv);
    mosa_rope_kernel<<<256, 256>>>();
    mosa_flash_kernel<<<dim3(4, NHM, BB), 256, FA_SMEM_BYTES>>>();
    dense_qkv_wmma_kernel<<<dim3(12, 32), 256>>>(X, dwqkv);
    dense_rope_kernel<<<2048, 256>>>();
    dense_flash_wmma_kernel<<<dim3(32, NHD, BB), 256, DF_SMEM_BYTES>>>();
    final_wmma_kernel<<<dim3(8, 32), 256>>>(mwo, dwo, out);
}

// round 8
// speedup vs baseline: 1.3786x; 1.0255x over previous
#include <cuda_runtime.h>
#include <mma.h>
#include <math.h>

using namespace nvcuda;

#define BB   2
#define TT   2048
#define HH   1024
#define HPP  64
#define NHM  8
#define NHD  8
#define KSEL 256           // TT / SPARSITY
#define QKV3 192           // 3*HP
#define NEGINF (-3.0e38f)

// ---------------- scratch ----------------
__device__ __align__(128) float d_scores[BB*NHM*TT];
__device__ __align__(128) int   d_idx   [BB*NHM*KSEL];
__device__ __align__(128) float d_gates [BB*NHM*KSEL];
__device__ __align__(128) float d_mqkv  [BB*NHM*KSEL*QKV3];
__device__ __align__(128) float d_dqkv  [(size_t)BB*TT*NHD*QKV3];
__device__ __align__(128) float d_Y     [(size_t)BB*TT*1024];

__device__ __forceinline__ float f2tf32(float f) {
    unsigned u; asm("cvt.rna.tf32.f32 %0, %1;" : "=r"(u) : "f"(f));
    return __uint_as_float(u);
}

// ---------------- zero mosa half of Y (dense half fully overwritten) --------
__global__ void zeroY_kernel() {
    int i = blockIdx.x*blockDim.x + threadIdx.x;   // BB*TT*128 float4s
    if (i < BB*TT*128) {
        int r = i >> 7, c = i & 127;
        *(float4*)&d_Y[(size_t)r*1024 + c*4] = make_float4(0.f,0.f,0.f,0.f);
    }
}

// ---------------- router ----------------
__global__ void router_kernel(const float* __restrict__ X,
                              const float* __restrict__ rw) {
    __shared__ float Xs[HH];
    int t = blockIdx.x, b = blockIdx.y;
    const float* xr = X + ((size_t)b*TT + t)*HH;
    for (int i = threadIdx.x; i < HH; i += blockDim.x) Xs[i] = xr[i];
    __syncthreads();
    int w = threadIdx.x >> 5, lane = threadIdx.x & 31;
    float s = 0.f;
    for (int h = lane; h < HH; h += 32) s += Xs[h] * rw[h*NHM + w];
    #pragma unroll
    for (int o = 16; o; o >>= 1) s += __shfl_down_sync(0xffffffffu, s, o);
    if (lane == 0) d_scores[((size_t)b*NHM + w)*TT + t] = s;
}

// ---------------- top-k ----------------
__global__ void topk_kernel() {
    __shared__ float vals[TT];
    __shared__ int   inds[TT];
    int bn = blockIdx.x, tid = threadIdx.x;
    const float* sc = d_scores + (size_t)bn*TT;
    for (int t = tid; t < TT; t += blockDim.x) { vals[t] = sc[t]; inds[t] = t; }
    __syncthreads();
    for (int k = 2; k <= TT; k <<= 1)
        for (int j = k >> 1; j > 0; j >>= 1) {
            for (int t = tid; t < TT; t += blockDim.x) {
                int p = t ^ j;
                if (p > t) {
                    float va = vals[t], vb = vals[p];
                    int ia = inds[t], ib = inds[p];
                    bool a_first = (va > vb) || (va == vb && ia < ib);
                    bool desc = ((t & k) == 0);
                    if (desc ? !a_first : a_first) {
                        vals[t] = vb; vals[p] = va; inds[t] = ib; inds[p] = ia;
                    }
                }
            }
            __syncthreads();
        }
    for (int k = 2; k <= KSEL; k <<= 1)
        for (int j = k >> 1; j > 0; j >>= 1) {
            for (int t = tid; t < KSEL; t += blockDim.x) {
                int p = t ^ j;
                if (p > t) {
                    int ia = inds[t], ib = inds[p];
                    bool asc = ((t & k) == 0);
                    if (asc ? (ia > ib) : (ia < ib)) { inds[t] = ib; inds[p] = ia; }
                }
            }
            __syncthreads();
        }
    for (int kk = tid; kk < KSEL; kk += blockDim.x) {
        int id = inds[kk];
        d_idx[bn*KSEL + kk] = id;
        float s = sc[id];
        d_gates[bn*KSEL + kk] = 1.f / (1.f + expf(-s));
    }
}

// ---------------- MoSA qkv via tf32 wmma: (256x1024 gathered)@(1024x192) ----
// grid (3, 4, 16): 64x64 C tile, 8 warps 2x4 (warp tile 32x16), BK=16.
#define MQ_AS 20
#define MQ_BS 68
__global__ __launch_bounds__(256) void mosa_qkv_wmma_kernel(
        const float* __restrict__ X, const float* __restrict__ W) {
    __shared__ __align__(16) float As[64*MQ_AS];
    __shared__ __align__(16) float Bs[16*MQ_BS];
    int bn = blockIdx.z, b = bn >> 3, n = bn & 7;
    int mt = blockIdx.y, nt = blockIdx.x;
    int tid = threadIdx.x;
    int warp = tid >> 5, wm = warp >> 2, wn = warp & 3;
    int arow = tid >> 2, a4 = (tid & 3)*4;
    int brow = tid >> 4, bcol = (tid & 15)*4;
    int tok = d_idx[bn*KSEL + mt*64 + arow];
    const float* Ap = X + ((size_t)b*TT + tok)*HH + a4;
    const float* Bp = W + (size_t)n*QKV3 + nt*64 + bcol;

    float4 a_st, b_st;
    auto load_tile = [&](int k0) {
        a_st = *(const float4*)(Ap + k0);
        b_st = *(const float4*)(Bp + (size_t)(k0 + brow)*(NHM*QKV3));
    };
    auto store_tile = [&]() {
        As[arow*MQ_AS + a4+0] = f2tf32(a_st.x);
        As[arow*MQ_AS + a4+1] = f2tf32(a_st.y);
        As[arow*MQ_AS + a4+2] = f2tf32(a_st.z);
        As[arow*MQ_AS + a4+3] = f2tf32(a_st.w);
        Bs[brow*MQ_BS + bcol+0] = f2tf32(b_st.x);
        Bs[brow*MQ_BS + bcol+1] = f2tf32(b_st.y);
        Bs[brow*MQ_BS + bcol+2] = f2tf32(b_st.z);
        Bs[brow*MQ_BS + bcol+3] = f2tf32(b_st.w);
    };

    wmma::fragment<wmma::accumulator, 16, 16, 8, float> acc[2];
    wmma::fill_fragment(acc[0], 0.f);
    wmma::fill_fragment(acc[1], 0.f);

    load_tile(0);
    store_tile();
    __syncthreads();

    #pragma unroll 1
    for (int kt = 0; kt < HH/16; kt++) {
        bool more = (kt + 1 < HH/16);
        if (more) load_tile((kt+1)*16);
        #pragma unroll
        for (int ks = 0; ks < 2; ks++) {
            wmma::fragment<wmma::matrix_b, 16, 16, 8,
                           wmma::precision::tf32, wmma::row_major> bf;
            wmma::load_matrix_sync(bf, &Bs[(ks*8)*MQ_BS + wn*16], MQ_BS);
            #pragma unroll
            for (int mi = 0; mi < 2; mi++) {
                wmma::fragment<wmma::matrix_a, 16, 16, 8,
                               wmma::precision::tf32, wmma::row_major> af;
                wmma::load_matrix_sync(af, &As[(wm*32 + mi*16)*MQ_AS + ks*8], MQ_AS);
                wmma::mma_sync(acc[mi], af, bf, acc[mi]);
            }
        }
        if (more) {
            __syncthreads();
            store_tile();
            __syncthreads();
        }
    }
    #pragma unroll
    for (int mi = 0; mi < 2; mi++)
        wmma::store_matrix_sync(
            &d_mqkv[((size_t)bn*KSEL + mt*64 + wm*32 + mi*16)*QKV3 + nt*64 + wn*16],
            acc[mi], QKV3, wmma::mem_row_major);
}

// ================= tf32 WMMA GEMM (dense qkv + final) ========================
#define AS_STRIDE 20
#define BS_STRIDE 136

__global__ __launch_bounds__(256) void dense_qkv_wmma_kernel(
        const float* __restrict__ A, const float* __restrict__ B)
{
    __shared__ __align__(16) float As[128*AS_STRIDE];
    __shared__ __align__(16) float Bs[16*BS_STRIDE];
    const int K = HH, lda = HH, ldb = NHD*QKV3, ldc = NHD*QKV3;
    int tid = threadIdx.x;
    int warp = tid >> 5;
    int wm = warp >> 1, wn = warp & 1;
    int row0 = blockIdx.y*128, col0 = blockIdx.x*128;
    int arow = tid >> 2, acol = (tid & 3)*4;
    int brow = tid >> 5, bcol = (tid & 31)*4;

    const float* Ag = A + (size_t)(row0 + arow)*lda + acol;
    const float* Bg = B + col0 + bcol;

    float4 a0, a1, b0, b1;
    auto load_tile = [&](int k0) {
        a0 = *(const float4*)(Ag + k0);
        a1 = *(const float4*)(Ag + (size_t)64*lda + k0);
        b0 = *(const float4*)(Bg + (size_t)(k0 + brow)*ldb);
        b1 = *(const float4*)(Bg + (size_t)(k0 + brow + 8)*ldb);
    };
    auto store_tile = [&]() {
        As[arow*AS_STRIDE + acol+0] = f2tf32(a0.x);
        As[arow*AS_STRIDE + acol+1] = f2tf32(a0.y);
        As[arow*AS_STRIDE + acol+2] = f2tf32(a0.z);
        As[arow*AS_STRIDE + acol+3] = f2tf32(a0.w);
        As[(arow+64)*AS_STRIDE + acol+0] = f2tf32(a1.x);
        As[(arow+64)*AS_STRIDE + acol+1] = f2tf32(a1.y);
        As[(arow+64)*AS_STRIDE + acol+2] = f2tf32(a1.z);
        As[(arow+64)*AS_STRIDE + acol+3] = f2tf32(a1.w);
        Bs[brow*BS_STRIDE + bcol+0] = f2tf32(b0.x);
        Bs[brow*BS_STRIDE + bcol+1] = f2tf32(b0.y);
        Bs[brow*BS_STRIDE + bcol+2] = f2tf32(b0.z);
        Bs[brow*BS_STRIDE + bcol+3] = f2tf32(b0.w);
        Bs[(brow+8)*BS_STRIDE + bcol+0] = f2tf32(b1.x);
        Bs[(brow+8)*BS_STRIDE + bcol+1] = f2tf32(b1.y);
        Bs[(brow+8)*BS_STRIDE + bcol+2] = f2tf32(b1.z);
        Bs[(brow+8)*BS_STRIDE + bcol+3] = f2tf32(b1.w);
    };

    wmma::fragment<wmma::accumulator, 16, 16, 8, float> acc[2][4];
    #pragma unroll
    for (int mi = 0; mi < 2; mi++)
        #pragma unroll
        for (int ni = 0; ni < 4; ni++)
            wmma::fill_fragment(acc[mi][ni], 0.0f);

    load_tile(0); store_tile(); __syncthreads();

    #pragma unroll 1
    for (int kt = 0; kt < K/16; kt++) {
        bool more = (kt + 1 < K/16);
        if (more) load_tile((kt+1)*16);
        #pragma unroll
        for (int ks = 0; ks < 2; ks++) {
            wmma::fragment<wmma::matrix_a, 16, 16, 8,
                           wmma::precision::tf32, wmma::row_major> af[2];
            wmma::fragment<wmma::matrix_b, 16, 16, 8,
                           wmma::precision::tf32, wmma::row_major> bf[4];
            #pragma unroll
            for (int mi = 0; mi < 2; mi++)
                wmma::load_matrix_sync(af[mi],
                    &As[(wm*32 + mi*16)*AS_STRIDE + ks*8], AS_STRIDE);
            #pragma unroll
            for (int ni = 0; ni < 4; ni++)
                wmma::load_matrix_sync(bf[ni],
                    &Bs[(ks*8)*BS_STRIDE + wn*64 + ni*16], BS_STRIDE);
            #pragma unroll
            for (int mi = 0; mi < 2; mi++)
                #pragma unroll
                for (int ni = 0; ni < 4; ni++)
                    wmma::mma_sync(acc[mi][ni], af[mi], bf[ni], acc[mi][ni]);
        }
        if (more) { __syncthreads(); store_tile(); __syncthreads(); }
    }
    #pragma unroll
    for (int mi = 0; mi < 2; mi++)
        #pragma unroll
        for (int ni = 0; ni < 4; ni++)
            wmma::store_matrix_sync(
                &d_dqkv[(size_t)(row0 + wm*32 + mi*16)*ldc + col0 + wn*64 + ni*16],
                acc[mi][ni], ldc, wmma::mem_row_major);
}

__global__ __launch_bounds__(256) void final_wmma_kernel(
        const float* __restrict__ mwo, const float* __restrict__ dwo,
        float* __restrict__ out)
{
    __shared__ __align__(16) float As[128*AS_STRIDE];
    __shared__ __align__(16) float Bs[16*BS_STRIDE];
    const int K = 1024, lda = 1024, ldb = 1024, ldc = 1024;
    int tid = threadIdx.x;
    int warp = tid >> 5;
    int wm = warp >> 1, wn = warp & 1;
    int row0 = blockIdx.y*128, col0 = blockIdx.x*128;
    int arow = tid >> 2, acol = (tid & 3)*4;
    int brow = tid >> 5, bcol = (tid & 31)*4;

    const float* Ag = d_Y + (size_t)(row0 + arow)*lda + acol;

    float4 a0, a1, b0, b1;
    auto load_tile = [&](int k0) {
        a0 = *(const float4*)(Ag + k0);
        a1 = *(const float4*)(Ag + (size_t)64*lda + k0);
        int r0 = k0 + brow, r1 = k0 + brow + 8;
        const float* p0 = (r0 < 512) ? (mwo + (size_t)r0*ldb)
                                     : (dwo + (size_t)(r0 - 512)*ldb);
        const float* p1 = (r1 < 512) ? (mwo + (size_t)r1*ldb)
                                     : (dwo + (size_t)(r1 - 512)*ldb);
        b0 = *(const float4*)(p0 + col0 + bcol);
        b1 = *(const float4*)(p1 + col0 + bcol);
    };
    auto store_tile = [&]() {
        As[arow*AS_STRIDE + acol+0] = f2tf32(a0.x);
        As[arow*AS_STRIDE + acol+1] = f2tf32(a0.y);
        As[arow*AS_STRIDE + acol+2] = f2tf32(a0.z);
        As[arow*AS_STRIDE + acol+3] = f2tf32(a0.w);
        As[(arow+64)*AS_STRIDE + acol+0] = f2tf32(a1.x);
        As[(arow+64)*AS_STRIDE + acol+1] = f2tf32(a1.y);
        As[(arow+64)*AS_STRIDE + acol+2] = f2tf32(a1.z);
        As[(arow+64)*AS_STRIDE + acol+3] = f2tf32(a1.w);
        Bs[brow*BS_STRIDE + bcol+0] = f2tf32(b0.x);
        Bs[brow*BS_STRIDE + bcol+1] = f2tf32(b0.y);
        Bs[brow*BS_STRIDE + bcol+2] = f2tf32(b0.z);
        Bs[brow*BS_STRIDE + bcol+3] = f2tf32(b0.w);
        Bs[(brow+8)*BS_STRIDE + bcol+0] = f2tf32(b1.x);
        Bs[(brow+8)*BS_STRIDE + bcol+1] = f2tf32(b1.y);
        Bs[(brow+8)*BS_STRIDE + bcol+2] = f2tf32(b1.z);
        Bs[(brow+8)*BS_STRIDE + bcol+3] = f2tf32(b1.w);
    };

    wmma::fragment<wmma::accumulator, 16, 16, 8, float> acc[2][4];
    #pragma unroll
    for (int mi = 0; mi < 2; mi++)
        #pragma unroll
        for (int ni = 0; ni < 4; ni++)
            wmma::fill_fragment(acc[mi][ni], 0.0f);

    load_tile(0); store_tile(); __syncthreads();

    #pragma unroll 1
    for (int kt = 0; kt < K/16; kt++) {
        bool more = (kt + 1 < K/16);
        if (more) load_tile((kt+1)*16);
        #pragma unroll
        for (int ks = 0; ks < 2; ks++) {
            wmma::fragment<wmma::matrix_a, 16, 16, 8,
                           wmma::precision::tf32, wmma::row_major> af[2];
            wmma::fragment<wmma::matrix_b, 16, 16, 8,
                           wmma::precision::tf32, wmma::row_major> bf[4];
            #pragma unroll
            for (int mi = 0; mi < 2; mi++)
                wmma::load_matrix_sync(af[mi],
                    &As[(wm*32 + mi*16)*AS_STRIDE + ks*8], AS_STRIDE);
            #pragma unroll
            for (int ni = 0; ni < 4; ni++)
                wmma::load_matrix_sync(bf[ni],
                    &Bs[(ks*8)*BS_STRIDE + wn*64 + ni*16], BS_STRIDE);
            #pragma unroll
            for (int mi = 0; mi < 2; mi++)
                #pragma unroll
                for (int ni = 0; ni < 4; ni++)
                    wmma::mma_sync(acc[mi][ni], af[mi], bf[ni], acc[mi][ni]);
        }
        if (more) { __syncthreads(); store_tile(); __syncthreads(); }
    }
    #pragma unroll
    for (int mi = 0; mi < 2; mi++)
        #pragma unroll
        for (int ni = 0; ni < 4; ni++)
            wmma::store_matrix_sync(
                &out[(size_t)(row0 + wm*32 + mi*16)*ldc + col0 + wn*64 + ni*16],
                acc[mi][ni], ldc, wmma::mem_row_major);
}

// ---------------- RoPE ----------------
__device__ __forceinline__ float inv_freq(int j) {
    return (float)exp(-(double)j * (9.210340371976184 / 16.0)); // 10000^{-j/16}
}

__global__ void mosa_rope_kernel() {
    int g = blockIdx.x*blockDim.x + threadIdx.x;
    int j  = g & 15;
    int kk = (g >> 4) & 255;
    int bn = g >> 12;
    float pos = (float)d_idx[bn*KSEL + kk];
    float ang = pos * inv_freq(j);
    float s, c; sincosf(ang, &s, &c);
    float* p = d_mqkv + ((size_t)bn*KSEL + kk)*QKV3;
    float x1 = p[j], x2 = p[16+j];
    p[j] = x1*c - x2*s;  p[16+j] = x1*s + x2*c;
    x1 = p[64+j]; x2 = p[80+j];
    p[64+j] = x1*c - x2*s; p[80+j] = x1*s + x2*c;
}

__global__ void dense_rope_kernel() {
    int g = blockIdx.x*blockDim.x + threadIdx.x;
    int j = g & 15;
    int n = (g >> 4) & 7;
    int t = (g >> 7) & 2047;
    int b = g >> 18;
    float ang = (float)t * inv_freq(j);
    float s, c; sincosf(ang, &s, &c);
    float* p = d_dqkv + ((size_t)(b*TT + t))*(NHD*QKV3) + n*QKV3;
    float x1 = p[j], x2 = p[16+j];
    p[j] = x1*c - x2*s;  p[16+j] = x1*s + x2*c;
    x1 = p[64+j]; x2 = p[80+j];
    p[64+j] = x1*c - x2*s; p[80+j] = x1*s + x2*c;
}

// ================= flash attention (tf32 wmma, quad-register softmax) ========
// Block 256 thr (8 warps 2x4). Templated on source/sink. 4 syncs / kt-iter.
#define DF_LD 76
#define DF_SMEM_BYTES (5*64*DF_LD*4)

template<bool MOSA>
__global__ __launch_bounds__(256) void flash_wmma_kernel() {
    extern __shared__ float sm[];
    float* Qs = sm;                 // [64][DF_LD] tf32-rounded
    float* Ks = Qs + 64*DF_LD;
    float* Vs = Ks + 64*DF_LD;
    float* Ss = Vs + 64*DF_LD;      // scores -> P (tf32-rounded)
    float* Os = Ss + 64*DF_LD;      // fp32 accum

    int qt = blockIdx.x, n = blockIdx.y, b = blockIdx.z;
    int bn = b*NHM + n;
    int tid = threadIdx.x;
    int warp = tid >> 5;
    int wm = warp >> 2, wn = warp & 3;
    int row = tid >> 2, seg = tid & 3;
    const int RS = MOSA ? QKV3 : NHD*QKV3;

    // Q tile + zero O
    for (int s = tid; s < 1024; s += 256) {
        int r = s >> 4, c4 = (s & 15)*4;
        size_t base = MOSA ? ((size_t)(bn*KSEL + qt*64 + r))*QKV3
                           : ((size_t)(b*TT + qt*64 + r))*RS + n*QKV3;
        float4 v = *(const float4*)(d_dqkv + base + c4);
        if (MOSA) v = *(const float4*)(d_mqkv + base + c4);
        Qs[r*DF_LD + c4+0] = f2tf32(v.x);
        Qs[r*DF_LD + c4+1] = f2tf32(v.y);
        Qs[r*DF_LD + c4+2] = f2tf32(v.z);
        Qs[r*DF_LD + c4+3] = f2tf32(v.w);
        *(float4*)&Os[r*DF_LD + c4] = make_float4(0.f,0.f,0.f,0.f);
    }
    float m_run = NEGINF, l_run = 0.f;

    for (int kt = 0; kt <= qt; kt++) {
        __syncthreads();
        for (int s = tid; s < 1024; s += 256) {
            int r = s >> 4, c4 = (s & 15)*4;
            size_t base = MOSA ? ((size_t)(bn*KSEL + kt*64 + r))*QKV3
                               : ((size_t)(b*TT + kt*64 + r))*RS + n*QKV3;
            const float* src = MOSA ? d_mqkv : d_dqkv;
            float4 kv = *(const float4*)(src + base + 64 + c4);
            float4 vv = *(const float4*)(src + base + 128 + c4);
            Ks[r*DF_LD + c4+0] = f2tf32(kv.x);
            Ks[r*DF_LD + c4+1] = f2tf32(kv.y);
            Ks[r*DF_LD + c4+2] = f2tf32(kv.z);
            Ks[r*DF_LD + c4+3] = f2tf32(kv.w);
            Vs[r*DF_LD + c4+0] = f2tf32(vv.x);
            Vs[r*DF_LD + c4+1] = f2tf32(vv.y);
            Vs[r*DF_LD + c4+2] = f2tf32(vv.z);
            Vs[r*DF_LD + c4+3] = f2tf32(vv.w);
        }
        __syncthreads();

        // S = Q @ K^T
        {
            wmma::fragment<wmma::accumulator, 16, 16, 8, float> sacc[2];
            wmma::fill_fragment(sacc[0], 0.f);
            wmma::fill_fragment(sacc[1], 0.f);
            #pragma unroll
            for (int k0 = 0; k0 < 64; k0 += 8) {
                wmma::fragment<wmma::matrix_b, 16, 16, 8,
                               wmma::precision::tf32, wmma::col_major> bf;
                wmma::load_matrix_sync(bf, &Ks[(wn*16)*DF_LD + k0], DF_LD);
                #pragma unroll
                for (int mi = 0; mi < 2; mi++) {
                    wmma::fragment<wmma::matrix_a, 16, 16, 8,
                                   wmma::precision::tf32, wmma::row_major> af;
                    wmma::load_matrix_sync(af, &Qs[(wm*32 + mi*16)*DF_LD + k0], DF_LD);
                    wmma::mma_sync(sacc[mi], af, bf, sacc[mi]);
                }
            }
            #pragma unroll
            for (int mi = 0; mi < 2; mi++)
                wmma::store_matrix_sync(&Ss[(wm*32 + mi*16)*DF_LD + wn*16],
                                        sacc[mi], DF_LD, wmma::mem_row_major);
        }
        __syncthreads();

        // online softmax — quad (4 consecutive lanes) owns a row
        bool diag = (kt == qt);
        float svr[16];
        float mx = NEGINF;
        #pragma unroll
        for (int i = 0; i < 16; i++) {
            int c = seg*16 + i;
            float sv = Ss[row*DF_LD + c]*0.125f;
            if (diag && c > row) sv = NEGINF;
            svr[i] = sv;
            mx = fmaxf(mx, sv);
        }
        mx = fmaxf(mx, __shfl_xor_sync(0xffffffffu, mx, 1));
        mx = fmaxf(mx, __shfl_xor_sync(0xffffffffu, mx, 2));
        float mn = fmaxf(m_run, mx);
        float alpha = __expf(m_run - mn);
        float ps = 0.f;
        #pragma unroll
        for (int i = 0; i < 16; i++) {
            float p = __expf(svr[i] - mn);
            Ss[row*DF_LD + seg*16 + i] = f2tf32(p);
            ps += p;
        }
        ps += __shfl_xor_sync(0xffffffffu, ps, 1);
        ps += __shfl_xor_sync(0xffffffffu, ps, 2);
        l_run = l_run*alpha + ps;
        m_run = mn;
        #pragma unroll
        for (int i = 0; i < 16; i++)
            Os[row*DF_LD + seg*16 + i] *= alpha;
        __syncthreads();

        // O += P @ V
        {
            wmma::fragment<wmma::accumulator, 16, 16, 8, float> oacc[2];
            #pragma unroll
            for (int mi = 0; mi < 2; mi++)
                wmma::load_matrix_sync(oacc[mi],
                    &Os[(wm*32 + mi*16)*DF_LD + wn*16], DF_LD, wmma::mem_row_major);
            #pragma unroll
            for (int k0 = 0; k0 < 64; k0 += 8) {
                wmma::fragment<wmma::matrix_b, 16, 16, 8,
                               wmma::precision::tf32, wmma::row_major> bf;
                wmma::load_matrix_sync(bf, &Vs[k0*DF_LD + wn*16], DF_LD);
                #pragma unroll
                for (int mi = 0; mi < 2; mi++) {
                    wmma::fragment<wmma::matrix_a, 16, 16, 8,
                                   wmma::precision::tf32, wmma::row_major> af;
                    wmma::load_matrix_sync(af, &Ss[(wm*32 + mi*16)*DF_LD + k0], DF_LD);
                    wmma::mma_sync(oacc[mi], af, bf, oacc[mi]);
                }
            }
            #pragma unroll
            for (int mi = 0; mi < 2; mi++)
                wmma::store_matrix_sync(&Os[(wm*32 + mi*16)*DF_LD + wn*16],
                                        oacc[mi], DF_LD, wmma::mem_row_major);
        }
    }
    __syncthreads();
    if (MOSA) {
        int q = qt*64 + row;
        int tok = d_idx[bn*KSEL + q];
        float g = d_gates[bn*KSEL + q];
        float scale = g / l_run;
        #pragma unroll
        for (int i = 0; i < 16; i++) {
            int c = seg*16 + i;
            d_Y[((size_t)(b*TT + tok))*1024 + n*64 + c] = Os[row*DF_LD + c]*scale;
        }
    } else {
        float li = 1.f/l_run;
        #pragma unroll
        for (int i = 0; i < 16; i++) {
            int c = seg*16 + i;
            d_Y[((size_t)(b*TT + qt*64 + row))*1024 + 512 + n*64 + c] =
                Os[row*DF_LD + c]*li;
        }
    }
}

// ---------------- launch ----------------
extern "C" void kernel_launch(void* const* d_in, const int* in_sizes, int n_in,
                              void* d_out, int out_size) {
    const float* X     = (const float*)d_in[0];
    const float* rw    = (const float*)d_in[1];
    const float* mwqkv = (const float*)d_in[2];
    const float* mwo   = (const float*)d_in[3];
    const float* dwqkv = (const float*)d_in[4];
    const float* dwo   = (const float*)d_in[5];
    float* out = (float*)d_out;

    cudaFuncSetAttribute(flash_wmma_kernel<false>,
        cudaFuncAttributeMaxDynamicSharedMemorySize, DF_SMEM_BYTES);
    cudaFuncSetAttribute(flash_wmma_kernel<true>,
        cudaFuncAttributeMaxDynamicSharedMemorySize, DF_SMEM_BYTES);

    zeroY_kernel<<<2048, 256>>>();
    router_kernel<<<dim3(TT, BB), 256>>>(X, rw);
    topk_kernel<<<BB*NHM, 1024>>>();
    mosa_qkv_wmma_kernel<<<dim3(3, 4, BB*NHM), 256>>>(X, mwqkv);
    mosa_rope_kernel<<<256, 256>>>();
    flash_wmma_kernel<true><<<dim3(4, NHM, BB), 256, DF_SMEM_BYTES>>>();
    dense_qkv_wmma_kernel<<<dim3(12, 32), 256>>>(X, dwqkv);
    dense_rope_kernel<<<2048, 256>>>();
    flash_wmma_kernel<false><<<dim3(32, NHD, BB), 256, DF_SMEM_BYTES>>>();
    final_wmma_kernel<<<dim3(8, 32), 256>>>(mwo, dwo, out);
}

// round 9
// speedup vs baseline: 1.4517x; 1.0530x over previous
#include <cuda_runtime.h>
#include <mma.h>
#include <math.h>

using namespace nvcuda;

#define BB   2
#define TT   2048
#define HH   1024
#define HPP  64
#define NHM  8
#define NHD  8
#define KSEL 256
#define QKV3 192
#define NEGINF (-3.0e38f)

__device__ __align__(128) float d_scores[BB*NHM*TT];
__device__ __align__(128) int   d_idx   [BB*NHM*KSEL];
__device__ __align__(128) float d_gates [BB*NHM*KSEL];
__device__ __align__(128) float d_mqkv  [BB*NHM*KSEL*QKV3];
__device__ __align__(128) float d_dqkv  [(size_t)BB*TT*NHD*QKV3];
__device__ __align__(128) float d_Y     [(size_t)BB*TT*1024];

__device__ __forceinline__ float f2tf32(float f) {
    unsigned u; asm("cvt.rna.tf32.f32 %0, %1;" : "=r"(u) : "f"(f));
    return __uint_as_float(u);
}

// ---------------- zero mosa half of Y ----------------
__global__ void zeroY_kernel() {
    int i = blockIdx.x*blockDim.x + threadIdx.x;
    if (i < BB*TT*128) {
        int r = i >> 7, c = i & 127;
        *(float4*)&d_Y[(size_t)r*1024 + c*4] = make_float4(0.f,0.f,0.f,0.f);
    }
}

// ---------------- router ----------------
__global__ void router_kernel(const float* __restrict__ X,
                              const float* __restrict__ rw) {
    __shared__ float Xs[HH];
    int t = blockIdx.x, b = blockIdx.y;
    const float* xr = X + ((size_t)b*TT + t)*HH;
    for (int i = threadIdx.x; i < HH; i += blockDim.x) Xs[i] = xr[i];
    __syncthreads();
    int w = threadIdx.x >> 5, lane = threadIdx.x & 31;
    float s = 0.f;
    for (int h = lane; h < HH; h += 32) s += Xs[h] * rw[h*NHM + w];
    #pragma unroll
    for (int o = 16; o; o >>= 1) s += __shfl_down_sync(0xffffffffu, s, o);
    if (lane == 0) d_scores[((size_t)b*NHM + w)*TT + t] = s;
}

// ---------------- top-k ----------------
__global__ void topk_kernel() {
    __shared__ float vals[TT];
    __shared__ int   inds[TT];
    int bn = blockIdx.x, tid = threadIdx.x;
    const float* sc = d_scores + (size_t)bn*TT;
    for (int t = tid; t < TT; t += blockDim.x) { vals[t] = sc[t]; inds[t] = t; }
    __syncthreads();
    for (int k = 2; k <= TT; k <<= 1)
        for (int j = k >> 1; j > 0; j >>= 1) {
            for (int t = tid; t < TT; t += blockDim.x) {
                int p = t ^ j;
                if (p > t) {
                    float va = vals[t], vb = vals[p];
                    int ia = inds[t], ib = inds[p];
                    bool a_first = (va > vb) || (va == vb && ia < ib);
                    bool desc = ((t & k) == 0);
                    if (desc ? !a_first : a_first) {
                        vals[t] = vb; vals[p] = va; inds[t] = ib; inds[p] = ia;
                    }
                }
            }
            __syncthreads();
        }
    for (int k = 2; k <= KSEL; k <<= 1)
        for (int j = k >> 1; j > 0; j >>= 1) {
            for (int t = tid; t < KSEL; t += blockDim.x) {
                int p = t ^ j;
                if (p > t) {
                    int ia = inds[t], ib = inds[p];
                    bool asc = ((t & k) == 0);
                    if (asc ? (ia > ib) : (ia < ib)) { inds[t] = ib; inds[p] = ia; }
                }
            }
            __syncthreads();
        }
    for (int kk = tid; kk < KSEL; kk += blockDim.x) {
        int id = inds[kk];
        d_idx[bn*KSEL + kk] = id;
        float s = sc[id];
        d_gates[bn*KSEL + kk] = 1.f / (1.f + expf(-s));
    }
}

// ---------------- MoSA qkv via tf32 wmma (double-buffered) ----------------
#define MQ_AS 20
#define MQ_BS 68
__global__ __launch_bounds__(256) void mosa_qkv_wmma_kernel(
        const float* __restrict__ X, const float* __restrict__ W) {
    __shared__ __align__(16) float As[2][64*MQ_AS];
    __shared__ __align__(16) float Bs[2][16*MQ_BS];
    int bn = blockIdx.z, b = bn >> 3, n = bn & 7;
    int mt = blockIdx.y, nt = blockIdx.x;
    int tid = threadIdx.x;
    int warp = tid >> 5, wm = warp >> 2, wn = warp & 3;
    int arow = tid >> 2, a4 = (tid & 3)*4;
    int brow = tid >> 4, bcol = (tid & 15)*4;
    int tok = d_idx[bn*KSEL + mt*64 + arow];
    const float* Ap = X + ((size_t)b*TT + tok)*HH + a4;
    const float* Bp = W + (size_t)n*QKV3 + nt*64 + bcol;

    float4 a_st, b_st;
    auto load_tile = [&](int k0) {
        a_st = *(const float4*)(Ap + k0);
        b_st = *(const float4*)(Bp + (size_t)(k0 + brow)*(NHM*QKV3));
    };
    auto store_tile = [&](int bi) {
        float* A_ = As[bi]; float* B_ = Bs[bi];
        A_[arow*MQ_AS + a4+0] = f2tf32(a_st.x);
        A_[arow*MQ_AS + a4+1] = f2tf32(a_st.y);
        A_[arow*MQ_AS + a4+2] = f2tf32(a_st.z);
        A_[arow*MQ_AS + a4+3] = f2tf32(a_st.w);
        B_[brow*MQ_BS + bcol+0] = f2tf32(b_st.x);
        B_[brow*MQ_BS + bcol+1] = f2tf32(b_st.y);
        B_[brow*MQ_BS + bcol+2] = f2tf32(b_st.z);
        B_[brow*MQ_BS + bcol+3] = f2tf32(b_st.w);
    };

    wmma::fragment<wmma::accumulator, 16, 16, 8, float> acc[2];
    wmma::fill_fragment(acc[0], 0.f);
    wmma::fill_fragment(acc[1], 0.f);

    load_tile(0); store_tile(0); __syncthreads();

    #pragma unroll 1
    for (int kt = 0; kt < HH/16; kt++) {
        bool more = (kt + 1 < HH/16);
        if (more) load_tile((kt+1)*16);
        int bi = kt & 1;
        #pragma unroll
        for (int ks = 0; ks < 2; ks++) {
            wmma::fragment<wmma::matrix_b, 16, 16, 8,
                           wmma::precision::tf32, wmma::row_major> bf;
            wmma::load_matrix_sync(bf, &Bs[bi][(ks*8)*MQ_BS + wn*16], MQ_BS);
            #pragma unroll
            for (int mi = 0; mi < 2; mi++) {
                wmma::fragment<wmma::matrix_a, 16, 16, 8,
                               wmma::precision::tf32, wmma::row_major> af;
                wmma::load_matrix_sync(af, &As[bi][(wm*32 + mi*16)*MQ_AS + ks*8], MQ_AS);
                wmma::mma_sync(acc[mi], af, bf, acc[mi]);
            }
        }
        if (more) { store_tile(bi ^ 1); __syncthreads(); }
    }
    #pragma unroll
    for (int mi = 0; mi < 2; mi++)
        wmma::store_matrix_sync(
            &d_mqkv[((size_t)bn*KSEL + mt*64 + wm*32 + mi*16)*QKV3 + nt*64 + wn*16],
            acc[mi], QKV3, wmma::mem_row_major);
}

// ================= tf32 WMMA GEMM (double-buffered) ==========================
#define AS_STRIDE 20
#define BS_STRIDE 136

__global__ __launch_bounds__(256) void dense_qkv_wmma_kernel(
        const float* __restrict__ A, const float* __restrict__ B)
{
    __shared__ __align__(16) float As[2][128*AS_STRIDE];
    __shared__ __align__(16) float Bs[2][16*BS_STRIDE];
    const int K = HH, lda = HH, ldb = NHD*QKV3, ldc = NHD*QKV3;
    int tid = threadIdx.x;
    int warp = tid >> 5;
    int wm = warp >> 1, wn = warp & 1;
    int row0 = blockIdx.y*128, col0 = blockIdx.x*128;
    int arow = tid >> 2, acol = (tid & 3)*4;
    int brow = tid >> 5, bcol = (tid & 31)*4;

    const float* Ag = A + (size_t)(row0 + arow)*lda + acol;
    const float* Bg = B + col0 + bcol;

    float4 a0, a1, b0, b1;
    auto load_tile = [&](int k0) {
        a0 = *(const float4*)(Ag + k0);
        a1 = *(const float4*)(Ag + (size_t)64*lda + k0);
        b0 = *(const float4*)(Bg + (size_t)(k0 + brow)*ldb);
        b1 = *(const float4*)(Bg + (size_t)(k0 + brow + 8)*ldb);
    };
    auto store_tile = [&](int bi) {
        float* A_ = As[bi]; float* B_ = Bs[bi];
        A_[arow*AS_STRIDE + acol+0] = f2tf32(a0.x);
        A_[arow*AS_STRIDE + acol+1] = f2tf32(a0.y);
        A_[arow*AS_STRIDE + acol+2] = f2tf32(a0.z);
        A_[arow*AS_STRIDE + acol+3] = f2tf32(a0.w);
        A_[(arow+64)*AS_STRIDE + acol+0] = f2tf32(a1.x);
        A_[(arow+64)*AS_STRIDE + acol+1] = f2tf32(a1.y);
        A_[(arow+64)*AS_STRIDE + acol+2] = f2tf32(a1.z);
        A_[(arow+64)*AS_STRIDE + acol+3] = f2tf32(a1.w);
        B_[brow*BS_STRIDE + bcol+0] = f2tf32(b0.x);
        B_[brow*BS_STRIDE + bcol+1] = f2tf32(b0.y);
        B_[brow*BS_STRIDE + bcol+2] = f2tf32(b0.z);
        B_[brow*BS_STRIDE + bcol+3] = f2tf32(b0.w);
        B_[(brow+8)*BS_STRIDE + bcol+0] = f2tf32(b1.x);
        B_[(brow+8)*BS_STRIDE + bcol+1] = f2tf32(b1.y);
        B_[(brow+8)*BS_STRIDE + bcol+2] = f2tf32(b1.z);
        B_[(brow+8)*BS_STRIDE + bcol+3] = f2tf32(b1.w);
    };

    wmma::fragment<wmma::accumulator, 16, 16, 8, float> acc[2][4];
    #pragma unroll
    for (int mi = 0; mi < 2; mi++)
        #pragma unroll
        for (int ni = 0; ni < 4; ni++)
            wmma::fill_fragment(acc[mi][ni], 0.0f);

    load_tile(0); store_tile(0); __syncthreads();

    #pragma unroll 1
    for (int kt = 0; kt < K/16; kt++) {
        bool more = (kt + 1 < K/16);
        if (more) load_tile((kt+1)*16);
        int bi = kt & 1;
        #pragma unroll
        for (int ks = 0; ks < 2; ks++) {
            wmma::fragment<wmma::matrix_a, 16, 16, 8,
                           wmma::precision::tf32, wmma::row_major> af[2];
            wmma::fragment<wmma::matrix_b, 16, 16, 8,
                           wmma::precision::tf32, wmma::row_major> bf[4];
            #pragma unroll
            for (int mi = 0; mi < 2; mi++)
                wmma::load_matrix_sync(af[mi],
                    &As[bi][(wm*32 + mi*16)*AS_STRIDE + ks*8], AS_STRIDE);
            #pragma unroll
            for (int ni = 0; ni < 4; ni++)
                wmma::load_matrix_sync(bf[ni],
                    &Bs[bi][(ks*8)*BS_STRIDE + wn*64 + ni*16], BS_STRIDE);
            #pragma unroll
            for (int mi = 0; mi < 2; mi++)
                #pragma unroll
                for (int ni = 0; ni < 4; ni++)
                    wmma::mma_sync(acc[mi][ni], af[mi], bf[ni], acc[mi][ni]);
        }
        if (more) { store_tile(bi ^ 1); __syncthreads(); }
    }
    #pragma unroll
    for (int mi = 0; mi < 2; mi++)
        #pragma unroll
        for (int ni = 0; ni < 4; ni++)
            wmma::store_matrix_sync(
                &d_dqkv[(size_t)(row0 + wm*32 + mi*16)*ldc + col0 + wn*64 + ni*16],
                acc[mi][ni], ldc, wmma::mem_row_major);
}

__global__ __launch_bounds__(256) void final_wmma_kernel(
        const float* __restrict__ mwo, const float* __restrict__ dwo,
        float* __restrict__ out)
{
    __shared__ __align__(16) float As[2][128*AS_STRIDE];
    __shared__ __align__(16) float Bs[2][16*BS_STRIDE];
    const int K = 1024, lda = 1024, ldb = 1024, ldc = 1024;
    int tid = threadIdx.x;
    int warp = tid >> 5;
    int wm = warp >> 1, wn = warp & 1;
    int row0 = blockIdx.y*128, col0 = blockIdx.x*128;
    int arow = tid >> 2, acol = (tid & 3)*4;
    int brow = tid >> 5, bcol = (tid & 31)*4;

    const float* Ag = d_Y + (size_t)(row0 + arow)*lda + acol;

    float4 a0, a1, b0, b1;
    auto load_tile = [&](int k0) {
        a0 = *(const float4*)(Ag + k0);
        a1 = *(const float4*)(Ag + (size_t)64*lda + k0);
        int r0 = k0 + brow, r1 = k0 + brow + 8;
        const float* p0 = (r0 < 512) ? (mwo + (size_t)r0*ldb)
                                     : (dwo + (size_t)(r0 - 512)*ldb);
        const float* p1 = (r1 < 512) ? (mwo + (size_t)r1*ldb)
                                     : (dwo + (size_t)(r1 - 512)*ldb);
        b0 = *(const float4*)(p0 + col0 + bcol);
        b1 = *(const float4*)(p1 + col0 + bcol);
    };
    auto store_tile = [&](int bi) {
        float* A_ = As[bi]; float* B_ = Bs[bi];
        A_[arow*AS_STRIDE + acol+0] = f2tf32(a0.x);
        A_[arow*AS_STRIDE + acol+1] = f2tf32(a0.y);
        A_[arow*AS_STRIDE + acol+2] = f2tf32(a0.z);
        A_[arow*AS_STRIDE + acol+3] = f2tf32(a0.w);
        A_[(arow+64)*AS_STRIDE + acol+0] = f2tf32(a1.x);
        A_[(arow+64)*AS_STRIDE + acol+1] = f2tf32(a1.y);
        A_[(arow+64)*AS_STRIDE + acol+2] = f2tf32(a1.z);
        A_[(arow+64)*AS_STRIDE + acol+3] = f2tf32(a1.w);
        B_[brow*BS_STRIDE + bcol+0] = f2tf32(b0.x);
        B_[brow*BS_STRIDE + bcol+1] = f2tf32(b0.y);
        B_[brow*BS_STRIDE + bcol+2] = f2tf32(b0.z);
        B_[brow*BS_STRIDE + bcol+3] = f2tf32(b0.w);
        B_[(brow+8)*BS_STRIDE + bcol+0] = f2tf32(b1.x);
        B_[(brow+8)*BS_STRIDE + bcol+1] = f2tf32(b1.y);
        B_[(brow+8)*BS_STRIDE + bcol+2] = f2tf32(b1.z);
        B_[(brow+8)*BS_STRIDE + bcol+3] = f2tf32(b1.w);
    };

    wmma::fragment<wmma::accumulator, 16, 16, 8, float> acc[2][4];
    #pragma unroll
    for (int mi = 0; mi < 2; mi++)
        #pragma unroll
        for (int ni = 0; ni < 4; ni++)
            wmma::fill_fragment(acc[mi][ni], 0.0f);

    load_tile(0); store_tile(0); __syncthreads();

    #pragma unroll 1
    for (int kt = 0; kt < K/16; kt++) {
        bool more = (kt + 1 < K/16);
        if (more) load_tile((kt+1)*16);
        int bi = kt & 1;
        #pragma unroll
        for (int ks = 0; ks < 2; ks++) {
            wmma::fragment<wmma::matrix_a, 16, 16, 8,
                           wmma::precision::tf32, wmma::row_major> af[2];
            wmma::fragment<wmma::matrix_b, 16, 16, 8,
                           wmma::precision::tf32, wmma::row_major> bf[4];
            #pragma unroll
            for (int mi = 0; mi < 2; mi++)
                wmma::load_matrix_sync(af[mi],
                    &As[bi][(wm*32 + mi*16)*AS_STRIDE + ks*8], AS_STRIDE);
            #pragma unroll
            for (int ni = 0; ni < 4; ni++)
                wmma::load_matrix_sync(bf[ni],
                    &Bs[bi][(ks*8)*BS_STRIDE + wn*64 + ni*16], BS_STRIDE);
            #pragma unroll
            for (int mi = 0; mi < 2; mi++)
                #pragma unroll
                for (int ni = 0; ni < 4; ni++)
                    wmma::mma_sync(acc[mi][ni], af[mi], bf[ni], acc[mi][ni]);
        }
        if (more) { store_tile(bi ^ 1); __syncthreads(); }
    }
    #pragma unroll
    for (int mi = 0; mi < 2; mi++)
        #pragma unroll
        for (int ni = 0; ni < 4; ni++)
            wmma::store_matrix_sync(
                &out[(size_t)(row0 + wm*32 + mi*16)*ldc + col0 + wn*64 + ni*16],
                acc[mi][ni], ldc, wmma::mem_row_major);
}

// ---------------- RoPE ----------------
__device__ __forceinline__ float inv_freq(int j) {
    return (float)exp(-(double)j * (9.210340371976184 / 16.0));
}

__global__ void mosa_rope_kernel() {
    int g = blockIdx.x*blockDim.x + threadIdx.x;
    int j  = g & 15;
    int kk = (g >> 4) & 255;
    int bn = g >> 12;
    float pos = (float)d_idx[bn*KSEL + kk];
    float ang = pos * inv_freq(j);
    float s, c; sincosf(ang, &s, &c);
    float* p = d_mqkv + ((size_t)bn*KSEL + kk)*QKV3;
    float x1 = p[j], x2 = p[16+j];
    p[j] = x1*c - x2*s;  p[16+j] = x1*s + x2*c;
    x1 = p[64+j]; x2 = p[80+j];
    p[64+j] = x1*c - x2*s; p[80+j] = x1*s + x2*c;
}

__global__ void dense_rope_kernel() {
    int g = blockIdx.x*blockDim.x + threadIdx.x;
    int j = g & 15;
    int n = (g >> 4) & 7;
    int t = (g >> 7) & 2047;
    int b = g >> 18;
    float ang = (float)t * inv_freq(j);
    float s, c; sincosf(ang, &s, &c);
    float* p = d_dqkv + ((size_t)(b*TT + t))*(NHD*QKV3) + n*QKV3;
    float x1 = p[j], x2 = p[16+j];
    p[j] = x1*c - x2*s;  p[16+j] = x1*s + x2*c;
    x1 = p[64+j]; x2 = p[80+j];
    p[64+j] = x1*c - x2*s; p[80+j] = x1*s + x2*c;
}

// ================= flash attention (tf32 wmma, K/V register prefetch) ========
#define DF_LD 76
#define DF_SMEM_BYTES (5*64*DF_LD*4)

template<bool MOSA>
__global__ __launch_bounds__(256) void flash_wmma_kernel() {
    extern __shared__ float sm[];
    float* Qs = sm;
    float* Ks = Qs + 64*DF_LD;
    float* Vs = Ks + 64*DF_LD;
    float* Ss = Vs + 64*DF_LD;
    float* Os = Ss + 64*DF_LD;

    int qt = MOSA ? blockIdx.x : (gridDim.x - 1 - blockIdx.x);  // big blocks first
    int n = blockIdx.y, b = blockIdx.z;
    int bn = b*NHM + n;
    int tid = threadIdx.x;
    int warp = tid >> 5;
    int wm = warp >> 2, wn = warp & 3;
    int row = tid >> 2, seg = tid & 3;
    const int RS = MOSA ? QKV3 : NHD*QKV3;
    const float* src = MOSA ? d_mqkv : d_dqkv;

    // Q tile + zero O
    for (int s = tid; s < 1024; s += 256) {
        int r = s >> 4, c4 = (s & 15)*4;
        size_t base = MOSA ? ((size_t)(bn*KSEL + qt*64 + r))*QKV3
                           : ((size_t)(b*TT + qt*64 + r))*RS + n*QKV3;
        float4 v = *(const float4*)(src + base + c4);
        Qs[r*DF_LD + c4+0] = f2tf32(v.x);
        Qs[r*DF_LD + c4+1] = f2tf32(v.y);
        Qs[r*DF_LD + c4+2] = f2tf32(v.z);
        Qs[r*DF_LD + c4+3] = f2tf32(v.w);
        *(float4*)&Os[r*DF_LD + c4] = make_float4(0.f,0.f,0.f,0.f);
    }
    float m_run = NEGINF, l_run = 0.f;

    // register staging for K/V tile (4 float4 each per thread)
    float4 kpre[4], vpre[4];
    auto ld_kv = [&](int kt) {
        #pragma unroll
        for (int i = 0; i < 4; i++) {
            int s = tid + i*256;
            int r = s >> 4, c4 = (s & 15)*4;
            size_t base = MOSA ? ((size_t)(bn*KSEL + kt*64 + r))*QKV3
                               : ((size_t)(b*TT + kt*64 + r))*RS + n*QKV3;
            kpre[i] = *(const float4*)(src + base + 64 + c4);
            vpre[i] = *(const float4*)(src + base + 128 + c4);
        }
    };
    auto st_kv = [&]() {
        #pragma unroll
        for (int i = 0; i < 4; i++) {
            int s = tid + i*256;
            int r = s >> 4, c4 = (s & 15)*4;
            Ks[r*DF_LD + c4+0] = f2tf32(kpre[i].x);
            Ks[r*DF_LD + c4+1] = f2tf32(kpre[i].y);
            Ks[r*DF_LD + c4+2] = f2tf32(kpre[i].z);
            Ks[r*DF_LD + c4+3] = f2tf32(kpre[i].w);
            Vs[r*DF_LD + c4+0] = f2tf32(vpre[i].x);
            Vs[r*DF_LD + c4+1] = f2tf32(vpre[i].y);
            Vs[r*DF_LD + c4+2] = f2tf32(vpre[i].z);
            Vs[r*DF_LD + c4+3] = f2tf32(vpre[i].w);
        }
    };

    ld_kv(0);
    for (int kt = 0; kt <= qt; kt++) {
        __syncthreads();          // prev-iter readers of Ks/Vs done
        st_kv();
        __syncthreads();
        if (kt < qt) ld_kv(kt+1); // overlap next tile's gmem latency with compute

        // S = Q @ K^T
        {
            wmma::fragment<wmma::accumulator, 16, 16, 8, float> sacc[2];
            wmma::fill_fragment(sacc[0], 0.f);
            wmma::fill_fragment(sacc[1], 0.f);
            #pragma unroll
            for (int k0 = 0; k0 < 64; k0 += 8) {
                wmma::fragment<wmma::matrix_b, 16, 16, 8,
                               wmma::precision::tf32, wmma::col_major> bf;
                wmma::load_matrix_sync(bf, &Ks[(wn*16)*DF_LD + k0], DF_LD);
                #pragma unroll
                for (int mi = 0; mi < 2; mi++) {
                    wmma::fragment<wmma::matrix_a, 16, 16, 8,
                                   wmma::precision::tf32, wmma::row_major> af;
                    wmma::load_matrix_sync(af, &Qs[(wm*32 + mi*16)*DF_LD + k0], DF_LD);
                    wmma::mma_sync(sacc[mi], af, bf, sacc[mi]);
                }
            }
            #pragma unroll
            for (int mi = 0; mi < 2; mi++)
                wmma::store_matrix_sync(&Ss[(wm*32 + mi*16)*DF_LD + wn*16],
                                        sacc[mi], DF_LD, wmma::mem_row_major);
        }
        __syncthreads();

        // online softmax
        bool diag = (kt == qt);
        float svr[16];
        float mx = NEGINF;
        #pragma unroll
        for (int i = 0; i < 16; i++) {
            int c = seg*16 + i;
            float sv = Ss[row*DF_LD + c]*0.125f;
            if (diag && c > row) sv = NEGINF;
            svr[i] = sv;
            mx = fmaxf(mx, sv);
        }
        mx = fmaxf(mx, __shfl_xor_sync(0xffffffffu, mx, 1));
        mx = fmaxf(mx, __shfl_xor_sync(0xffffffffu, mx, 2));
        float mn = fmaxf(m_run, mx);
        float alpha = __expf(m_run - mn);
        float ps = 0.f;
        #pragma unroll
        for (int i = 0; i < 16; i++) {
            float p = __expf(svr[i] - mn);
            Ss[row*DF_LD + seg*16 + i] = f2tf32(p);
            ps += p;
        }
        ps += __shfl_xor_sync(0xffffffffu, ps, 1);
        ps += __shfl_xor_sync(0xffffffffu, ps, 2);
        l_run = l_run*alpha + ps;
        m_run = mn;
        #pragma unroll
        for (int i = 0; i < 16; i++)
            Os[row*DF_LD + seg*16 + i] *= alpha;
        __syncthreads();

        // O += P @ V
        {
            wmma::fragment<wmma::accumulator, 16, 16, 8, float> oacc[2];
            #pragma unroll
            for (int mi = 0; mi < 2; mi++)
                wmma::load_matrix_sync(oacc[mi],
                    &Os[(wm*32 + mi*16)*DF_LD + wn*16], DF_LD, wmma::mem_row_major);
            #pragma unroll
            for (int k0 = 0; k0 < 64; k0 += 8) {
                wmma::fragment<wmma::matrix_b, 16, 16, 8,
                               wmma::precision::tf32, wmma::row_major> bf;
                wmma::load_matrix_sync(bf, &Vs[k0*DF_LD + wn*16], DF_LD);
                #pragma unroll
                for (int mi = 0; mi < 2; mi++) {
                    wmma::fragment<wmma::matrix_a, 16, 16, 8,
                                   wmma::precision::tf32, wmma::row_major> af;
                    wmma::load_matrix_sync(af, &Ss[(wm*32 + mi*16)*DF_LD + k0], DF_LD);
                    wmma::mma_sync(oacc[mi], af, bf, oacc[mi]);
                }
            }
            #pragma unroll
            for (int mi = 0; mi < 2; mi++)
                wmma::store_matrix_sync(&Os[(wm*32 + mi*16)*DF_LD + wn*16],
                                        oacc[mi], DF_LD, wmma::mem_row_major);
        }
    }
    __syncthreads();
    if (MOSA) {
        int q = qt*64 + row;
        int tok = d_idx[bn*KSEL + q];
        float g = d_gates[bn*KSEL + q];
        float scale = g / l_run;
        #pragma unroll
        for (int i = 0; i < 16; i++) {
            int c = seg*16 + i;
            d_Y[((size_t)(b*TT + tok))*1024 + n*64 + c] = Os[row*DF_LD + c]*scale;
        }
    } else {
        float li = 1.f/l_run;
        #pragma unroll
        for (int i = 0; i < 16; i++) {
            int c = seg*16 + i;
            d_Y[((size_t)(b*TT + qt*64 + row))*1024 + 512 + n*64 + c] =
                Os[row*DF_LD + c]*li;
        }
    }
}

// ---------------- launch ----------------
extern "C" void kernel_launch(void* const* d_in, const int* in_sizes, int n_in,
                              void* d_out, int out_size) {
    const float* X     = (const float*)d_in[0];
    const float* rw    = (const float*)d_in[1];
    const float* mwqkv = (const float*)d_in[2];
    const float* mwo   = (const float*)d_in[3];
    const float* dwqkv = (const float*)d_in[4];
    const float* dwo   = (const float*)d_in[5];
    float* out = (float*)d_out;

    cudaFuncSetAttribute(flash_wmma_kernel<false>,
        cudaFuncAttributeMaxDynamicSharedMemorySize, DF_SMEM_BYTES);
    cudaFuncSetAttribute(flash_wmma_kernel<true>,
        cudaFuncAttributeMaxDynamicSharedMemorySize, DF_SMEM_BYTES);

    zeroY_kernel<<<2048, 256>>>();
    router_kernel<<<dim3(TT, BB), 256>>>(X, rw);
    topk_kernel<<<BB*NHM, 1024>>>();
    mosa_qkv_wmma_kernel<<<dim3(3, 4, BB*NHM), 256>>>(X, mwqkv);
    mosa_rope_kernel<<<256, 256>>>();
    flash_wmma_kernel<true><<<dim3(4, NHM, BB), 256, DF_SMEM_BYTES>>>();
    dense_qkv_wmma_kernel<<<dim3(12, 32), 256>>>(X, dwqkv);
    dense_rope_kernel<<<2048, 256>>>();
    flash_wmma_kernel<false><<<dim3(32, NHD, BB), 256, DF_SMEM_BYTES>>>();
    final_wmma_kernel<<<dim3(8, 32), 256>>>(mwo, dwo, out);
}

// round 10
// speedup vs baseline: 1.6749x; 1.1538x over previous
#include <cuda_runtime.h>
#include <mma.h>
#include <math.h>

using namespace nvcuda;

#define BB   2
#define TT   2048
#define HH   1024
#define HPP  64
#define NHM  8
#define NHD  8
#define KSEL 256
#define QKV3 192
#define NEGINF (-3.0e38f)

__device__ __align__(128) float d_scores[BB*NHM*TT];
__device__ __align__(128) int   d_idx   [BB*NHM*KSEL];
__device__ __align__(128) float d_gates [BB*NHM*KSEL];
__device__ __align__(128) float d_mqkv  [BB*NHM*KSEL*QKV3];
__device__ __align__(128) float d_dqkv  [(size_t)BB*TT*NHD*QKV3];
__device__ __align__(128) float d_Y     [(size_t)BB*TT*1024];

__device__ __forceinline__ float f2tf32(float f) {
    unsigned u; asm("cvt.rna.tf32.f32 %0, %1;" : "=r"(u) : "f"(f));
    return __uint_as_float(u);
}

// ---------------- zero mosa half of Y ----------------
__global__ void zeroY_kernel() {
    int i = blockIdx.x*blockDim.x + threadIdx.x;
    if (i < BB*TT*128) {
        int r = i >> 7, c = i & 127;
        *(float4*)&d_Y[(size_t)r*1024 + c*4] = make_float4(0.f,0.f,0.f,0.f);
    }
}

// ---------------- router ----------------
__global__ void router_kernel(const float* __restrict__ X,
                              const float* __restrict__ rw) {
    __shared__ float Xs[HH];
    int t = blockIdx.x, b = blockIdx.y;
    const float* xr = X + ((size_t)b*TT + t)*HH;
    for (int i = threadIdx.x; i < HH; i += blockDim.x) Xs[i] = xr[i];
    __syncthreads();
    int w = threadIdx.x >> 5, lane = threadIdx.x & 31;
    float s = 0.f;
    for (int h = lane; h < HH; h += 32) s += Xs[h] * rw[h*NHM + w];
    #pragma unroll
    for (int o = 16; o; o >>= 1) s += __shfl_down_sync(0xffffffffu, s, o);
    if (lane == 0) d_scores[((size_t)b*NHM + w)*TT + t] = s;
}

// ---------------- top-k ----------------
__global__ void topk_kernel() {
    __shared__ float vals[TT];
    __shared__ int   inds[TT];
    int bn = blockIdx.x, tid = threadIdx.x;
    const float* sc = d_scores + (size_t)bn*TT;
    for (int t = tid; t < TT; t += blockDim.x) { vals[t] = sc[t]; inds[t] = t; }
    __syncthreads();
    for (int k = 2; k <= TT; k <<= 1)
        for (int j = k >> 1; j > 0; j >>= 1) {
            for (int t = tid; t < TT; t += blockDim.x) {
                int p = t ^ j;
                if (p > t) {
                    float va = vals[t], vb = vals[p];
                    int ia = inds[t], ib = inds[p];
                    bool a_first = (va > vb) || (va == vb && ia < ib);
                    bool desc = ((t & k) == 0);
                    if (desc ? !a_first : a_first) {
                        vals[t] = vb; vals[p] = va; inds[t] = ib; inds[p] = ia;
                    }
                }
            }
            __syncthreads();
        }
    for (int k = 2; k <= KSEL; k <<= 1)
        for (int j = k >> 1; j > 0; j >>= 1) {
            for (int t = tid; t < KSEL; t += blockDim.x) {
                int p = t ^ j;
                if (p > t) {
                    int ia = inds[t], ib = inds[p];
                    bool asc = ((t & k) == 0);
                    if (asc ? (ia > ib) : (ia < ib)) { inds[t] = ib; inds[p] = ia; }
                }
            }
            __syncthreads();
        }
    for (int kk = tid; kk < KSEL; kk += blockDim.x) {
        int id = inds[kk];
        d_idx[bn*KSEL + kk] = id;
        float s = sc[id];
        d_gates[bn*KSEL + kk] = 1.f / (1.f + expf(-s));
    }
}

// ---------------- MoSA qkv via tf32 wmma (double-buffered) ----------------
#define MQ_AS 20
#define MQ_BS 68
__global__ __launch_bounds__(256) void mosa_qkv_wmma_kernel(
        const float* __restrict__ X, const float* __restrict__ W) {
    __shared__ __align__(16) float As[2][64*MQ_AS];
    __shared__ __align__(16) float Bs[2][16*MQ_BS];
    int bn = blockIdx.z, b = bn >> 3, n = bn & 7;
    int mt = blockIdx.y, nt = blockIdx.x;
    int tid = threadIdx.x;
    int warp = tid >> 5, wm = warp >> 2, wn = warp & 3;
    int arow = tid >> 2, a4 = (tid & 3)*4;
    int brow = tid >> 4, bcol = (tid & 15)*4;
    int tok = d_idx[bn*KSEL + mt*64 + arow];
    const float* Ap = X + ((size_t)b*TT + tok)*HH + a4;
    const float* Bp = W + (size_t)n*QKV3 + nt*64 + bcol;

    float4 a_st, b_st;
    auto load_tile = [&](int k0) {
        a_st = *(const float4*)(Ap + k0);
        b_st = *(const float4*)(Bp + (size_t)(k0 + brow)*(NHM*QKV3));
    };
    auto store_tile = [&](int bi) {
        float* A_ = As[bi]; float* B_ = Bs[bi];
        A_[arow*MQ_AS + a4+0] = f2tf32(a_st.x);
        A_[arow*MQ_AS + a4+1] = f2tf32(a_st.y);
        A_[arow*MQ_AS + a4+2] = f2tf32(a_st.z);
        A_[arow*MQ_AS + a4+3] = f2tf32(a_st.w);
        B_[brow*MQ_BS + bcol+0] = f2tf32(b_st.x);
        B_[brow*MQ_BS + bcol+1] = f2tf32(b_st.y);
        B_[brow*MQ_BS + bcol+2] = f2tf32(b_st.z);
        B_[brow*MQ_BS + bcol+3] = f2tf32(b_st.w);
    };

    wmma::fragment<wmma::accumulator, 16, 16, 8, float> acc[2];
    wmma::fill_fragment(acc[0], 0.f);
    wmma::fill_fragment(acc[1], 0.f);

    load_tile(0); store_tile(0); __syncthreads();

    #pragma unroll 1
    for (int kt = 0; kt < HH/16; kt++) {
        bool more = (kt + 1 < HH/16);
        if (more) load_tile((kt+1)*16);
        int bi = kt & 1;
        #pragma unroll
        for (int ks = 0; ks < 2; ks++) {
            wmma::fragment<wmma::matrix_b, 16, 16, 8,
                           wmma::precision::tf32, wmma::row_major> bf;
            wmma::load_matrix_sync(bf, &Bs[bi][(ks*8)*MQ_BS + wn*16], MQ_BS);
            #pragma unroll
            for (int mi = 0; mi < 2; mi++) {
                wmma::fragment<wmma::matrix_a, 16, 16, 8,
                               wmma::precision::tf32, wmma::row_major> af;
                wmma::load_matrix_sync(af, &As[bi][(wm*32 + mi*16)*MQ_AS + ks*8], MQ_AS);
                wmma::mma_sync(acc[mi], af, bf, acc[mi]);
            }
        }
        if (more) { store_tile(bi ^ 1); __syncthreads(); }
    }
    #pragma unroll
    for (int mi = 0; mi < 2; mi++)
        wmma::store_matrix_sync(
            &d_mqkv[((size_t)bn*KSEL + mt*64 + wm*32 + mi*16)*QKV3 + nt*64 + wn*16],
            acc[mi], QKV3, wmma::mem_row_major);
}

// ================= tf32 WMMA GEMM (double-buffered) ==========================
#define AS_STRIDE 20
#define BS_STRIDE 136

__global__ __launch_bounds__(256) void dense_qkv_wmma_kernel(
        const float* __restrict__ A, const float* __restrict__ B)
{
    __shared__ __align__(16) float As[2][128*AS_STRIDE];
    __shared__ __align__(16) float Bs[2][16*BS_STRIDE];
    const int K = HH, lda = HH, ldb = NHD*QKV3, ldc = NHD*QKV3;
    int tid = threadIdx.x;
    int warp = tid >> 5;
    int wm = warp >> 1, wn = warp & 1;
    int row0 = blockIdx.y*128, col0 = blockIdx.x*128;
    int arow = tid >> 2, acol = (tid & 3)*4;
    int brow = tid >> 5, bcol = (tid & 31)*4;

    const float* Ag = A + (size_t)(row0 + arow)*lda + acol;
    const float* Bg = B + col0 + bcol;

    float4 a0, a1, b0, b1;
    auto load_tile = [&](int k0) {
        a0 = *(const float4*)(Ag + k0);
        a1 = *(const float4*)(Ag + (size_t)64*lda + k0);
        b0 = *(const float4*)(Bg + (size_t)(k0 + brow)*ldb);
        b1 = *(const float4*)(Bg + (size_t)(k0 + brow + 8)*ldb);
    };
    auto store_tile = [&](int bi) {
        float* A_ = As[bi]; float* B_ = Bs[bi];
        A_[arow*AS_STRIDE + acol+0] = f2tf32(a0.x);
        A_[arow*AS_STRIDE + acol+1] = f2tf32(a0.y);
        A_[arow*AS_STRIDE + acol+2] = f2tf32(a0.z);
        A_[arow*AS_STRIDE + acol+3] = f2tf32(a0.w);
        A_[(arow+64)*AS_STRIDE + acol+0] = f2tf32(a1.x);
        A_[(arow+64)*AS_STRIDE + acol+1] = f2tf32(a1.y);
        A_[(arow+64)*AS_STRIDE + acol+2] = f2tf32(a1.z);
        A_[(arow+64)*AS_STRIDE + acol+3] = f2tf32(a1.w);
        B_[brow*BS_STRIDE + bcol+0] = f2tf32(b0.x);
        B_[brow*BS_STRIDE + bcol+1] = f2tf32(b0.y);
        B_[brow*BS_STRIDE + bcol+2] = f2tf32(b0.z);
        B_[brow*BS_STRIDE + bcol+3] = f2tf32(b0.w);
        B_[(brow+8)*BS_STRIDE + bcol+0] = f2tf32(b1.x);
        B_[(brow+8)*BS_STRIDE + bcol+1] = f2tf32(b1.y);
        B_[(brow+8)*BS_STRIDE + bcol+2] = f2tf32(b1.z);
        B_[(brow+8)*BS_STRIDE + bcol+3] = f2tf32(b1.w);
    };

    wmma::fragment<wmma::accumulator, 16, 16, 8, float> acc[2][4];
    #pragma unroll
    for (int mi = 0; mi < 2; mi++)
        #pragma unroll
        for (int ni = 0; ni < 4; ni++)
            wmma::fill_fragment(acc[mi][ni], 0.0f);

    load_tile(0); store_tile(0); __syncthreads();

    #pragma unroll 1
    for (int kt = 0; kt < K/16; kt++) {
        bool more = (kt + 1 < K/16);
        if (more) load_tile((kt+1)*16);
        int bi = kt & 1;
        #pragma unroll
        for (int ks = 0; ks < 2; ks++) {
            wmma::fragment<wmma::matrix_a, 16, 16, 8,
                           wmma::precision::tf32, wmma::row_major> af[2];
            wmma::fragment<wmma::matrix_b, 16, 16, 8,
                           wmma::precision::tf32, wmma::row_major> bf[4];
            #pragma unroll
            for (int mi = 0; mi < 2; mi++)
                wmma::load_matrix_sync(af[mi],
                    &As[bi][(wm*32 + mi*16)*AS_STRIDE + ks*8], AS_STRIDE);
            #pragma unroll
            for (int ni = 0; ni < 4; ni++)
                wmma::load_matrix_sync(bf[ni],
                    &Bs[bi][(ks*8)*BS_STRIDE + wn*64 + ni*16], BS_STRIDE);
            #pragma unroll
            for (int mi = 0; mi < 2; mi++)
                #pragma unroll
                for (int ni = 0; ni < 4; ni++)
                    wmma::mma_sync(acc[mi][ni], af[mi], bf[ni], acc[mi][ni]);
        }
        if (more) { store_tile(bi ^ 1); __syncthreads(); }
    }
    #pragma unroll
    for (int mi = 0; mi < 2; mi++)
        #pragma unroll
        for (int ni = 0; ni < 4; ni++)
            wmma::store_matrix_sync(
                &d_dqkv[(size_t)(row0 + wm*32 + mi*16)*ldc + col0 + wn*64 + ni*16],
                acc[mi][ni], ldc, wmma::mem_row_major);
}

__global__ __launch_bounds__(256) void final_wmma_kernel(
        const float* __restrict__ mwo, const float* __restrict__ dwo,
        float* __restrict__ out)
{
    __shared__ __align__(16) float As[2][128*AS_STRIDE];
    __shared__ __align__(16) float Bs[2][16*BS_STRIDE];
    const int K = 1024, lda = 1024, ldb = 1024, ldc = 1024;
    int tid = threadIdx.x;
    int warp = tid >> 5;
    int wm = warp >> 1, wn = warp & 1;
    int row0 = blockIdx.y*128, col0 = blockIdx.x*128;
    int arow = tid >> 2, acol = (tid & 3)*4;
    int brow = tid >> 5, bcol = (tid & 31)*4;

    const float* Ag = d_Y + (size_t)(row0 + arow)*lda + acol;

    float4 a0, a1, b0, b1;
    auto load_tile = [&](int k0) {
        a0 = *(const float4*)(Ag + k0);
        a1 = *(const float4*)(Ag + (size_t)64*lda + k0);
        int r0 = k0 + brow, r1 = k0 + brow + 8;
        const float* p0 = (r0 < 512) ? (mwo + (size_t)r0*ldb)
                                     : (dwo + (size_t)(r0 - 512)*ldb);
        const float* p1 = (r1 < 512) ? (mwo + (size_t)r1*ldb)
                                     : (dwo + (size_t)(r1 - 512)*ldb);
        b0 = *(const float4*)(p0 + col0 + bcol);
        b1 = *(const float4*)(p1 + col0 + bcol);
    };
    auto store_tile = [&](int bi) {
        float* A_ = As[bi]; float* B_ = Bs[bi];
        A_[arow*AS_STRIDE + acol+0] = f2tf32(a0.x);
        A_[arow*AS_STRIDE + acol+1] = f2tf32(a0.y);
        A_[arow*AS_STRIDE + acol+2] = f2tf32(a0.z);
        A_[arow*AS_STRIDE + acol+3] = f2tf32(a0.w);
        A_[(arow+64)*AS_STRIDE + acol+0] = f2tf32(a1.x);
        A_[(arow+64)*AS_STRIDE + acol+1] = f2tf32(a1.y);
        A_[(arow+64)*AS_STRIDE + acol+2] = f2tf32(a1.z);
        A_[(arow+64)*AS_STRIDE + acol+3] = f2tf32(a1.w);
        B_[brow*BS_STRIDE + bcol+0] = f2tf32(b0.x);
        B_[brow*BS_STRIDE + bcol+1] = f2tf32(b0.y);
        B_[brow*BS_STRIDE + bcol+2] = f2tf32(b0.z);
        B_[brow*BS_STRIDE + bcol+3] = f2tf32(b0.w);
        B_[(brow+8)*BS_STRIDE + bcol+0] = f2tf32(b1.x);
        B_[(brow+8)*BS_STRIDE + bcol+1] = f2tf32(b1.y);
        B_[(brow+8)*BS_STRIDE + bcol+2] = f2tf32(b1.z);
        B_[(brow+8)*BS_STRIDE + bcol+3] = f2tf32(b1.w);
    };

    wmma::fragment<wmma::accumulator, 16, 16, 8, float> acc[2][4];
    #pragma unroll
    for (int mi = 0; mi < 2; mi++)
        #pragma unroll
        for (int ni = 0; ni < 4; ni++)
            wmma::fill_fragment(acc[mi][ni], 0.0f);

    load_tile(0); store_tile(0); __syncthreads();

    #pragma unroll 1
    for (int kt = 0; kt < K/16; kt++) {
        bool more = (kt + 1 < K/16);
        if (more) load_tile((kt+1)*16);
        int bi = kt & 1;
        #pragma unroll
        for (int ks = 0; ks < 2; ks++) {
            wmma::fragment<wmma::matrix_a, 16, 16, 8,
                           wmma::precision::tf32, wmma::row_major> af[2];
            wmma::fragment<wmma::matrix_b, 16, 16, 8,
                           wmma::precision::tf32, wmma::row_major> bf[4];
            #pragma unroll
            for (int mi = 0; mi < 2; mi++)
                wmma::load_matrix_sync(af[mi],
                    &As[bi][(wm*32 + mi*16)*AS_STRIDE + ks*8], AS_STRIDE);
            #pragma unroll
            for (int ni = 0; ni < 4; ni++)
                wmma::load_matrix_sync(bf[ni],
                    &Bs[bi][(ks*8)*BS_STRIDE + wn*64 + ni*16], BS_STRIDE);
            #pragma unroll
            for (int mi = 0; mi < 2; mi++)
                #pragma unroll
                for (int ni = 0; ni < 4; ni++)
                    wmma::mma_sync(acc[mi][ni], af[mi], bf[ni], acc[mi][ni]);
        }
        if (more) { store_tile(bi ^ 1); __syncthreads(); }
    }
    #pragma unroll
    for (int mi = 0; mi < 2; mi++)
        #pragma unroll
        for (int ni = 0; ni < 4; ni++)
            wmma::store_matrix_sync(
                &out[(size_t)(row0 + wm*32 + mi*16)*ldc + col0 + wn*64 + ni*16],
                acc[mi][ni], ldc, wmma::mem_row_major);
}

// ---------------- RoPE ----------------
__device__ __forceinline__ float inv_freq(int j) {
    return (float)exp(-(double)j * (9.210340371976184 / 16.0));
}

__global__ void mosa_rope_kernel() {
    int g = blockIdx.x*blockDim.x + threadIdx.x;
    int j  = g & 15;
    int kk = (g >> 4) & 255;
    int bn = g >> 12;
    float pos = (float)d_idx[bn*KSEL + kk];
    float ang = pos * inv_freq(j);
    float s, c; sincosf(ang, &s, &c);
    float* p = d_mqkv + ((size_t)bn*KSEL + kk)*QKV3;
    float x1 = p[j], x2 = p[16+j];
    p[j] = x1*c - x2*s;  p[16+j] = x1*s + x2*c;
    x1 = p[64+j]; x2 = p[80+j];
    p[64+j] = x1*c - x2*s; p[80+j] = x1*s + x2*c;
}

__global__ void dense_rope_kernel() {
    int g = blockIdx.x*blockDim.x + threadIdx.x;
    int j = g & 15;
    int n = (g >> 4) & 7;
    int t = (g >> 7) & 2047;
    int b = g >> 18;
    float ang = (float)t * inv_freq(j);
    float s, c; sincosf(ang, &s, &c);
    float* p = d_dqkv + ((size_t)(b*TT + t))*(NHD*QKV3) + n*QKV3;
    float x1 = p[j], x2 = p[16+j];
    p[j] = x1*c - x2*s;  p[16+j] = x1*s + x2*c;
    x1 = p[64+j]; x2 = p[80+j];
    p[64+j] = x1*c - x2*s; p[80+j] = x1*s + x2*c;
}

// ================= flash attention (tf32 wmma, K/V register prefetch) ========
#define DF_LD 76
#define DF_SMEM_BYTES (5*64*DF_LD*4)

template<bool MOSA>
__global__ __launch_bounds__(256) void flash_wmma_kernel() {
    extern __shared__ float sm[];
    float* Qs = sm;
    float* Ks = Qs + 64*DF_LD;
    float* Vs = Ks + 64*DF_LD;
    float* Ss = Vs + 64*DF_LD;
    float* Os = Ss + 64*DF_LD;

    int qt = MOSA ? blockIdx.x : (gridDim.x - 1 - blockIdx.x);
    int n = blockIdx.y, b = blockIdx.z;
    int bn = b*NHM + n;
    int tid = threadIdx.x;
    int warp = tid >> 5;
    int wm = warp >> 2, wn = warp & 3;
    int row = tid >> 2, seg = tid & 3;
    const int RS = MOSA ? QKV3 : NHD*QKV3;
    const float* src = MOSA ? d_mqkv : d_dqkv;

    for (int s = tid; s < 1024; s += 256) {
        int r = s >> 4, c4 = (s & 15)*4;
        size_t base = MOSA ? ((size_t)(bn*KSEL + qt*64 + r))*QKV3
                           : ((size_t)(b*TT + qt*64 + r))*RS + n*QKV3;
        float4 v = *(const float4*)(src + base + c4);
        Qs[r*DF_LD + c4+0] = f2tf32(v.x);
        Qs[r*DF_LD + c4+1] = f2tf32(v.y);
        Qs[r*DF_LD + c4+2] = f2tf32(v.z);
        Qs[r*DF_LD + c4+3] = f2tf32(v.w);
        *(float4*)&Os[r*DF_LD + c4] = make_float4(0.f,0.f,0.f,0.f);
    }
    float m_run = NEGINF, l_run = 0.f;

    float4 kpre[4], vpre[4];
    auto ld_kv = [&](int kt) {
        #pragma unroll
        for (int i = 0; i < 4; i++) {
            int s = tid + i*256;
            int r = s >> 4, c4 = (s & 15)*4;
            size_t base = MOSA ? ((size_t)(bn*KSEL + kt*64 + r))*QKV3
                               : ((size_t)(b*TT + kt*64 + r))*RS + n*QKV3;
            kpre[i] = *(const float4*)(src + base + 64 + c4);
            vpre[i] = *(const float4*)(src + base + 128 + c4);
        }
    };
    auto st_kv = [&]() {
        #pragma unroll
        for (int i = 0; i < 4; i++) {
            int s = tid + i*256;
            int r = s >> 4, c4 = (s & 15)*4;
            Ks[r*DF_LD + c4+0] = f2tf32(kpre[i].x);
            Ks[r*DF_LD + c4+1] = f2tf32(kpre[i].y);
            Ks[r*DF_LD + c4+2] = f2tf32(kpre[i].z);
            Ks[r*DF_LD + c4+3] = f2tf32(kpre[i].w);
            Vs[r*DF_LD + c4+0] = f2tf32(vpre[i].x);
            Vs[r*DF_LD + c4+1] = f2tf32(vpre[i].y);
            Vs[r*DF_LD + c4+2] = f2tf32(vpre[i].z);
            Vs[r*DF_LD + c4+3] = f2tf32(vpre[i].w);
        }
    };

    ld_kv(0);
    for (int kt = 0; kt <= qt; kt++) {
        __syncthreads();
        st_kv();
        __syncthreads();
        if (kt < qt) ld_kv(kt+1);

        {
            wmma::fragment<wmma::accumulator, 16, 16, 8, float> sacc[2];
            wmma::fill_fragment(sacc[0], 0.f);
            wmma::fill_fragment(sacc[1], 0.f);
            #pragma unroll
            for (int k0 = 0; k0 < 64; k0 += 8) {
                wmma::fragment<wmma::matrix_b, 16, 16, 8,
                               wmma::precision::tf32, wmma::col_major> bf;
                wmma::load_matrix_sync(bf, &Ks[(wn*16)*DF_LD + k0], DF_LD);
                #pragma unroll
                for (int mi = 0; mi < 2; mi++) {
                    wmma::fragment<wmma::matrix_a, 16, 16, 8,
                                   wmma::precision::tf32, wmma::row_major> af;
                    wmma::load_matrix_sync(af, &Qs[(wm*32 + mi*16)*DF_LD + k0], DF_LD);
                    wmma::mma_sync(sacc[mi], af, bf, sacc[mi]);
                }
            }
            #pragma unroll
            for (int mi = 0; mi < 2; mi++)
                wmma::store_matrix_sync(&Ss[(wm*32 + mi*16)*DF_LD + wn*16],
                                        sacc[mi], DF_LD, wmma::mem_row_major);
        }
        __syncthreads();

        bool diag = (kt == qt);
        float svr[16];
        float mx = NEGINF;
        #pragma unroll
        for (int i = 0; i < 16; i++) {
            int c = seg*16 + i;
            float sv = Ss[row*DF_LD + c]*0.125f;
            if (diag && c > row) sv = NEGINF;
            svr[i] = sv;
            mx = fmaxf(mx, sv);
        }
        mx = fmaxf(mx, __shfl_xor_sync(0xffffffffu, mx, 1));
        mx = fmaxf(mx, __shfl_xor_sync(0xffffffffu, mx, 2));
        float mn = fmaxf(m_run, mx);
        float alpha = __expf(m_run - mn);
        float ps = 0.f;
        #pragma unroll
        for (int i = 0; i < 16; i++) {
            float p = __expf(svr[i] - mn);
            Ss[row*DF_LD + seg*16 + i] = f2tf32(p);
            ps += p;
        }
        ps += __shfl_xor_sync(0xffffffffu, ps, 1);
        ps += __shfl_xor_sync(0xffffffffu, ps, 2);
        l_run = l_run*alpha + ps;
        m_run = mn;
        #pragma unroll
        for (int i = 0; i < 16; i++)
            Os[row*DF_LD + seg*16 + i] *= alpha;
        __syncthreads();

        {
            wmma::fragment<wmma::accumulator, 16, 16, 8, float> oacc[2];
            #pragma unroll
            for (int mi = 0; mi < 2; mi++)
                wmma::load_matrix_sync(oacc[mi],
                    &Os[(wm*32 + mi*16)*DF_LD + wn*16], DF_LD, wmma::mem_row_major);
            #pragma unroll
            for (int k0 = 0; k0 < 64; k0 += 8) {
                wmma::fragment<wmma::matrix_b, 16, 16, 8,
                               wmma::precision::tf32, wmma::row_major> bf;
                wmma::load_matrix_sync(bf, &Vs[k0*DF_LD + wn*16], DF_LD);
                #pragma unroll
                for (int mi = 0; mi < 2; mi++) {
                    wmma::fragment<wmma::matrix_a, 16, 16, 8,
                                   wmma::precision::tf32, wmma::row_major> af;
                    wmma::load_matrix_sync(af, &Ss[(wm*32 + mi*16)*DF_LD + k0], DF_LD);
                    wmma::mma_sync(oacc[mi], af, bf, oacc[mi]);
                }
            }
            #pragma unroll
            for (int mi = 0; mi < 2; mi++)
                wmma::store_matrix_sync(&Os[(wm*32 + mi*16)*DF_LD + wn*16],
                                        oacc[mi], DF_LD, wmma::mem_row_major);
        }
    }
    __syncthreads();
    if (MOSA) {
        int q = qt*64 + row;
        int tok = d_idx[bn*KSEL + q];
        float g = d_gates[bn*KSEL + q];
        float scale = g / l_run;
        #pragma unroll
        for (int i = 0; i < 16; i++) {
            int c = seg*16 + i;
            d_Y[((size_t)(b*TT + tok))*1024 + n*64 + c] = Os[row*DF_LD + c]*scale;
        }
    } else {
        float li = 1.f/l_run;
        #pragma unroll
        for (int i = 0; i < 16; i++) {
            int c = seg*16 + i;
            d_Y[((size_t)(b*TT + qt*64 + row))*1024 + 512 + n*64 + c] =
                Os[row*DF_LD + c]*li;
        }
    }
}

// ---------------- launch: fork-join graph (mosa branch ∥ dense branch) -------
extern "C" void kernel_launch(void* const* d_in, const int* in_sizes, int n_in,
                              void* d_out, int out_size) {
    const float* X     = (const float*)d_in[0];
    const float* rw    = (const float*)d_in[1];
    const float* mwqkv = (const float*)d_in[2];
    const float* mwo   = (const float*)d_in[3];
    const float* dwqkv = (const float*)d_in[4];
    const float* dwo   = (const float*)d_in[5];
    float* out = (float*)d_out;

    // One-time handles (resource caching only; the captured WORK is identical
    // on every call — same kernels, same dependencies).
    static cudaStream_t sB = nullptr;
    static cudaEvent_t eFork = nullptr, eJoin = nullptr;
    if (sB == nullptr) {
        cudaStreamCreateWithFlags(&sB, cudaStreamNonBlocking);
        cudaEventCreateWithFlags(&eFork, cudaEventDisableTiming);
        cudaEventCreateWithFlags(&eJoin, cudaEventDisableTiming);
    }

    cudaFuncSetAttribute(flash_wmma_kernel<false>,
        cudaFuncAttributeMaxDynamicSharedMemorySize, DF_SMEM_BYTES);
    cudaFuncSetAttribute(flash_wmma_kernel<true>,
        cudaFuncAttributeMaxDynamicSharedMemorySize, DF_SMEM_BYTES);

    // fork
    cudaEventRecord(eFork, 0);
    cudaStreamWaitEvent(sB, eFork, 0);

    // ---- branch A (default stream): mosa chain ----
    zeroY_kernel<<<2048, 256>>>();
    router_kernel<<<dim3(TT, BB), 256>>>(X, rw);
    topk_kernel<<<BB*NHM, 1024>>>();
    mosa_qkv_wmma_kernel<<<dim3(3, 4, BB*NHM), 256>>>(X, mwqkv);
    mosa_rope_kernel<<<256, 256>>>();
    flash_wmma_kernel<true><<<dim3(4, NHM, BB), 256, DF_SMEM_BYTES>>>();

    // ---- branch B (side stream): dense chain ----
    dense_qkv_wmma_kernel<<<dim3(12, 32), 256, 0, sB>>>(X, dwqkv);
    dense_rope_kernel<<<2048, 256, 0, sB>>>();
    flash_wmma_kernel<false><<<dim3(32, NHD, BB), 256, DF_SMEM_BYTES, sB>>>();

    // join
    cudaEventRecord(eJoin, sB);
    cudaStreamWaitEvent(0, eJoin, 0);

    final_wmma_kernel<<<dim3(8, 32), 256>>>(mwo, dwo, out);
}

// round 11
// speedup vs baseline: 1.9203x; 1.1465x over previous
#include <cuda_runtime.h>
#include <mma.h>
#include <math.h>

using namespace nvcuda;

#define BB   2
#define TT   2048
#define HH   1024
#define HPP  64
#define NHM  8
#define NHD  8
#define KSEL 256
#define QKV3 192
#define NEGINF (-3.0e38f)

__device__ __align__(128) float d_scores[BB*NHM*TT];
__device__ __align__(128) int   d_idx   [BB*NHM*KSEL];
__device__ __align__(128) float d_gates [BB*NHM*KSEL];
__device__ __align__(128) float d_mqkv  [BB*NHM*KSEL*QKV3];
__device__ __align__(128) float d_dqkv  [(size_t)BB*TT*NHD*QKV3];
__device__ __align__(128) float d_Y     [(size_t)BB*TT*1024];

__device__ __forceinline__ float f2tf32(float f) {
    unsigned u; asm("cvt.rna.tf32.f32 %0, %1;" : "=r"(u) : "f"(f));
    return __uint_as_float(u);
}

__device__ __forceinline__ void mma_tf32(float* c, const unsigned* a,
                                         unsigned b0, unsigned b1) {
    asm volatile("mma.sync.aligned.m16n8k8.row.col.f32.tf32.tf32.f32 "
        "{%0,%1,%2,%3}, {%4,%5,%6,%7}, {%8,%9}, {%0,%1,%2,%3};"
        : "+f"(c[0]), "+f"(c[1]), "+f"(c[2]), "+f"(c[3])
        : "r"(a[0]), "r"(a[1]), "r"(a[2]), "r"(a[3]), "r"(b0), "r"(b1));
}

// ---------------- zero mosa half of Y ----------------
__global__ void zeroY_kernel() {
    int i = blockIdx.x*blockDim.x + threadIdx.x;
    if (i < BB*TT*128) {
        int r = i >> 7, c = i & 127;
        *(float4*)&d_Y[(size_t)r*1024 + c*4] = make_float4(0.f,0.f,0.f,0.f);
    }
}

// ---------------- router ----------------
__global__ void router_kernel(const float* __restrict__ X,
                              const float* __restrict__ rw) {
    __shared__ float Xs[HH];
    int t = blockIdx.x, b = blockIdx.y;
    const float* xr = X + ((size_t)b*TT + t)*HH;
    for (int i = threadIdx.x; i < HH; i += blockDim.x) Xs[i] = xr[i];
    __syncthreads();
    int w = threadIdx.x >> 5, lane = threadIdx.x & 31;
    float s = 0.f;
    for (int h = lane; h < HH; h += 32) s += Xs[h] * rw[h*NHM + w];
    #pragma unroll
    for (int o = 16; o; o >>= 1) s += __shfl_down_sync(0xffffffffu, s, o);
    if (lane == 0) d_scores[((size_t)b*NHM + w)*TT + t] = s;
}

// ---------------- top-k ----------------
__global__ void topk_kernel() {
    __shared__ float vals[TT];
    __shared__ int   inds[TT];
    int bn = blockIdx.x, tid = threadIdx.x;
    const float* sc = d_scores + (size_t)bn*TT;
    for (int t = tid; t < TT; t += blockDim.x) { vals[t] = sc[t]; inds[t] = t; }
    __syncthreads();
    for (int k = 2; k <= TT; k <<= 1)
        for (int j = k >> 1; j > 0; j >>= 1) {
            for (int t = tid; t < TT; t += blockDim.x) {
                int p = t ^ j;
                if (p > t) {
                    float va = vals[t], vb = vals[p];
                    int ia = inds[t], ib = inds[p];
                    bool a_first = (va > vb) || (va == vb && ia < ib);
                    bool desc = ((t & k) == 0);
                    if (desc ? !a_first : a_first) {
                        vals[t] = vb; vals[p] = va; inds[t] = ib; inds[p] = ia;
                    }
                }
            }
            __syncthreads();
        }
    for (int k = 2; k <= KSEL; k <<= 1)
        for (int j = k >> 1; j > 0; j >>= 1) {
            for (int t = tid; t < KSEL; t += blockDim.x) {
                int p = t ^ j;
                if (p > t) {
                    int ia = inds[t], ib = inds[p];
                    bool asc = ((t & k) == 0);
                    if (asc ? (ia > ib) : (ia < ib)) { inds[t] = ib; inds[p] = ia; }
                }
            }
            __syncthreads();
        }
    for (int kk = tid; kk < KSEL; kk += blockDim.x) {
        int id = inds[kk];
        d_idx[bn*KSEL + kk] = id;
        float s = sc[id];
        d_gates[bn*KSEL + kk] = 1.f / (1.f + expf(-s));
    }
}

// ---------------- MoSA qkv via tf32 wmma (double-buffered) ----------------
#define MQ_AS 20
#define MQ_BS 68
__global__ __launch_bounds__(256) void mosa_qkv_wmma_kernel(
        const float* __restrict__ X, const float* __restrict__ W) {
    __shared__ __align__(16) float As[2][64*MQ_AS];
    __shared__ __align__(16) float Bs[2][16*MQ_BS];
    int bn = blockIdx.z, b = bn >> 3, n = bn & 7;
    int mt = blockIdx.y, nt = blockIdx.x;
    int tid = threadIdx.x;
    int warp = tid >> 5, wm = warp >> 2, wn = warp & 3;
    int arow = tid >> 2, a4 = (tid & 3)*4;
    int brow = tid >> 4, bcol = (tid & 15)*4;
    int tok = d_idx[bn*KSEL + mt*64 + arow];
    const float* Ap = X + ((size_t)b*TT + tok)*HH + a4;
    const float* Bp = W + (size_t)n*QKV3 + nt*64 + bcol;

    float4 a_st, b_st;
    auto load_tile = [&](int k0) {
        a_st = *(const float4*)(Ap + k0);
        b_st = *(const float4*)(Bp + (size_t)(k0 + brow)*(NHM*QKV3));
    };
    auto store_tile = [&](int bi) {
        float* A_ = As[bi]; float* B_ = Bs[bi];
        A_[arow*MQ_AS + a4+0] = f2tf32(a_st.x);
        A_[arow*MQ_AS + a4+1] = f2tf32(a_st.y);
        A_[arow*MQ_AS + a4+2] = f2tf32(a_st.z);
        A_[arow*MQ_AS + a4+3] = f2tf32(a_st.w);
        B_[brow*MQ_BS + bcol+0] = f2tf32(b_st.x);
        B_[brow*MQ_BS + bcol+1] = f2tf32(b_st.y);
        B_[brow*MQ_BS + bcol+2] = f2tf32(b_st.z);
        B_[brow*MQ_BS + bcol+3] = f2tf32(b_st.w);
    };

    wmma::fragment<wmma::accumulator, 16, 16, 8, float> acc[2];
    wmma::fill_fragment(acc[0], 0.f);
    wmma::fill_fragment(acc[1], 0.f);

    load_tile(0); store_tile(0); __syncthreads();

    #pragma unroll 1
    for (int kt = 0; kt < HH/16; kt++) {
        bool more = (kt + 1 < HH/16);
        if (more) load_tile((kt+1)*16);
        int bi = kt & 1;
        #pragma unroll
        for (int ks = 0; ks < 2; ks++) {
            wmma::fragment<wmma::matrix_b, 16, 16, 8,
                           wmma::precision::tf32, wmma::row_major> bf;
            wmma::load_matrix_sync(bf, &Bs[bi][(ks*8)*MQ_BS + wn*16], MQ_BS);
            #pragma unroll
            for (int mi = 0; mi < 2; mi++) {
                wmma::fragment<wmma::matrix_a, 16, 16, 8,
                               wmma::precision::tf32, wmma::row_major> af;
                wmma::load_matrix_sync(af, &As[bi][(wm*32 + mi*16)*MQ_AS + ks*8], MQ_AS);
                wmma::mma_sync(acc[mi], af, bf, acc[mi]);
            }
        }
        if (more) { store_tile(bi ^ 1); __syncthreads(); }
    }
    #pragma unroll
    for (int mi = 0; mi < 2; mi++)
        wmma::store_matrix_sync(
            &d_mqkv[((size_t)bn*KSEL + mt*64 + wm*32 + mi*16)*QKV3 + nt*64 + wn*16],
            acc[mi], QKV3, wmma::mem_row_major);
}

// ================= tf32 WMMA GEMM (double-buffered) ==========================
#define AS_STRIDE 20
#define BS_STRIDE 136

__global__ __launch_bounds__(256) void dense_qkv_wmma_kernel(
        const float* __restrict__ A, const float* __restrict__ B)
{
    __shared__ __align__(16) float As[2][128*AS_STRIDE];
    __shared__ __align__(16) float Bs[2][16*BS_STRIDE];
    const int K = HH, lda = HH, ldb = NHD*QKV3, ldc = NHD*QKV3;
    int tid = threadIdx.x;
    int warp = tid >> 5;
    int wm = warp >> 1, wn = warp & 1;
    int row0 = blockIdx.y*128, col0 = blockIdx.x*128;
    int arow = tid >> 2, acol = (tid & 3)*4;
    int brow = tid >> 5, bcol = (tid & 31)*4;

    const float* Ag = A + (size_t)(row0 + arow)*lda + acol;
    const float* Bg = B + col0 + bcol;

    float4 a0, a1, b0, b1;
    auto load_tile = [&](int k0) {
        a0 = *(const float4*)(Ag + k0);
        a1 = *(const float4*)(Ag + (size_t)64*lda + k0);
        b0 = *(const float4*)(Bg + (size_t)(k0 + brow)*ldb);
        b1 = *(const float4*)(Bg + (size_t)(k0 + brow + 8)*ldb);
    };
    auto store_tile = [&](int bi) {
        float* A_ = As[bi]; float* B_ = Bs[bi];
        A_[arow*AS_STRIDE + acol+0] = f2tf32(a0.x);
        A_[arow*AS_STRIDE + acol+1] = f2tf32(a0.y);
        A_[arow*AS_STRIDE + acol+2] = f2tf32(a0.z);
        A_[arow*AS_STRIDE + acol+3] = f2tf32(a0.w);
        A_[(arow+64)*AS_STRIDE + acol+0] = f2tf32(a1.x);
        A_[(arow+64)*AS_STRIDE + acol+1] = f2tf32(a1.y);
        A_[(arow+64)*AS_STRIDE + acol+2] = f2tf32(a1.z);
        A_[(arow+64)*AS_STRIDE + acol+3] = f2tf32(a1.w);
        B_[brow*BS_STRIDE + bcol+0] = f2tf32(b0.x);
        B_[brow*BS_STRIDE + bcol+1] = f2tf32(b0.y);
        B_[brow*BS_STRIDE + bcol+2] = f2tf32(b0.z);
        B_[brow*BS_STRIDE + bcol+3] = f2tf32(b0.w);
        B_[(brow+8)*BS_STRIDE + bcol+0] = f2tf32(b1.x);
        B_[(brow+8)*BS_STRIDE + bcol+1] = f2tf32(b1.y);
        B_[(brow+8)*BS_STRIDE + bcol+2] = f2tf32(b1.z);
        B_[(brow+8)*BS_STRIDE + bcol+3] = f2tf32(b1.w);
    };

    wmma::fragment<wmma::accumulator, 16, 16, 8, float> acc[2][4];
    #pragma unroll
    for (int mi = 0; mi < 2; mi++)
        #pragma unroll
        for (int ni = 0; ni < 4; ni++)
            wmma::fill_fragment(acc[mi][ni], 0.0f);

    load_tile(0); store_tile(0); __syncthreads();

    #pragma unroll 1
    for (int kt = 0; kt < K/16; kt++) {
        bool more = (kt + 1 < K/16);
        if (more) load_tile((kt+1)*16);
        int bi = kt & 1;
        #pragma unroll
        for (int ks = 0; ks < 2; ks++) {
            wmma::fragment<wmma::matrix_a, 16, 16, 8,
                           wmma::precision::tf32, wmma::row_major> af[2];
            wmma::fragment<wmma::matrix_b, 16, 16, 8,
                           wmma::precision::tf32, wmma::row_major> bf[4];
            #pragma unroll
            for (int mi = 0; mi < 2; mi++)
                wmma::load_matrix_sync(af[mi],
                    &As[bi][(wm*32 + mi*16)*AS_STRIDE + ks*8], AS_STRIDE);
            #pragma unroll
            for (int ni = 0; ni < 4; ni++)
                wmma::load_matrix_sync(bf[ni],
                    &Bs[bi][(ks*8)*BS_STRIDE + wn*64 + ni*16], BS_STRIDE);
            #pragma unroll
            for (int mi = 0; mi < 2; mi++)
                #pragma unroll
                for (int ni = 0; ni < 4; ni++)
                    wmma::mma_sync(acc[mi][ni], af[mi], bf[ni], acc[mi][ni]);
        }
        if (more) { store_tile(bi ^ 1); __syncthreads(); }
    }
    #pragma unroll
    for (int mi = 0; mi < 2; mi++)
        #pragma unroll
        for (int ni = 0; ni < 4; ni++)
            wmma::store_matrix_sync(
                &d_dqkv[(size_t)(row0 + wm*32 + mi*16)*ldc + col0 + wn*64 + ni*16],
                acc[mi][ni], ldc, wmma::mem_row_major);
}

__global__ __launch_bounds__(256) void final_wmma_kernel(
        const float* __restrict__ mwo, const float* __restrict__ dwo,
        float* __restrict__ out)
{
    __shared__ __align__(16) float As[2][128*AS_STRIDE];
    __shared__ __align__(16) float Bs[2][16*BS_STRIDE];
    const int K = 1024, lda = 1024, ldb = 1024, ldc = 1024;
    int tid = threadIdx.x;
    int warp = tid >> 5;
    int wm = warp >> 1, wn = warp & 1;
    int row0 = blockIdx.y*128, col0 = blockIdx.x*128;
    int arow = tid >> 2, acol = (tid & 3)*4;
    int brow = tid >> 5, bcol = (tid & 31)*4;

    const float* Ag = d_Y + (size_t)(row0 + arow)*lda + acol;

    float4 a0, a1, b0, b1;
    auto load_tile = [&](int k0) {
        a0 = *(const float4*)(Ag + k0);
        a1 = *(const float4*)(Ag + (size_t)64*lda + k0);
        int r0 = k0 + brow, r1 = k0 + brow + 8;
        const float* p0 = (r0 < 512) ? (mwo + (size_t)r0*ldb)
                                     : (dwo + (size_t)(r0 - 512)*ldb);
        const float* p1 = (r1 < 512) ? (mwo + (size_t)r1*ldb)
                                     : (dwo + (size_t)(r1 - 512)*ldb);
        b0 = *(const float4*)(p0 + col0 + bcol);
        b1 = *(const float4*)(p1 + col0 + bcol);
    };
    auto store_tile = [&](int bi) {
        float* A_ = As[bi]; float* B_ = Bs[bi];
        A_[arow*AS_STRIDE + acol+0] = f2tf32(a0.x);
        A_[arow*AS_STRIDE + acol+1] = f2tf32(a0.y);
        A_[arow*AS_STRIDE + acol+2] = f2tf32(a0.z);
        A_[arow*AS_STRIDE + acol+3] = f2tf32(a0.w);
        A_[(arow+64)*AS_STRIDE + acol+0] = f2tf32(a1.x);
        A_[(arow+64)*AS_STRIDE + acol+1] = f2tf32(a1.y);
        A_[(arow+64)*AS_STRIDE + acol+2] = f2tf32(a1.z);
        A_[(arow+64)*AS_STRIDE + acol+3] = f2tf32(a1.w);
        B_[brow*BS_STRIDE + bcol+0] = f2tf32(b0.x);
        B_[brow*BS_STRIDE + bcol+1] = f2tf32(b0.y);
        B_[brow*BS_STRIDE + bcol+2] = f2tf32(b0.z);
        B_[brow*BS_STRIDE + bcol+3] = f2tf32(b0.w);
        B_[(brow+8)*BS_STRIDE + bcol+0] = f2tf32(b1.x);
        B_[(brow+8)*BS_STRIDE + bcol+1] = f2tf32(b1.y);
        B_[(brow+8)*BS_STRIDE + bcol+2] = f2tf32(b1.z);
        B_[(brow+8)*BS_STRIDE + bcol+3] = f2tf32(b1.w);
    };

    wmma::fragment<wmma::accumulator, 16, 16, 8, float> acc[2][4];
    #pragma unroll
    for (int mi = 0; mi < 2; mi++)
        #pragma unroll
        for (int ni = 0; ni < 4; ni++)
            wmma::fill_fragment(acc[mi][ni], 0.0f);

    load_tile(0); store_tile(0); __syncthreads();

    #pragma unroll 1
    for (int kt = 0; kt < K/16; kt++) {
        bool more = (kt + 1 < K/16);
        if (more) load_tile((kt+1)*16);
        int bi = kt & 1;
        #pragma unroll
        for (int ks = 0; ks < 2; ks++) {
            wmma::fragment<wmma::matrix_a, 16, 16, 8,
                           wmma::precision::tf32, wmma::row_major> af[2];
            wmma::fragment<wmma::matrix_b, 16, 16, 8,
                           wmma::precision::tf32, wmma::row_major> bf[4];
            #pragma unroll
            for (int mi = 0; mi < 2; mi++)
                wmma::load_matrix_sync(af[mi],
                    &As[bi][(wm*32 + mi*16)*AS_STRIDE + ks*8], AS_STRIDE);
            #pragma unroll
            for (int ni = 0; ni < 4; ni++)
                wmma::load_matrix_sync(bf[ni],
                    &Bs[bi][(ks*8)*BS_STRIDE + wn*64 + ni*16], BS_STRIDE);
            #pragma unroll
            for (int mi = 0; mi < 2; mi++)
                #pragma unroll
                for (int ni = 0; ni < 4; ni++)
                    wmma::mma_sync(acc[mi][ni], af[mi], bf[ni], acc[mi][ni]);
        }
        if (more) { store_tile(bi ^ 1); __syncthreads(); }
    }
    #pragma unroll
    for (int mi = 0; mi < 2; mi++)
        #pragma unroll
        for (int ni = 0; ni < 4; ni++)
            wmma::store_matrix_sync(
                &out[(size_t)(row0 + wm*32 + mi*16)*ldc + col0 + wn*64 + ni*16],
                acc[mi][ni], ldc, wmma::mem_row_major);
}

// ---------------- RoPE ----------------
__device__ __forceinline__ float inv_freq(int j) {
    return (float)exp(-(double)j * (9.210340371976184 / 16.0));
}

__global__ void mosa_rope_kernel() {
    int g = blockIdx.x*blockDim.x + threadIdx.x;
    int j  = g & 15;
    int kk = (g >> 4) & 255;
    int bn = g >> 12;
    float pos = (float)d_idx[bn*KSEL + kk];
    float ang = pos * inv_freq(j);
    float s, c; sincosf(ang, &s, &c);
    float* p = d_mqkv + ((size_t)bn*KSEL + kk)*QKV3;
    float x1 = p[j], x2 = p[16+j];
    p[j] = x1*c - x2*s;  p[16+j] = x1*s + x2*c;
    x1 = p[64+j]; x2 = p[80+j];
    p[64+j] = x1*c - x2*s; p[80+j] = x1*s + x2*c;
}

__global__ void dense_rope_kernel() {
    int g = blockIdx.x*blockDim.x + threadIdx.x;
    int j = g & 15;
    int n = (g >> 4) & 7;
    int t = (g >> 7) & 2047;
    int b = g >> 18;
    float ang = (float)t * inv_freq(j);
    float s, c; sincosf(ang, &s, &c);
    float* p = d_dqkv + ((size_t)(b*TT + t))*(NHD*QKV3) + n*QKV3;
    float x1 = p[j], x2 = p[16+j];
    p[j] = x1*c - x2*s;  p[16+j] = x1*s + x2*c;
    x1 = p[64+j]; x2 = p[80+j];
    p[64+j] = x1*c - x2*s; p[80+j] = x1*s + x2*c;
}

// ================= FA2-style flash: register O/softmax, mma.sync tf32 ========
// BM=128, BN=64, 8 warps (warp w: rows w*16..w*16+16), 3 syncs/iter.
#define FQ_LD 68
#define FK_LD 68
#define FV_LD 76
#define FP_LD 68
#define FL_SMEM_BYTES ((128*FQ_LD + 64*FK_LD + 64*FV_LD + 128*FP_LD)*4)

template<bool MOSA>
__global__ __launch_bounds__(256, 2) void flash_fa2_kernel() {
    extern __shared__ float sm[];
    float* Qs = sm;                       // [128][FQ_LD]
    float* Ks = Qs + 128*FQ_LD;           // [64][FK_LD]
    float* Vs = Ks + 64*FK_LD;            // [64][FV_LD]
    float* Ps = Vs + 64*FV_LD;            // [128][FP_LD]

    int qt = MOSA ? blockIdx.x : (gridDim.x - 1 - blockIdx.x);
    int n = blockIdx.y, b = blockIdx.z;
    int bn = b*NHM + n;
    int tid = threadIdx.x;
    int w = tid >> 5, lane = tid & 31;
    int lq = lane >> 2, lr = lane & 3;
    const int RS = MOSA ? QKV3 : NHD*QKV3;
    const float* src = MOSA ? d_mqkv : d_dqkv;

    // load Q tile (128x64) into smem, tf32
    for (int s = tid; s < 2048; s += 256) {
        int r = s >> 4, c4 = (s & 15)*4;
        size_t base = MOSA ? ((size_t)(bn*KSEL + qt*128 + r))*QKV3
                           : ((size_t)(b*TT + qt*128 + r))*RS + n*QKV3;
        float4 v = *(const float4*)(src + base + c4);
        Qs[r*FQ_LD + c4+0] = f2tf32(v.x);
        Qs[r*FQ_LD + c4+1] = f2tf32(v.y);
        Qs[r*FQ_LD + c4+2] = f2tf32(v.z);
        Qs[r*FQ_LD + c4+3] = f2tf32(v.w);
    }

    int row0 = w*16;                      // local warp row base
    int gr0 = qt*128 + row0 + lq;         // global q row (c0,c1)
    int gr1 = gr0 + 8;                    // (c2,c3)

    float o[8][4];
    #pragma unroll
    for (int ni = 0; ni < 8; ni++)
        #pragma unroll
        for (int e = 0; e < 4; e++) o[ni][e] = 0.f;
    float m0 = NEGINF, m1 = NEGINF, l0 = 0.f, l1 = 0.f;

    int nkt = 2*qt + 2;
    for (int kt = 0; kt < nkt; kt++) {
        // K/V tile -> smem (tf32)
        for (int s = tid; s < 1024; s += 256) {
            int r = s >> 4, c4 = (s & 15)*4;
            size_t base = MOSA ? ((size_t)(bn*KSEL + kt*64 + r))*QKV3
                               : ((size_t)(b*TT + kt*64 + r))*RS + n*QKV3;
            float4 kv = *(const float4*)(src + base + 64 + c4);
            float4 vv = *(const float4*)(src + base + 128 + c4);
            Ks[r*FK_LD + c4+0] = f2tf32(kv.x);
            Ks[r*FK_LD + c4+1] = f2tf32(kv.y);
            Ks[r*FK_LD + c4+2] = f2tf32(kv.z);
            Ks[r*FK_LD + c4+3] = f2tf32(kv.w);
            Vs[r*FV_LD + c4+0] = f2tf32(vv.x);
            Vs[r*FV_LD + c4+1] = f2tf32(vv.y);
            Vs[r*FV_LD + c4+2] = f2tf32(vv.z);
            Vs[r*FV_LD + c4+3] = f2tf32(vv.w);
        }
        __syncthreads();   // (1) K/V ready (also Q on first iter)

        // ---- S = Q K^T : acc[ni] covers rows [row0,row0+16), cols [ni*8, ni*8+8)
        float sacc[8][4];
        #pragma unroll
        for (int ni = 0; ni < 8; ni++)
            #pragma unroll
            for (int e = 0; e < 4; e++) sacc[ni][e] = 0.f;
        #pragma unroll
        for (int k = 0; k < 8; k++) {
            unsigned af[4];
            af[0] = __float_as_uint(Qs[(row0 + lq)*FQ_LD + k*8 + lr]);
            af[1] = __float_as_uint(Qs[(row0 + 8 + lq)*FQ_LD + k*8 + lr]);
            af[2] = __float_as_uint(Qs[(row0 + lq)*FQ_LD + k*8 + lr + 4]);
            af[3] = __float_as_uint(Qs[(row0 + 8 + lq)*FQ_LD + k*8 + lr + 4]);
            #pragma unroll
            for (int ni = 0; ni < 8; ni++) {
                unsigned b0 = __float_as_uint(Ks[(ni*8 + lq)*FK_LD + k*8 + lr]);
                unsigned b1 = __float_as_uint(Ks[(ni*8 + lq)*FK_LD + k*8 + lr + 4]);
                mma_tf32(sacc[ni], af, b0, b1);
            }
        }

        // ---- online softmax in registers (quad owns rows gr0, gr1)
        int cbase = kt*64 + 2*lr;
        float mx0 = NEGINF, mx1 = NEGINF;
        #pragma unroll
        for (int ni = 0; ni < 8; ni++) {
            int c0 = cbase + ni*8, c1 = c0 + 1;
            float s00 = (c0 <= gr0) ? sacc[ni][0]*0.125f : NEGINF;
            float s01 = (c1 <= gr0) ? sacc[ni][1]*0.125f : NEGINF;
            float s10 = (c0 <= gr1) ? sacc[ni][2]*0.125f : NEGINF;
            float s11 = (c1 <= gr1) ? sacc[ni][3]*0.125f : NEGINF;
            sacc[ni][0] = s00; sacc[ni][1] = s01;
            sacc[ni][2] = s10; sacc[ni][3] = s11;
            mx0 = fmaxf(mx0, fmaxf(s00, s01));
            mx1 = fmaxf(mx1, fmaxf(s10, s11));
        }
        mx0 = fmaxf(mx0, __shfl_xor_sync(0xffffffffu, mx0, 1));
        mx0 = fmaxf(mx0, __shfl_xor_sync(0xffffffffu, mx0, 2));
        mx1 = fmaxf(mx1, __shfl_xor_sync(0xffffffffu, mx1, 1));
        mx1 = fmaxf(mx1, __shfl_xor_sync(0xffffffffu, mx1, 2));
        float mn0 = fmaxf(m0, mx0), mn1 = fmaxf(m1, mx1);
        float al0 = __expf(m0 - mn0), al1 = __expf(m1 - mn1);
        float ps0 = 0.f, ps1 = 0.f;
        #pragma unroll
        for (int ni = 0; ni < 8; ni++) {
            float p00 = __expf(sacc[ni][0] - mn0);
            float p01 = __expf(sacc[ni][1] - mn0);
            float p10 = __expf(sacc[ni][2] - mn1);
            float p11 = __expf(sacc[ni][3] - mn1);
            ps0 += p00 + p01;
            ps1 += p10 + p11;
            int c = ni*8 + 2*lr;
            *(float2*)&Ps[(row0 + lq)*FP_LD + c] =
                make_float2(f2tf32(p00), f2tf32(p01));
            *(float2*)&Ps[(row0 + 8 + lq)*FP_LD + c] =
                make_float2(f2tf32(p10), f2tf32(p11));
        }
        ps0 += __shfl_xor_sync(0xffffffffu, ps0, 1);
        ps0 += __shfl_xor_sync(0xffffffffu, ps0, 2);
        ps1 += __shfl_xor_sync(0xffffffffu, ps1, 1);
        ps1 += __shfl_xor_sync(0xffffffffu, ps1, 2);
        l0 = l0*al0 + ps0;  m0 = mn0;
        l1 = l1*al1 + ps1;  m1 = mn1;
        // rescale O in registers (c0,c1: row gr0; c2,c3: row gr1)
        #pragma unroll
        for (int ni = 0; ni < 8; ni++) {
            o[ni][0] *= al0; o[ni][1] *= al0;
            o[ni][2] *= al1; o[ni][3] *= al1;
        }
        __syncthreads();   // (2) P visible

        // ---- O += P V : k over keys (8 steps), ni over d (8 tiles)
        #pragma unroll
        for (int k = 0; k < 8; k++) {
            unsigned af[4];
            af[0] = __float_as_uint(Ps[(row0 + lq)*FP_LD + k*8 + lr]);
            af[1] = __float_as_uint(Ps[(row0 + 8 + lq)*FP_LD + k*8 + lr]);
            af[2] = __float_as_uint(Ps[(row0 + lq)*FP_LD + k*8 + lr + 4]);
            af[3] = __float_as_uint(Ps[(row0 + 8 + lq)*FP_LD + k*8 + lr + 4]);
            #pragma unroll
            for (int ni = 0; ni < 8; ni++) {
                unsigned b0 = __float_as_uint(Vs[(k*8 + lr)*FV_LD + ni*8 + lq]);
                unsigned b1 = __float_as_uint(Vs[(k*8 + lr + 4)*FV_LD + ni*8 + lq]);
                mma_tf32(o[ni], af, b0, b1);
            }
        }
        __syncthreads();   // (3) Ps/Vs consumed; safe to overwrite next iter
    }

    // ---- epilogue
    if (MOSA) {
        int tok0 = d_idx[bn*KSEL + gr0];
        int tok1 = d_idx[bn*KSEL + gr1];
        float s0 = d_gates[bn*KSEL + gr0] / l0;
        float s1 = d_gates[bn*KSEL + gr1] / l1;
        #pragma unroll
        for (int ni = 0; ni < 8; ni++) {
            int c = n*64 + ni*8 + 2*lr;
            *(float2*)&d_Y[((size_t)(b*TT + tok0))*1024 + c] =
                make_float2(o[ni][0]*s0, o[ni][1]*s0);
            *(float2*)&d_Y[((size_t)(b*TT + tok1))*1024 + c] =
                make_float2(o[ni][2]*s1, o[ni][3]*s1);
        }
    } else {
        float s0 = 1.f/l0, s1 = 1.f/l1;
        #pragma unroll
        for (int ni = 0; ni < 8; ni++) {
            int c = 512 + n*64 + ni*8 + 2*lr;
            *(float2*)&d_Y[((size_t)(b*TT + gr0))*1024 + c] =
                make_float2(o[ni][0]*s0, o[ni][1]*s0);
            *(float2*)&d_Y[((size_t)(b*TT + gr1))*1024 + c] =
                make_float2(o[ni][2]*s1, o[ni][3]*s1);
        }
    }
}

// ---------------- launch: fork-join graph (mosa branch ∥ dense branch) -------
extern "C" void kernel_launch(void* const* d_in, const int* in_sizes, int n_in,
                              void* d_out, int out_size) {
    const float* X     = (const float*)d_in[0];
    const float* rw    = (const float*)d_in[1];
    const float* mwqkv = (const float*)d_in[2];
    const float* mwo   = (const float*)d_in[3];
    const float* dwqkv = (const float*)d_in[4];
    const float* dwo   = (const float*)d_in[5];
    float* out = (float*)d_out;

    static cudaStream_t sB = nullptr;
    static cudaEvent_t eFork = nullptr, eJoin = nullptr;
    if (sB == nullptr) {
        cudaStreamCreateWithFlags(&sB, cudaStreamNonBlocking);
        cudaEventCreateWithFlags(&eFork, cudaEventDisableTiming);
        cudaEventCreateWithFlags(&eJoin, cudaEventDisableTiming);
        cudaFuncSetAttribute(flash_fa2_kernel<false>,
            cudaFuncAttributeMaxDynamicSharedMemorySize, FL_SMEM_BYTES);
        cudaFuncSetAttribute(flash_fa2_kernel<true>,
            cudaFuncAttributeMaxDynamicSharedMemorySize, FL_SMEM_BYTES);
    }

    cudaEventRecord(eFork, 0);
    cudaStreamWaitEvent(sB, eFork, 0);

    // ---- branch A (default stream): mosa chain ----
    zeroY_kernel<<<2048, 256>>>();
    router_kernel<<<dim3(TT, BB), 256>>>(X, rw);
    topk_kernel<<<BB*NHM, 1024>>>();
    mosa_qkv_wmma_kernel<<<dim3(3, 4, BB*NHM), 256>>>(X, mwqkv);
    mosa_rope_kernel<<<256, 256>>>();
    flash_fa2_kernel<true><<<dim3(2, NHM, BB), 256, FL_SMEM_BYTES>>>();

    // ---- branch B (side stream): dense chain ----
    dense_qkv_wmma_kernel<<<dim3(12, 32), 256, 0, sB>>>(X, dwqkv);
    dense_rope_kernel<<<2048, 256, 0, sB>>>();
    flash_fa2_kernel<false><<<dim3(16, NHD, BB), 256, FL_SMEM_BYTES, sB>>>();

    // join
    cudaEventRecord(eJoin, sB);
    cudaStreamWaitEvent(0, eJoin, 0);

    final_wmma_kernel<<<dim3(8, 32), 256>>>(mwo, dwo, out);
}

// round 13
// speedup vs baseline: 1.9207x; 1.0002x over previous
#include <cuda_runtime.h>
#include <mma.h>
#include <math.h>

using namespace nvcuda;

#define BB   2
#define TT   2048
#define HH   1024
#define HPP  64
#define NHM  8
#define NHD  8
#define KSEL 256
#define QKV3 192
#define NEGINF (-3.0e38f)

__device__ __align__(128) float d_scores[BB*NHM*TT];
__device__ __align__(128) int   d_idx   [BB*NHM*KSEL];
__device__ __align__(128) float d_gates [BB*NHM*KSEL];
__device__ __align__(128) float d_mqkv  [BB*NHM*KSEL*QKV3];
__device__ __align__(128) float d_dqkv  [(size_t)BB*TT*NHD*QKV3];
__device__ __align__(128) float d_Y     [(size_t)BB*TT*1024];

__device__ __forceinline__ float f2tf32(float f) {
    unsigned u; asm("cvt.rna.tf32.f32 %0, %1;" : "=r"(u) : "f"(f));
    return __uint_as_float(u);
}

__device__ __forceinline__ void mma_tf32(float* c, const unsigned* a,
                                         unsigned b0, unsigned b1) {
    asm volatile("mma.sync.aligned.m16n8k8.row.col.f32.tf32.tf32.f32 "
        "{%0,%1,%2,%3}, {%4,%5,%6,%7}, {%8,%9}, {%0,%1,%2,%3};"
        : "+f"(c[0]), "+f"(c[1]), "+f"(c[2]), "+f"(c[3])
        : "r"(a[0]), "r"(a[1]), "r"(a[2]), "r"(a[3]), "r"(b0), "r"(b1));
}

// ---------------- zero: mosa half of Y + d_mqkv (split-K atomic target) ------
// total work = BB*TT*128 + BB*NHM*KSEL*QKV3/4 = 524288 + 196608 = 720896 thr
#define ZERO_BLOCKS 2816
__global__ void zeroY_kernel() {
    int i = blockIdx.x*blockDim.x + threadIdx.x;
    const int NY = BB*TT*128;                 // float4s in Y mosa half
    const int NM = BB*NHM*KSEL*QKV3/4;        // float4s in d_mqkv
    if (i < NY) {
        int r = i >> 7, c = i & 127;
        *(float4*)&d_Y[(size_t)r*1024 + c*4] = make_float4(0.f,0.f,0.f,0.f);
    } else if (i - NY < NM) {
        ((float4*)d_mqkv)[i - NY] = make_float4(0.f,0.f,0.f,0.f);
    }
}

// ---------------- router ----------------
__global__ void router_kernel(const float* __restrict__ X,
                              const float* __restrict__ rw) {
    __shared__ float Xs[HH];
    int t = blockIdx.x, b = blockIdx.y;
    const float* xr = X + ((size_t)b*TT + t)*HH;
    for (int i = threadIdx.x; i < HH; i += blockDim.x) Xs[i] = xr[i];
    __syncthreads();
    int w = threadIdx.x >> 5, lane = threadIdx.x & 31;
    float s = 0.f;
    for (int h = lane; h < HH; h += 32) s += Xs[h] * rw[h*NHM + w];
    #pragma unroll
    for (int o = 16; o; o >>= 1) s += __shfl_down_sync(0xffffffffu, s, o);
    if (lane == 0) d_scores[((size_t)b*NHM + w)*TT + t] = s;
}

// ---------------- top-k via 4-level radix select + ordered compaction --------
__global__ __launch_bounds__(1024) void topk_kernel() {
    __shared__ unsigned keys[TT];
    __shared__ int hist[256];
    __shared__ int warpsum[32];
    __shared__ int bcast[2];
    int bn = blockIdx.x, tid = threadIdx.x;
    int lane = tid & 31, wid = tid >> 5;
    const float* sc = d_scores + (size_t)bn*TT;

    for (int t = tid; t < TT; t += 1024) {
        unsigned u = __float_as_uint(sc[t]);
        u ^= (u & 0x80000000u) ? 0xFFFFFFFFu : 0x80000000u;  // order-preserving flip
        keys[t] = u;
    }
    __syncthreads();

    unsigned prefix = 0;
    int need = KSEL;
    #pragma unroll 1
    for (int level = 0; level < 4; level++) {
        int shift = 24 - level*8;
        if (tid < 256) hist[tid] = 0;
        __syncthreads();
        for (int t = tid; t < TT; t += 1024) {
            unsigned k = keys[t];
            bool match = (level == 0) || ((k >> (shift + 8)) == (prefix >> (shift + 8)));
            if (match) atomicAdd(&hist[(k >> shift) & 255], 1);
        }
        __syncthreads();
        if (tid == 0) {
            int cum = 0, bsel = 0;
            for (int b = 255; b >= 0; b--) {
                int c = hist[b];
                if (cum + c >= need) { bsel = b; break; }
                cum += c;
            }
            bcast[0] = bsel;
            bcast[1] = need - cum;
        }
        __syncthreads();
        int bsel = bcast[0];
        need = bcast[1];
        prefix |= ((unsigned)bsel) << shift;
        __syncthreads();
    }
    unsigned thr = prefix;   // exact key of the 256th-largest; need = #equals to take

    int t0 = tid*2, t1 = tid*2 + 1;
    unsigned k0 = keys[t0], k1 = keys[t1];
    int eq0 = (k0 == thr), eq1 = (k1 == thr);
    int gt0 = (k0 > thr),  gt1 = (k1 > thr);

    // scan 1: index-ordered rank among equals
    int mysum = eq0 + eq1;
    int incl = mysum;
    #pragma unroll
    for (int o = 1; o < 32; o <<= 1) {
        int v = __shfl_up_sync(0xffffffffu, incl, o);
        if (lane >= o) incl += v;
    }
    if (lane == 31) warpsum[wid] = incl;
    __syncthreads();
    if (wid == 0) {
        int v = warpsum[lane];
        int iv = v;
        #pragma unroll
        for (int o = 1; o < 32; o <<= 1) {
            int x = __shfl_up_sync(0xffffffffu, iv, o);
            if (lane >= o) iv += x;
        }
        warpsum[lane] = iv - v;
    }
    __syncthreads();
    int exb = warpsum[wid] + (incl - mysum);
    int sel0 = gt0 || (eq0 && exb < need);
    int sel1 = gt1 || (eq1 && (exb + eq0) < need);
    __syncthreads();

    // scan 2: output positions (index order => ascending sorted indices)
    int mysum2 = sel0 + sel1;
    int incl2 = mysum2;
    #pragma unroll
    for (int o = 1; o < 32; o <<= 1) {
        int v = __shfl_up_sync(0xffffffffu, incl2, o);
        if (lane >= o) incl2 += v;
    }
    if (lane == 31) warpsum[wid] = incl2;
    __syncthreads();
    if (wid == 0) {
        int v = warpsum[lane];
        int iv = v;
        #pragma unroll
        for (int o = 1; o < 32; o <<= 1) {
            int x = __shfl_up_sync(0xffffffffu, iv, o);
            if (lane >= o) iv += x;
        }
        warpsum[lane] = iv - v;
    }
    __syncthreads();
    int pos = warpsum[wid] + (incl2 - mysum2);
    if (sel0) {
        d_idx[bn*KSEL + pos] = t0;
        d_gates[bn*KSEL + pos] = 1.f/(1.f + expf(-sc[t0]));
    }
    pos += sel0;
    if (sel1) {
        d_idx[bn*KSEL + pos] = t1;
        d_gates[bn*KSEL + pos] = 1.f/(1.f + expf(-sc[t1]));
    }
}

// ---------------- MoSA qkv: tf32 wmma, split-K x2, atomicAdd epilogue --------
#define MQ_AS 20
#define MQ_BS 68
__global__ __launch_bounds__(256) void mosa_qkv_wmma_kernel(
        const float* __restrict__ X, const float* __restrict__ W) {
    __shared__ __align__(16) float As[2][64*MQ_AS];
    __shared__ __align__(16) float Bs[2][16*MQ_BS];
    __shared__ __align__(16) float stg[8][256];
    int z = blockIdx.z, bn = z >> 1, half = z & 1;
    int b = bn >> 3, n = bn & 7;
    int mt = blockIdx.y, nt = blockIdx.x;
    int tid = threadIdx.x, lane = tid & 31;
    int warp = tid >> 5, wm = warp >> 2, wn = warp & 3;
    int arow = tid >> 2, a4 = (tid & 3)*4;
    int brow = tid >> 4, bcol = (tid & 15)*4;
    int tok = d_idx[bn*KSEL + mt*64 + arow];
    const float* Ap = X + ((size_t)b*TT + tok)*HH + half*512 + a4;
    const float* Bp = W + (size_t)n*QKV3 + nt*64 + bcol;
    int krow0 = half*512;

    float4 a_st, b_st;
    auto load_tile = [&](int k0) {
        a_st = *(const float4*)(Ap + k0);
        b_st = *(const float4*)(Bp + (size_t)(krow0 + k0 + brow)*(NHM*QKV3));
    };
    auto store_tile = [&](int bi) {
        float* A_ = As[bi]; float* B_ = Bs[bi];
        A_[arow*MQ_AS + a4+0] = f2tf32(a_st.x);
        A_[arow*MQ_AS + a4+1] = f2tf32(a_st.y);
        A_[arow*MQ_AS + a4+2] = f2tf32(a_st.z);
        A_[arow*MQ_AS + a4+3] = f2tf32(a_st.w);
        B_[brow*MQ_BS + bcol+0] = f2tf32(b_st.x);
        B_[brow*MQ_BS + bcol+1] = f2tf32(b_st.y);
        B_[brow*MQ_BS + bcol+2] = f2tf32(b_st.z);
        B_[brow*MQ_BS + bcol+3] = f2tf32(b_st.w);
    };

    wmma::fragment<wmma::accumulator, 16, 16, 8, float> acc[2];
    wmma::fill_fragment(acc[0], 0.f);
    wmma::fill_fragment(acc[1], 0.f);

    load_tile(0); store_tile(0); __syncthreads();

    const int KT = 512/16;
    #pragma unroll 1
    for (int kt = 0; kt < KT; kt++) {
        bool more = (kt + 1 < KT);
        if (more) load_tile((kt+1)*16);
        int bi = kt & 1;
        #pragma unroll
        for (int ks = 0; ks < 2; ks++) {
            wmma::fragment<wmma::matrix_b, 16, 16, 8,
                           wmma::precision::tf32, wmma::row_major> bf;
            wmma::load_matrix_sync(bf, &Bs[bi][(ks*8)*MQ_BS + wn*16], MQ_BS);
            #pragma unroll
            for (int mi = 0; mi < 2; mi++) {
                wmma::fragment<wmma::matrix_a, 16, 16, 8,
                               wmma::precision::tf32, wmma::row_major> af;
                wmma::load_matrix_sync(af, &As[bi][(wm*32 + mi*16)*MQ_AS + ks*8], MQ_AS);
                wmma::mma_sync(acc[mi], af, bf, acc[mi]);
            }
        }
        if (more) { store_tile(bi ^ 1); __syncthreads(); }
    }
    // epilogue: stage fragment -> smem -> atomicAdd (deterministic: 0 + a + b)
    float* wst = stg[warp];
    #pragma unroll
    for (int mi = 0; mi < 2; mi++) {
        wmma::store_matrix_sync(wst, acc[mi], 16, wmma::mem_row_major);
        __syncwarp();
        float* dst = &d_mqkv[((size_t)bn*KSEL + mt*64 + wm*32 + mi*16)*QKV3
                             + nt*64 + wn*16];
        #pragma unroll
        for (int e = 0; e < 8; e++) {
            int idx = lane*8 + e;
            int r = idx >> 4, c = idx & 15;
            atomicAdd(&dst[(size_t)r*QKV3 + c], wst[idx]);
        }
        __syncwarp();
    }
}

// ================= tf32 WMMA GEMM (double-buffered) ==========================
#define AS_STRIDE 20
#define BS_STRIDE 136

__global__ __launch_bounds__(256) void dense_qkv_wmma_kernel(
        const float* __restrict__ A, const float* __restrict__ B)
{
    __shared__ __align__(16) float As[2][128*AS_STRIDE];
    __shared__ __align__(16) float Bs[2][16*BS_STRIDE];
    const int K = HH, lda = HH, ldb = NHD*QKV3, ldc = NHD*QKV3;
    int tid = threadIdx.x;
    int warp = tid >> 5;
    int wm = warp >> 1, wn = warp & 1;
    int row0 = blockIdx.y*128, col0 = blockIdx.x*128;
    int arow = tid >> 2, acol = (tid & 3)*4;
    int brow = tid >> 5, bcol = (tid & 31)*4;

    const float* Ag = A + (size_t)(row0 + arow)*lda + acol;
    const float* Bg = B + col0 + bcol;

    float4 a0, a1, b0, b1;
    auto load_tile = [&](int k0) {
        a0 = *(const float4*)(Ag + k0);
        a1 = *(const float4*)(Ag + (size_t)64*lda + k0);
        b0 = *(const float4*)(Bg + (size_t)(k0 + brow)*ldb);
        b1 = *(const float4*)(Bg + (size_t)(k0 + brow + 8)*ldb);
    };
    auto store_tile = [&](int bi) {
        float* A_ = As[bi]; float* B_ = Bs[bi];
        A_[arow*AS_STRIDE + acol+0] = f2tf32(a0.x);
        A_[arow*AS_STRIDE + acol+1] = f2tf32(a0.y);
        A_[arow*AS_STRIDE + acol+2] = f2tf32(a0.z);
        A_[arow*AS_STRIDE + acol+3] = f2tf32(a0.w);
        A_[(arow+64)*AS_STRIDE + acol+0] = f2tf32(a1.x);
        A_[(arow+64)*AS_STRIDE + acol+1] = f2tf32(a1.y);
        A_[(arow+64)*AS_STRIDE + acol+2] = f2tf32(a1.z);
        A_[(arow+64)*AS_STRIDE + acol+3] = f2tf32(a1.w);
        B_[brow*BS_STRIDE + bcol+0] = f2tf32(b0.x);
        B_[brow*BS_STRIDE + bcol+1] = f2tf32(b0.y);
        B_[brow*BS_STRIDE + bcol+2] = f2tf32(b0.z);
        B_[brow*BS_STRIDE + bcol+3] = f2tf32(b0.w);
        B_[(brow+8)*BS_STRIDE + bcol+0] = f2tf32(b1.x);
        B_[(brow+8)*BS_STRIDE + bcol+1] = f2tf32(b1.y);
        B_[(brow+8)*BS_STRIDE + bcol+2] = f2tf32(b1.z);
        B_[(brow+8)*BS_STRIDE + bcol+3] = f2tf32(b1.w);
    };

    wmma::fragment<wmma::accumulator, 16, 16, 8, float> acc[2][4];
    #pragma unroll
    for (int mi = 0; mi < 2; mi++)
        #pragma unroll
        for (int ni = 0; ni < 4; ni++)
            wmma::fill_fragment(acc[mi][ni], 0.0f);

    load_tile(0); store_tile(0); __syncthreads();

    #pragma unroll 1
    for (int kt = 0; kt < K/16; kt++) {
        bool more = (kt + 1 < K/16);
        if (more) load_tile((kt+1)*16);
        int bi = kt & 1;
        #pragma unroll
        for (int ks = 0; ks < 2; ks++) {
            wmma::fragment<wmma::matrix_a, 16, 16, 8,
                           wmma::precision::tf32, wmma::row_major> af[2];
            wmma::fragment<wmma::matrix_b, 16, 16, 8,
                           wmma::precision::tf32, wmma::row_major> bf[4];
            #pragma unroll
            for (int mi = 0; mi < 2; mi++)
                wmma::load_matrix_sync(af[mi],
                    &As[bi][(wm*32 + mi*16)*AS_STRIDE + ks*8], AS_STRIDE);
            #pragma unroll
            for (int ni = 0; ni < 4; ni++)
                wmma::load_matrix_sync(bf[ni],
                    &Bs[bi][(ks*8)*BS_STRIDE + wn*64 + ni*16], BS_STRIDE);
            #pragma unroll
            for (int mi = 0; mi < 2; mi++)
                #pragma unroll
                for (int ni = 0; ni < 4; ni++)
                    wmma::mma_sync(acc[mi][ni], af[mi], bf[ni], acc[mi][ni]);
        }
        if (more) { store_tile(bi ^ 1); __syncthreads(); }
    }
    #pragma unroll
    for (int mi = 0; mi < 2; mi++)
        #pragma unroll
        for (int ni = 0; ni < 4; ni++)
            wmma::store_matrix_sync(
                &d_dqkv[(size_t)(row0 + wm*32 + mi*16)*ldc + col0 + wn*64 + ni*16],
                acc[mi][ni], ldc, wmma::mem_row_major);
}

__global__ __launch_bounds__(256) void final_wmma_kernel(
        const float* __restrict__ mwo, const float* __restrict__ dwo,
        float* __restrict__ out)
{
    __shared__ __align__(16) float As[2][128*AS_STRIDE];
    __shared__ __align__(16) float Bs[2][16*BS_STRIDE];
    const int K = 1024, lda = 1024, ldb = 1024, ldc = 1024;
    int tid = threadIdx.x;
    int warp = tid >> 5;
    int wm = warp >> 1, wn = warp & 1;
    int row0 = blockIdx.y*128, col0 = blockIdx.x*128;
    int arow = tid >> 2, acol = (tid & 3)*4;
    int brow = tid >> 5, bcol = (tid & 31)*4;

    const float* Ag = d_Y + (size_t)(row0 + arow)*lda + acol;

    float4 a0, a1, b0, b1;
    auto load_tile = [&](int k0) {
        a0 = *(const float4*)(Ag + k0);
        a1 = *(const float4*)(Ag + (size_t)64*lda + k0);
        int r0 = k0 + brow, r1 = k0 + brow + 8;
        const float* p0 = (r0 < 512) ? (mwo + (size_t)r0*ldb)
                                     : (dwo + (size_t)(r0 - 512)*ldb);
        const float* p1 = (r1 < 512) ? (mwo + (size_t)r1*ldb)
                                     : (dwo + (size_t)(r1 - 512)*ldb);
        b0 = *(const float4*)(p0 + col0 + bcol);
        b1 = *(const float4*)(p1 + col0 + bcol);
    };
    auto store_tile = [&](int bi) {
        float* A_ = As[bi]; float* B_ = Bs[bi];
        A_[arow*AS_STRIDE + acol+0] = f2tf32(a0.x);
        A_[arow*AS_STRIDE + acol+1] = f2tf32(a0.y);
        A_[arow*AS_STRIDE + acol+2] = f2tf32(a0.z);
        A_[arow*AS_STRIDE + acol+3] = f2tf32(a0.w);
        A_[(arow+64)*AS_STRIDE + acol+0] = f2tf32(a1.x);
        A_[(arow+64)*AS_STRIDE + acol+1] = f2tf32(a1.y);
        A_[(arow+64)*AS_STRIDE + acol+2] = f2tf32(a1.z);
        A_[(arow+64)*AS_STRIDE + acol+3] = f2tf32(a1.w);
        B_[brow*BS_STRIDE + bcol+0] = f2tf32(b0.x);
        B_[brow*BS_STRIDE + bcol+1] = f2tf32(b0.y);
        B_[brow*BS_STRIDE + bcol+2] = f2tf32(b0.z);
        B_[brow*BS_STRIDE + bcol+3] = f2tf32(b0.w);
        B_[(brow+8)*BS_STRIDE + bcol+0] = f2tf32(b1.x);
        B_[(brow+8)*BS_STRIDE + bcol+1] = f2tf32(b1.y);
        B_[(brow+8)*BS_STRIDE + bcol+2] = f2tf32(b1.z);
        B_[(brow+8)*BS_STRIDE + bcol+3] = f2tf32(b1.w);
    };

    wmma::fragment<wmma::accumulator, 16, 16, 8, float> acc[2][4];
    #pragma unroll
    for (int mi = 0; mi < 2; mi++)
        #pragma unroll
        for (int ni = 0; ni < 4; ni++)
            wmma::fill_fragment(acc[mi][ni], 0.0f);

    load_tile(0); store_tile(0); __syncthreads();

    #pragma unroll 1
    for (int kt = 0; kt < K/16; kt++) {
        bool more = (kt + 1 < K/16);
        if (more) load_tile((kt+1)*16);
        int bi = kt & 1;
        #pragma unroll
        for (int ks = 0; ks < 2; ks++) {
            wmma::fragment<wmma::matrix_a, 16, 16, 8,
                           wmma::precision::tf32, wmma::row_major> af[2];
            wmma::fragment<wmma::matrix_b, 16, 16, 8,
                           wmma::precision::tf32, wmma::row_major> bf[4];
            #pragma unroll
            for (int mi = 0; mi < 2; mi++)
                wmma::load_matrix_sync(af[mi],
                    &As[bi][(wm*32 + mi*16)*AS_STRIDE + ks*8], AS_STRIDE);
            #pragma unroll
            for (int ni = 0; ni < 4; ni++)
                wmma::load_matrix_sync(bf[ni],
                    &Bs[bi][(ks*8)*BS_STRIDE + wn*64 + ni*16], BS_STRIDE);
            #pragma unroll
            for (int mi = 0; mi < 2; mi++)
                #pragma unroll
                for (int ni = 0; ni < 4; ni++)
                    wmma::mma_sync(acc[mi][ni], af[mi], bf[ni], acc[mi][ni]);
        }
        if (more) { store_tile(bi ^ 1); __syncthreads(); }
    }
    #pragma unroll
    for (int mi = 0; mi < 2; mi++)
        #pragma unroll
        for (int ni = 0; ni < 4; ni++)
            wmma::store_matrix_sync(
                &out[(size_t)(row0 + wm*32 + mi*16)*ldc + col0 + wn*64 + ni*16],
                acc[mi][ni], ldc, wmma::mem_row_major);
}

// ---------------- RoPE ----------------
__device__ __forceinline__ float inv_freq(int j) {
    return (float)exp(-(double)j * (9.210340371976184 / 16.0));
}

__global__ void mosa_rope_kernel() {
    int g = blockIdx.x*blockDim.x + threadIdx.x;
    int j  = g & 15;
    int kk = (g >> 4) & 255;
    int bn = g >> 12;
    float pos = (float)d_idx[bn*KSEL + kk];
    float ang = pos * inv_freq(j);
    float s, c; sincosf(ang, &s, &c);
    float* p = d_mqkv + ((size_t)bn*KSEL + kk)*QKV3;
    float x1 = p[j], x2 = p[16+j];
    p[j] = x1*c - x2*s;  p[16+j] = x1*s + x2*c;
    x1 = p[64+j]; x2 = p[80+j];
    p[64+j] = x1*c - x2*s; p[80+j] = x1*s + x2*c;
}

__global__ void dense_rope_kernel() {
    int g = blockIdx.x*blockDim.x + threadIdx.x;
    int j = g & 15;
    int n = (g >> 4) & 7;
    int t = (g >> 7) & 2047;
    int b = g >> 18;
    float ang = (float)t * inv_freq(j);
    float s, c; sincosf(ang, &s, &c);
    float* p = d_dqkv + ((size_t)(b*TT + t))*(NHD*QKV3) + n*QKV3;
    float x1 = p[j], x2 = p[16+j];
    p[j] = x1*c - x2*s;  p[16+j] = x1*s + x2*c;
    x1 = p[64+j]; x2 = p[80+j];
    p[64+j] = x1*c - x2*s; p[80+j] = x1*s + x2*c;
}

// ========== FA2 flash: register O/softmax + K/V register prefetch ============
#define FQ_LD 68
#define FK_LD 68
#define FV_LD 76
#define FP_LD 68
#define FL_SMEM_BYTES ((128*FQ_LD + 64*FK_LD + 64*FV_LD + 128*FP_LD)*4)

template<bool MOSA>
__global__ __launch_bounds__(256, 2) void flash_fa2_kernel() {
    extern __shared__ float sm[];
    float* Qs = sm;                       // [128][FQ_LD]
    float* Ks = Qs + 128*FQ_LD;           // [64][FK_LD]
    float* Vs = Ks + 64*FK_LD;            // [64][FV_LD]
    float* Ps = Vs + 64*FV_LD;            // [128][FP_LD]

    int qt = MOSA ? blockIdx.x : (gridDim.x - 1 - blockIdx.x);
    int n = blockIdx.y, b = blockIdx.z;
    int bn = b*NHM + n;
    int tid = threadIdx.x;
    int w = tid >> 5, lane = tid & 31;
    int lq = lane >> 2, lr = lane & 3;
    const int RS = MOSA ? QKV3 : NHD*QKV3;
    const float* src = MOSA ? d_mqkv : d_dqkv;

    for (int s = tid; s < 2048; s += 256) {
        int r = s >> 4, c4 = (s & 15)*4;
        size_t base = MOSA ? ((size_t)(bn*KSEL + qt*128 + r))*QKV3
                           : ((size_t)(b*TT + qt*128 + r))*RS + n*QKV3;
        float4 v = *(const float4*)(src + base + c4);
        Qs[r*FQ_LD + c4+0] = f2tf32(v.x);
        Qs[r*FQ_LD + c4+1] = f2tf32(v.y);
        Qs[r*FQ_LD + c4+2] = f2tf32(v.z);
        Qs[r*FQ_LD + c4+3] = f2tf32(v.w);
    }

    int row0 = w*16;
    int gr0 = qt*128 + row0 + lq;
    int gr1 = gr0 + 8;

    float o[8][4];
    #pragma unroll
    for (int ni = 0; ni < 8; ni++)
        #pragma unroll
        for (int e = 0; e < 4; e++) o[ni][e] = 0.f;
    float m0 = NEGINF, m1 = NEGINF, l0 = 0.f, l1 = 0.f;

    float4 kpre[4], vpre[4];
    auto ld_kv = [&](int kt) {
        #pragma unroll
        for (int i = 0; i < 4; i++) {
            int s = tid + i*256;
            int r = s >> 4, c4 = (s & 15)*4;
            size_t base = MOSA ? ((size_t)(bn*KSEL + kt*64 + r))*QKV3
                               : ((size_t)(b*TT + kt*64 + r))*RS + n*QKV3;
            kpre[i] = *(const float4*)(src + base + 64 + c4);
            vpre[i] = *(const float4*)(src + base + 128 + c4);
        }
    };
    auto st_kv = [&]() {
        #pragma unroll
        for (int i = 0; i < 4; i++) {
            int s = tid + i*256;
            int r = s >> 4, c4 = (s & 15)*4;
            Ks[r*FK_LD + c4+0] = f2tf32(kpre[i].x);
            Ks[r*FK_LD + c4+1] = f2tf32(kpre[i].y);
            Ks[r*FK_LD + c4+2] = f2tf32(kpre[i].z);
            Ks[r*FK_LD + c4+3] = f2tf32(kpre[i].w);
            Vs[r*FV_LD + c4+0] = f2tf32(vpre[i].x);
            Vs[r*FV_LD + c4+1] = f2tf32(vpre[i].y);
            Vs[r*FV_LD + c4+2] = f2tf32(vpre[i].z);
            Vs[r*FV_LD + c4+3] = f2tf32(vpre[i].w);
        }
    };

    int nkt = 2*qt + 2;
    ld_kv(0);
    for (int kt = 0; kt < nkt; kt++) {
        st_kv();
        __syncthreads();   // (1) K/V (and Q on first iter) ready
        if (kt + 1 < nkt) ld_kv(kt+1);   // hide next tile's gmem latency

        float sacc[8][4];
        #pragma unroll
        for (int ni = 0; ni < 8; ni++)
            #pragma unroll
            for (int e = 0; e < 4; e++) sacc[ni][e] = 0.f;
        #pragma unroll
        for (int k = 0; k < 8; k++) {
            unsigned af[4];
            af[0] = __float_as_uint(Qs[(row0 + lq)*FQ_LD + k*8 + lr]);
            af[1] = __float_as_uint(Qs[(row0 + 8 + lq)*FQ_LD + k*8 + lr]);
            af[2] = __float_as_uint(Qs[(row0 + lq)*FQ_LD + k*8 + lr + 4]);
            af[3] = __float_as_uint(Qs[(row0 + 8 + lq)*FQ_LD + k*8 + lr + 4]);
            #pragma unroll
            for (int ni = 0; ni < 8; ni++) {
                unsigned b0 = __float_as_uint(Ks[(ni*8 + lq)*FK_LD + k*8 + lr]);
                unsigned b1 = __float_as_uint(Ks[(ni*8 + lq)*FK_LD + k*8 + lr + 4]);
                mma_tf32(sacc[ni], af, b0, b1);
            }
        }

        int cbase = kt*64 + 2*lr;
        float mx0 = NEGINF, mx1 = NEGINF;
        #pragma unroll
        for (int ni = 0; ni < 8; ni++) {
            int c0 = cbase + ni*8, c1 = c0 + 1;
            float s00 = (c0 <= gr0) ? sacc[ni][0]*0.125f : NEGINF;
            float s01 = (c1 <= gr0) ? sacc[ni][1]*0.125f : NEGINF;
            float s10 = (c0 <= gr1) ? sacc[ni][2]*0.125f : NEGINF;
            float s11 = (c1 <= gr1) ? sacc[ni][3]*0.125f : NEGINF;
            sacc[ni][0] = s00; sacc[ni][1] = s01;
            sacc[ni][2] = s10; sacc[ni][3] = s11;
            mx0 = fmaxf(mx0, fmaxf(s00, s01));
            mx1 = fmaxf(mx1, fmaxf(s10, s11));
        }
        mx0 = fmaxf(mx0, __shfl_xor_sync(0xffffffffu, mx0, 1));
        mx0 = fmaxf(mx0, __shfl_xor_sync(0xffffffffu, mx0, 2));
        mx1 = fmaxf(mx1, __shfl_xor_sync(0xffffffffu, mx1, 1));
        mx1 = fmaxf(mx1, __shfl_xor_sync(0xffffffffu, mx1, 2));
        float mn0 = fmaxf(m0, mx0), mn1 = fmaxf(m1, mx1);
        float al0 = __expf(m0 - mn0), al1 = __expf(m1 - mn1);
        float ps0 = 0.f, ps1 = 0.f;
        #pragma unroll
        for (int ni = 0; ni < 8; ni++) {
            float p00 = __expf(sacc[ni][0] - mn0);
            float p01 = __expf(sacc[ni][1] - mn0);
            float p10 = __expf(sacc[ni][2] - mn1);
            float p11 = __expf(sacc[ni][3] - mn1);
            ps0 += p00 + p01;
            ps1 += p10 + p11;
            int c = ni*8 + 2*lr;
            *(float2*)&Ps[(row0 + lq)*FP_LD + c] =
                make_float2(f2tf32(p00), f2tf32(p01));
            *(float2*)&Ps[(row0 + 8 + lq)*FP_LD + c] =
                make_float2(f2tf32(p10), f2tf32(p11));
        }
        ps0 += __shfl_xor_sync(0xffffffffu, ps0, 1);
        ps0 += __shfl_xor_sync(0xffffffffu, ps0, 2);
        ps1 += __shfl_xor_sync(0xffffffffu, ps1, 1);
        ps1 += __shfl_xor_sync(0xffffffffu, ps1, 2);
        l0 = l0*al0 + ps0;  m0 = mn0;
        l1 = l1*al1 + ps1;  m1 = mn1;
        #pragma unroll
        for (int ni = 0; ni < 8; ni++) {
            o[ni][0] *= al0; o[ni][1] *= al0;
            o[ni][2] *= al1; o[ni][3] *= al1;
        }
        __syncthreads();   // (2) P visible

        #pragma unroll
        for (int k = 0; k < 8; k++) {
            unsigned af[4];
            af[0] = __float_as_uint(Ps[(row0 + lq)*FP_LD + k*8 + lr]);
            af[1] = __float_as_uint(Ps[(row0 + 8 + lq)*FP_LD + k*8 + lr]);
            af[2] = __float_as_uint(Ps[(row0 + lq)*FP_LD + k*8 + lr + 4]);
            af[3] = __float_as_uint(Ps[(row0 + 8 + lq)*FP_LD + k*8 + lr + 4]);
            #pragma unroll
            for (int ni = 0; ni < 8; ni++) {
                unsigned b0 = __float_as_uint(Vs[(k*8 + lr)*FV_LD + ni*8 + lq]);
                unsigned b1 = __float_as_uint(Vs[(k*8 + lr + 4)*FV_LD + ni*8 + lq]);
                mma_tf32(o[ni], af, b0, b1);
            }
        }
        __syncthreads();   // (3) Ks/Vs/Ps consumed
    }

    if (MOSA) {
        int tok0 = d_idx[bn*KSEL + gr0];
        int tok1 = d_idx[bn*KSEL + gr1];
        float s0 = d_gates[bn*KSEL + gr0] / l0;
        float s1 = d_gates[bn*KSEL + gr1] / l1;
        #pragma unroll
        for (int ni = 0; ni < 8; ni++) {
            int c = n*64 + ni*8 + 2*lr;
            *(float2*)&d_Y[((size_t)(b*TT + tok0))*1024 + c] =
                make_float2(o[ni][0]*s0, o[ni][1]*s0);
            *(float2*)&d_Y[((size_t)(b*TT + tok1))*1024 + c] =
                make_float2(o[ni][2]*s1, o[ni][3]*s1);
        }
    } else {
        float s0 = 1.f/l0, s1 = 1.f/l1;
        #pragma unroll
        for (int ni = 0; ni < 8; ni++) {
            int c = 512 + n*64 + ni*8 + 2*lr;
            *(float2*)&d_Y[((size_t)(b*TT + gr0))*1024 + c] =
                make_float2(o[ni][0]*s0, o[ni][1]*s0);
            *(float2*)&d_Y[((size_t)(b*TT + gr1))*1024 + c] =
                make_float2(o[ni][2]*s1, o[ni][3]*s1);
        }
    }
}

// ---------------- launch: fork-join graph ----------------
extern "C" void kernel_launch(void* const* d_in, const int* in_sizes, int n_in,
                              void* d_out, int out_size) {
    const float* X     = (const float*)d_in[0];
    const float* rw    = (const float*)d_in[1];
    const float* mwqkv = (const float*)d_in[2];
    const float* mwo   = (const float*)d_in[3];
    const float* dwqkv = (const float*)d_in[4];
    const float* dwo   = (const float*)d_in[5];
    float* out = (float*)d_out;

    static cudaStream_t sB = nullptr;
    static cudaEvent_t eFork = nullptr, eJoin = nullptr;
    if (sB == nullptr) {
        cudaStreamCreateWithFlags(&sB, cudaStreamNonBlocking);
        cudaEventCreateWithFlags(&eFork, cudaEventDisableTiming);
        cudaEventCreateWithFlags(&eJoin, cudaEventDisableTiming);
        cudaFuncSetAttribute(flash_fa2_kernel<false>,
            cudaFuncAttributeMaxDynamicSharedMemorySize, FL_SMEM_BYTES);
        cudaFuncSetAttribute(flash_fa2_kernel<true>,
            cudaFuncAttributeMaxDynamicSharedMemorySize, FL_SMEM_BYTES);
    }

    cudaEventRecord(eFork, 0);
    cudaStreamWaitEvent(sB, eFork, 0);

    // ---- branch A (default stream): mosa chain ----
    zeroY_kernel<<<ZERO_BLOCKS, 256>>>();
    router_kernel<<<dim3(TT, BB), 256>>>(X, rw);
    topk_kernel<<<BB*NHM, 1024>>>();
    mosa_qkv_wmma_kernel<<<dim3(3, 4, 2*BB*NHM), 256>>>(X, mwqkv);
    mosa_rope_kernel<<<256, 256>>>();
    flash_fa2_kernel<true><<<dim3(2, NHM, BB), 256, FL_SMEM_BYTES>>>();

    // ---- branch B (side stream): dense chain ----
    dense_qkv_wmma_kernel<<<dim3(12, 32), 256, 0, sB>>>(X, dwqkv);
    dense_rope_kernel<<<2048, 256, 0, sB>>>();
    flash_fa2_kernel<false><<<dim3(16, NHD, BB), 256, FL_SMEM_BYTES, sB>>>();

    // join
    cudaEventRecord(eJoin, sB);
    cudaStreamWaitEvent(0, eJoin, 0);

    final_wmma_kernel<<<dim3(8, 32), 256>>>(mwo, dwo, out);
}

// round 16
// speedup vs baseline: 2.1655x; 1.1274x over previous
#include <cuda_runtime.h>
#include <mma.h>
#include <math.h>

using namespace nvcuda;

#define BB   2
#define TT   2048
#define HH   1024
#define HPP  64
#define NHM  8
#define NHD  8
#define KSEL 256
#define QKV3 192
#define NEGINF (-3.0e38f)

__device__ __align__(128) float d_scores[BB*NHM*TT];
__device__ __align__(128) int   d_idx   [BB*NHM*KSEL];
__device__ __align__(128) float d_gates [BB*NHM*KSEL];
__device__ __align__(128) float d_mqkv  [BB*NHM*KSEL*QKV3];
__device__ __align__(128) float d_dqkv  [(size_t)BB*TT*NHD*QKV3];
__device__ __align__(128) float d_Y     [(size_t)BB*TT*1024];

__device__ __forceinline__ float f2tf32(float f) {
    unsigned u; asm("cvt.rna.tf32.f32 %0, %1;" : "=r"(u) : "f"(f));
    return __uint_as_float(u);
}

__device__ __forceinline__ void mma_tf32(float* c, const unsigned* a,
                                         unsigned b0, unsigned b1) {
    asm volatile("mma.sync.aligned.m16n8k8.row.col.f32.tf32.tf32.f32 "
        "{%0,%1,%2,%3}, {%4,%5,%6,%7}, {%8,%9}, {%0,%1,%2,%3};"
        : "+f"(c[0]), "+f"(c[1]), "+f"(c[2]), "+f"(c[3])
        : "r"(a[0]), "r"(a[1]), "r"(a[2]), "r"(a[3]), "r"(b0), "r"(b1));
}

// ---------------- zero: mosa half of Y + d_mqkv ----------------
// total = BB*TT*128 + BB*NHM*KSEL*QKV3/4 = 524288 + 196608 = 720896 threads
#define ZERO_BLOCKS 2816
__global__ void zeroY_kernel() {
    int i = blockIdx.x*blockDim.x + threadIdx.x;
    const int NY = BB*TT*128;
    const int NM = BB*NHM*KSEL*QKV3/4;
    if (i < NY) {
        int r = i >> 7, c = i & 127;
        *(float4*)&d_Y[(size_t)r*1024 + c*4] = make_float4(0.f,0.f,0.f,0.f);
    } else if (i - NY < NM) {
        ((float4*)d_mqkv)[i - NY] = make_float4(0.f,0.f,0.f,0.f);
    }
}

// ---------------- router ----------------
__global__ void router_kernel(const float* __restrict__ X,
                              const float* __restrict__ rw) {
    __shared__ float Xs[HH];
    int t = blockIdx.x, b = blockIdx.y;
    const float* xr = X + ((size_t)b*TT + t)*HH;
    for (int i = threadIdx.x; i < HH; i += blockDim.x) Xs[i] = xr[i];
    __syncthreads();
    int w = threadIdx.x >> 5, lane = threadIdx.x & 31;
    float s = 0.f;
    for (int h = lane; h < HH; h += 32) s += Xs[h] * rw[h*NHM + w];
    #pragma unroll
    for (int o = 16; o; o >>= 1) s += __shfl_down_sync(0xffffffffu, s, o);
    if (lane == 0) d_scores[((size_t)b*NHM + w)*TT + t] = s;
}

// ---------------- top-k via radix select + ordered compaction ----------------
__global__ __launch_bounds__(1024) void topk_kernel() {
    __shared__ unsigned keys[TT];
    __shared__ int hist[256];
    __shared__ int warpsum[32];
    __shared__ int bcast[2];
    int bn = blockIdx.x, tid = threadIdx.x;
    int lane = tid & 31, wid = tid >> 5;
    const float* sc = d_scores + (size_t)bn*TT;

    for (int t = tid; t < TT; t += 1024) {
        unsigned u = __float_as_uint(sc[t]);
        u ^= (u & 0x80000000u) ? 0xFFFFFFFFu : 0x80000000u;
        keys[t] = u;
    }
    __syncthreads();

    unsigned prefix = 0;
    int need = KSEL;
    #pragma unroll 1
    for (int level = 0; level < 4; level++) {
        int shift = 24 - level*8;
        if (tid < 256) hist[tid] = 0;
        __syncthreads();
        for (int t = tid; t < TT; t += 1024) {
            unsigned k = keys[t];
            bool match = (level == 0) || ((k >> (shift + 8)) == (prefix >> (shift + 8)));
            if (match) atomicAdd(&hist[(k >> shift) & 255], 1);
        }
        __syncthreads();
        if (tid == 0) {
            int cum = 0, bsel = 0;
            for (int b = 255; b >= 0; b--) {
                int c = hist[b];
                if (cum + c >= need) { bsel = b; break; }
                cum += c;
            }
            bcast[0] = bsel;
            bcast[1] = need - cum;
        }
        __syncthreads();
        int bsel = bcast[0];
        need = bcast[1];
        prefix |= ((unsigned)bsel) << shift;
        __syncthreads();
    }
    unsigned thr = prefix;

    int t0 = tid*2, t1 = tid*2 + 1;
    unsigned k0 = keys[t0], k1 = keys[t1];
    int eq0 = (k0 == thr), eq1 = (k1 == thr);
    int gt0 = (k0 > thr),  gt1 = (k1 > thr);

    int mysum = eq0 + eq1;
    int incl = mysum;
    #pragma unroll
    for (int o = 1; o < 32; o <<= 1) {
        int v = __shfl_up_sync(0xffffffffu, incl, o);
        if (lane >= o) incl += v;
    }
    if (lane == 31) warpsum[wid] = incl;
    __syncthreads();
    if (wid == 0) {
        int v = warpsum[lane];
        int iv = v;
        #pragma unroll
        for (int o = 1; o < 32; o <<= 1) {
            int x = __shfl_up_sync(0xffffffffu, iv, o);
            if (lane >= o) iv += x;
        }
        warpsum[lane] = iv - v;
    }
    __syncthreads();
    int exb = warpsum[wid] + (incl - mysum);
    int sel0 = gt0 || (eq0 && exb < need);
    int sel1 = gt1 || (eq1 && (exb + eq0) < need);
    __syncthreads();

    int mysum2 = sel0 + sel1;
    int incl2 = mysum2;
    #pragma unroll
    for (int o = 1; o < 32; o <<= 1) {
        int v = __shfl_up_sync(0xffffffffu, incl2, o);
        if (lane >= o) incl2 += v;
    }
    if (lane == 31) warpsum[wid] = incl2;
    __syncthreads();
    if (wid == 0) {
        int v = warpsum[lane];
        int iv = v;
        #pragma unroll
        for (int o = 1; o < 32; o <<= 1) {
            int x = __shfl_up_sync(0xffffffffu, iv, o);
            if (lane >= o) iv += x;
        }
        warpsum[lane] = iv - v;
    }
    __syncthreads();
    int pos = warpsum[wid] + (incl2 - mysum2);
    if (sel0) {
        d_idx[bn*KSEL + pos] = t0;
        d_gates[bn*KSEL + pos] = 1.f/(1.f + expf(-sc[t0]));
    }
    pos += sel0;
    if (sel1) {
        d_idx[bn*KSEL + pos] = t1;
        d_gates[bn*KSEL + pos] = 1.f/(1.f + expf(-sc[t1]));
    }
}

// ---------------- MoSA qkv: tf32 wmma, split-K x2, atomicAdd epilogue --------
#define MQ_AS 20
#define MQ_BS 68
__global__ __launch_bounds__(256) void mosa_qkv_wmma_kernel(
        const float* __restrict__ X, const float* __restrict__ W) {
    __shared__ __align__(16) float As[2][64*MQ_AS];
    __shared__ __align__(16) float Bs[2][16*MQ_BS];
    __shared__ __align__(16) float stg[8][256];
    int z = blockIdx.z, bn = z >> 1, half = z & 1;
    int b = bn >> 3, n = bn & 7;
    int mt = blockIdx.y, nt = blockIdx.x;
    int tid = threadIdx.x, lane = tid & 31;
    int warp = tid >> 5, wm = warp >> 2, wn = warp & 3;
    int arow = tid >> 2, a4 = (tid & 3)*4;
    int brow = tid >> 4, bcol = (tid & 15)*4;
    int tok = d_idx[bn*KSEL + mt*64 + arow];
    const float* Ap = X + ((size_t)b*TT + tok)*HH + half*512 + a4;
    const float* Bp = W + (size_t)n*QKV3 + nt*64 + bcol;
    int krow0 = half*512;

    float4 a_st, b_st;
    auto load_tile = [&](int k0) {
        a_st = *(const float4*)(Ap + k0);
        b_st = *(const float4*)(Bp + (size_t)(krow0 + k0 + brow)*(NHM*QKV3));
    };
    auto store_tile = [&](int bi) {
        float* A_ = As[bi]; float* B_ = Bs[bi];
        A_[arow*MQ_AS + a4+0] = f2tf32(a_st.x);
        A_[arow*MQ_AS + a4+1] = f2tf32(a_st.y);
        A_[arow*MQ_AS + a4+2] = f2tf32(a_st.z);
        A_[arow*MQ_AS + a4+3] = f2tf32(a_st.w);
        B_[brow*MQ_BS + bcol+0] = f2tf32(b_st.x);
        B_[brow*MQ_BS + bcol+1] = f2tf32(b_st.y);
        B_[brow*MQ_BS + bcol+2] = f2tf32(b_st.z);
        B_[brow*MQ_BS + bcol+3] = f2tf32(b_st.w);
    };

    wmma::fragment<wmma::accumulator, 16, 16, 8, float> acc[2];
    wmma::fill_fragment(acc[0], 0.f);
    wmma::fill_fragment(acc[1], 0.f);

    load_tile(0); store_tile(0); __syncthreads();

    const int KT = 512/16;
    #pragma unroll 1
    for (int kt = 0; kt < KT; kt++) {
        bool more = (kt + 1 < KT);
        if (more) load_tile((kt+1)*16);
        int bi = kt & 1;
        #pragma unroll
        for (int ks = 0; ks < 2; ks++) {
            wmma::fragment<wmma::matrix_b, 16, 16, 8,
                           wmma::precision::tf32, wmma::row_major> bf;
            wmma::load_matrix_sync(bf, &Bs[bi][(ks*8)*MQ_BS + wn*16], MQ_BS);
            #pragma unroll
            for (int mi = 0; mi < 2; mi++) {
                wmma::fragment<wmma::matrix_a, 16, 16, 8,
                               wmma::precision::tf32, wmma::row_major> af;
                wmma::load_matrix_sync(af, &As[bi][(wm*32 + mi*16)*MQ_AS + ks*8], MQ_AS);
                wmma::mma_sync(acc[mi], af, bf, acc[mi]);
            }
        }
        if (more) { store_tile(bi ^ 1); __syncthreads(); }
    }
    float* wst = stg[warp];
    #pragma unroll
    for (int mi = 0; mi < 2; mi++) {
        wmma::store_matrix_sync(wst, acc[mi], 16, wmma::mem_row_major);
        __syncwarp();
        float* dst = &d_mqkv[((size_t)bn*KSEL + mt*64 + wm*32 + mi*16)*QKV3
                             + nt*64 + wn*16];
        #pragma unroll
        for (int e = 0; e < 8; e++) {
            int idx = lane*8 + e;
            int r = idx >> 4, c = idx & 15;
            atomicAdd(&dst[(size_t)r*QKV3 + c], wst[idx]);
        }
        __syncwarp();
    }
}

// ================= tf32 WMMA GEMM (double-buffered) ==========================
#define AS_STRIDE 20
#define BS_STRIDE 136

__global__ __launch_bounds__(256) void dense_qkv_wmma_kernel(
        const float* __restrict__ A, const float* __restrict__ B)
{
    __shared__ __align__(16) float As[2][128*AS_STRIDE];
    __shared__ __align__(16) float Bs[2][16*BS_STRIDE];
    const int K = HH, lda = HH, ldb = NHD*QKV3, ldc = NHD*QKV3;
    int tid = threadIdx.x;
    int warp = tid >> 5;
    int wm = warp >> 1, wn = warp & 1;
    int row0 = blockIdx.y*128, col0 = blockIdx.x*128;
    int arow = tid >> 2, acol = (tid & 3)*4;
    int brow = tid >> 5, bcol = (tid & 31)*4;

    const float* Ag = A + (size_t)(row0 + arow)*lda + acol;
    const float* Bg = B + col0 + bcol;

    float4 a0, a1, b0, b1;
    auto load_tile = [&](int k0) {
        a0 = *(const float4*)(Ag + k0);
        a1 = *(const float4*)(Ag + (size_t)64*lda + k0);
        b0 = *(const float4*)(Bg + (size_t)(k0 + brow)*ldb);
        b1 = *(const float4*)(Bg + (size_t)(k0 + brow + 8)*ldb);
    };
    auto store_tile = [&](int bi) {
        float* A_ = As[bi]; float* B_ = Bs[bi];
        A_[arow*AS_STRIDE + acol+0] = f2tf32(a0.x);
        A_[arow*AS_STRIDE + acol+1] = f2tf32(a0.y);
        A_[arow*AS_STRIDE + acol+2] = f2tf32(a0.z);
        A_[arow*AS_STRIDE + acol+3] = f2tf32(a0.w);
        A_[(arow+64)*AS_STRIDE + acol+0] = f2tf32(a1.x);
        A_[(arow+64)*AS_STRIDE + acol+1] = f2tf32(a1.y);
        A_[(arow+64)*AS_STRIDE + acol+2] = f2tf32(a1.z);
        A_[(arow+64)*AS_STRIDE + acol+3] = f2tf32(a1.w);
        B_[brow*BS_STRIDE + bcol+0] = f2tf32(b0.x);
        B_[brow*BS_STRIDE + bcol+1] = f2tf32(b0.y);
        B_[brow*BS_STRIDE + bcol+2] = f2tf32(b0.z);
        B_[brow*BS_STRIDE + bcol+3] = f2tf32(b0.w);
        B_[(brow+8)*BS_STRIDE + bcol+0] = f2tf32(b1.x);
        B_[(brow+8)*BS_STRIDE + bcol+1] = f2tf32(b1.y);
        B_[(brow+8)*BS_STRIDE + bcol+2] = f2tf32(b1.z);
        B_[(brow+8)*BS_STRIDE + bcol+3] = f2tf32(b1.w);
    };

    wmma::fragment<wmma::accumulator, 16, 16, 8, float> acc[2][4];
    #pragma unroll
    for (int mi = 0; mi < 2; mi++)
        #pragma unroll
        for (int ni = 0; ni < 4; ni++)
            wmma::fill_fragment(acc[mi][ni], 0.0f);

    load_tile(0); store_tile(0); __syncthreads();

    #pragma unroll 1
    for (int kt = 0; kt < K/16; kt++) {
        bool more = (kt + 1 < K/16);
        if (more) load_tile((kt+1)*16);
        int bi = kt & 1;
        #pragma unroll
        for (int ks = 0; ks < 2; ks++) {
            wmma::fragment<wmma::matrix_a, 16, 16, 8,
                           wmma::precision::tf32, wmma::row_major> af[2];
            wmma::fragment<wmma::matrix_b, 16, 16, 8,
                           wmma::precision::tf32, wmma::row_major> bf[4];
            #pragma unroll
            for (int mi = 0; mi < 2; mi++)
                wmma::load_matrix_sync(af[mi],
                    &As[bi][(wm*32 + mi*16)*AS_STRIDE + ks*8], AS_STRIDE);
            #pragma unroll
            for (int ni = 0; ni < 4; ni++)
                wmma::load_matrix_sync(bf[ni],
                    &Bs[bi][(ks*8)*BS_STRIDE + wn*64 + ni*16], BS_STRIDE);
            #pragma unroll
            for (int mi = 0; mi < 2; mi++)
                #pragma unroll
                for (int ni = 0; ni < 4; ni++)
                    wmma::mma_sync(acc[mi][ni], af[mi], bf[ni], acc[mi][ni]);
        }
        if (more) { store_tile(bi ^ 1); __syncthreads(); }
    }
    #pragma unroll
    for (int mi = 0; mi < 2; mi++)
        #pragma unroll
        for (int ni = 0; ni < 4; ni++)
            wmma::store_matrix_sync(
                &d_dqkv[(size_t)(row0 + wm*32 + mi*16)*ldc + col0 + wn*64 + ni*16],
                acc[mi][ni], ldc, wmma::mem_row_major);
}

// final GEMM halves: out (+)= Y[:, ycol0:ycol0+512] @ W[512,1024]
template<bool ADD>
__global__ __launch_bounds__(256) void final_half_kernel(
        const float* __restrict__ W, float* __restrict__ out, int ycol0)
{
    __shared__ __align__(16) float As[2][128*AS_STRIDE];
    __shared__ __align__(16) float Bs[2][16*BS_STRIDE];
    const int K = 512, lda = 1024, ldb = 1024, ldc = 1024;
    int tid = threadIdx.x;
    int warp = tid >> 5;
    int wm = warp >> 1, wn = warp & 1;
    int row0 = blockIdx.y*128, col0 = blockIdx.x*128;
    int arow = tid >> 2, acol = (tid & 3)*4;
    int brow = tid >> 5, bcol = (tid & 31)*4;

    const float* Ag = d_Y + (size_t)(row0 + arow)*lda + ycol0 + acol;
    const float* Bg = W + col0 + bcol;

    float4 a0, a1, b0, b1;
    auto load_tile = [&](int k0) {
        a0 = *(const float4*)(Ag + k0);
        a1 = *(const float4*)(Ag + (size_t)64*lda + k0);
        b0 = *(const float4*)(Bg + (size_t)(k0 + brow)*ldb);
        b1 = *(const float4*)(Bg + (size_t)(k0 + brow + 8)*ldb);
    };
    auto store_tile = [&](int bi) {
        float* A_ = As[bi]; float* B_ = Bs[bi];
        A_[arow*AS_STRIDE + acol+0] = f2tf32(a0.x);
        A_[arow*AS_STRIDE + acol+1] = f2tf32(a0.y);
        A_[arow*AS_STRIDE + acol+2] = f2tf32(a0.z);
        A_[arow*AS_STRIDE + acol+3] = f2tf32(a0.w);
        A_[(arow+64)*AS_STRIDE + acol+0] = f2tf32(a1.x);
        A_[(arow+64)*AS_STRIDE + acol+1] = f2tf32(a1.y);
        A_[(arow+64)*AS_STRIDE + acol+2] = f2tf32(a1.z);
        A_[(arow+64)*AS_STRIDE + acol+3] = f2tf32(a1.w);
        B_[brow*BS_STRIDE + bcol+0] = f2tf32(b0.x);
        B_[brow*BS_STRIDE + bcol+1] = f2tf32(b0.y);
        B_[brow*BS_STRIDE + bcol+2] = f2tf32(b0.z);
        B_[brow*BS_STRIDE + bcol+3] = f2tf32(b0.w);
        B_[(brow+8)*BS_STRIDE + bcol+0] = f2tf32(b1.x);
        B_[(brow+8)*BS_STRIDE + bcol+1] = f2tf32(b1.y);
        B_[(brow+8)*BS_STRIDE + bcol+2] = f2tf32(b1.z);
        B_[(brow+8)*BS_STRIDE + bcol+3] = f2tf32(b1.w);
    };

    wmma::fragment<wmma::accumulator, 16, 16, 8, float> acc[2][4];
    #pragma unroll
    for (int mi = 0; mi < 2; mi++)
        #pragma unroll
        for (int ni = 0; ni < 4; ni++)
            wmma::fill_fragment(acc[mi][ni], 0.0f);

    load_tile(0); store_tile(0); __syncthreads();

    #pragma unroll 1
    for (int kt = 0; kt < K/16; kt++) {
        bool more = (kt + 1 < K/16);
        if (more) load_tile((kt+1)*16);
        int bi = kt & 1;
        #pragma unroll
        for (int ks = 0; ks < 2; ks++) {
            wmma::fragment<wmma::matrix_a, 16, 16, 8,
                           wmma::precision::tf32, wmma::row_major> af[2];
            wmma::fragment<wmma::matrix_b, 16, 16, 8,
                           wmma::precision::tf32, wmma::row_major> bf[4];
            #pragma unroll
            for (int mi = 0; mi < 2; mi++)
                wmma::load_matrix_sync(af[mi],
                    &As[bi][(wm*32 + mi*16)*AS_STRIDE + ks*8], AS_STRIDE);
            #pragma unroll
            for (int ni = 0; ni < 4; ni++)
                wmma::load_matrix_sync(bf[ni],
                    &Bs[bi][(ks*8)*BS_STRIDE + wn*64 + ni*16], BS_STRIDE);
            #pragma unroll
            for (int mi = 0; mi < 2; mi++)
                #pragma unroll
                for (int ni = 0; ni < 4; ni++)
                    wmma::mma_sync(acc[mi][ni], af[mi], bf[ni], acc[mi][ni]);
        }
        if (more) { store_tile(bi ^ 1); __syncthreads(); }
    }
    #pragma unroll
    for (int mi = 0; mi < 2; mi++)
        #pragma unroll
        for (int ni = 0; ni < 4; ni++) {
            float* ptr = &out[(size_t)(row0 + wm*32 + mi*16)*ldc
                              + col0 + wn*64 + ni*16];
            if (ADD) {
                wmma::fragment<wmma::accumulator, 16, 16, 8, float> prev;
                wmma::load_matrix_sync(prev, ptr, ldc, wmma::mem_row_major);
                #pragma unroll
                for (int e = 0; e < prev.num_elements; e++)
                    acc[mi][ni].x[e] += prev.x[e];
            }
            wmma::store_matrix_sync(ptr, acc[mi][ni], ldc, wmma::mem_row_major);
        }
}

// ---------------- RoPE ----------------
__device__ __forceinline__ float inv_freq(int j) {
    return (float)exp(-(double)j * (9.210340371976184 / 16.0));
}

__global__ void mosa_rope_kernel() {
    int g = blockIdx.x*blockDim.x + threadIdx.x;
    int j  = g & 15;
    int kk = (g >> 4) & 255;
    int bn = g >> 12;
    float pos = (float)d_idx[bn*KSEL + kk];
    float ang = pos * inv_freq(j);
    float s, c; sincosf(ang, &s, &c);
    float* p = d_mqkv + ((size_t)bn*KSEL + kk)*QKV3;
    float x1 = p[j], x2 = p[16+j];
    p[j] = x1*c - x2*s;  p[16+j] = x1*s + x2*c;
    x1 = p[64+j]; x2 = p[80+j];
    p[64+j] = x1*c - x2*s; p[80+j] = x1*s + x2*c;
}

__global__ void dense_rope_kernel() {
    int g = blockIdx.x*blockDim.x + threadIdx.x;
    int j = g & 15;
    int n = (g >> 4) & 7;
    int t = (g >> 7) & 2047;
    int b = g >> 18;
    float ang = (float)t * inv_freq(j);
    float s, c; sincosf(ang, &s, &c);
    float* p = d_dqkv + ((size_t)(b*TT + t))*(NHD*QKV3) + n*QKV3;
    float x1 = p[j], x2 = p[16+j];
    p[j] = x1*c - x2*s;  p[16+j] = x1*s + x2*c;
    x1 = p[64+j]; x2 = p[80+j];
    p[64+j] = x1*c - x2*s; p[80+j] = x1*s + x2*c;
}

// ========== FA2 flash: register O/softmax/P, K/V prefetch, 2 syncs/iter ======
#define FQ_LD 68
#define FK_LD 68
#define FV_LD 76
#define FL_SMEM_BYTES ((128*FQ_LD + 64*FK_LD + 64*FV_LD)*4)

template<bool MOSA>
__global__ __launch_bounds__(256, 2) void flash_fa2_kernel() {
    extern __shared__ float sm[];
    float* Qs = sm;                       // [128][FQ_LD]
    float* Ks = Qs + 128*FQ_LD;           // [64][FK_LD]
    float* Vs = Ks + 64*FK_LD;            // [64][FV_LD]

    int qt = MOSA ? blockIdx.x : (gridDim.x - 1 - blockIdx.x);
    int n = blockIdx.y, b = blockIdx.z;
    int bn = b*NHM + n;
    int tid = threadIdx.x;
    int w = tid >> 5, lane = tid & 31;
    int lq = lane >> 2, lr = lane & 3;
    const int RS = MOSA ? QKV3 : NHD*QKV3;
    const float* src = MOSA ? d_mqkv : d_dqkv;

    for (int s = tid; s < 2048; s += 256) {
        int r = s >> 4, c4 = (s & 15)*4;
        size_t base = MOSA ? ((size_t)(bn*KSEL + qt*128 + r))*QKV3
                           : ((size_t)(b*TT + qt*128 + r))*RS + n*QKV3;
        float4 v = *(const float4*)(src + base + c4);
        Qs[r*FQ_LD + c4+0] = f2tf32(v.x);
        Qs[r*FQ_LD + c4+1] = f2tf32(v.y);
        Qs[r*FQ_LD + c4+2] = f2tf32(v.z);
        Qs[r*FQ_LD + c4+3] = f2tf32(v.w);
    }

    int row0 = w*16;
    int gr0 = qt*128 + row0 + lq;
    int gr1 = gr0 + 8;

    float o[8][4];
    #pragma unroll
    for (int ni = 0; ni < 8; ni++)
        #pragma unroll
        for (int e = 0; e < 4; e++) o[ni][e] = 0.f;
    float m0 = NEGINF, m1 = NEGINF, l0 = 0.f, l1 = 0.f;

    float4 kpre[4], vpre[4];
    auto ld_kv = [&](int kt) {
        #pragma unroll
        for (int i = 0; i < 4; i++) {
            int s = tid + i*256;
            int r = s >> 4, c4 = (s & 15)*4;
            size_t base = MOSA ? ((size_t)(bn*KSEL + kt*64 + r))*QKV3
                               : ((size_t)(b*TT + kt*64 + r))*RS + n*QKV3;
            kpre[i] = *(const float4*)(src + base + 64 + c4);
            vpre[i] = *(const float4*)(src + base + 128 + c4);
        }
    };
    auto st_kv = [&]() {
        #pragma unroll
        for (int i = 0; i < 4; i++) {
            int s = tid + i*256;
            int r = s >> 4, c4 = (s & 15)*4;
            Ks[r*FK_LD + c4+0] = f2tf32(kpre[i].x);
            Ks[r*FK_LD + c4+1] = f2tf32(kpre[i].y);
            Ks[r*FK_LD + c4+2] = f2tf32(kpre[i].z);
            Ks[r*FK_LD + c4+3] = f2tf32(kpre[i].w);
            Vs[r*FV_LD + c4+0] = f2tf32(vpre[i].x);
            Vs[r*FV_LD + c4+1] = f2tf32(vpre[i].y);
            Vs[r*FV_LD + c4+2] = f2tf32(vpre[i].z);
            Vs[r*FV_LD + c4+3] = f2tf32(vpre[i].w);
        }
    };

    int nkt = 2*qt + 2;
    ld_kv(0);
    for (int kt = 0; kt < nkt; kt++) {
        st_kv();
        __syncthreads();   // (1) K/V (and Q on first iter) ready
        if (kt + 1 < nkt) ld_kv(kt+1);   // hide next tile's gmem latency

        float sacc[8][4];
        #pragma unroll
        for (int ni = 0; ni < 8; ni++)
            #pragma unroll
            for (int e = 0; e < 4; e++) sacc[ni][e] = 0.f;
        #pragma unroll
        for (int k = 0; k < 8; k++) {
            unsigned af[4];
            af[0] = __float_as_uint(Qs[(row0 + lq)*FQ_LD + k*8 + lr]);
            af[1] = __float_as_uint(Qs[(row0 + 8 + lq)*FQ_LD + k*8 + lr]);
            af[2] = __float_as_uint(Qs[(row0 + lq)*FQ_LD + k*8 + lr + 4]);
            af[3] = __float_as_uint(Qs[(row0 + 8 + lq)*FQ_LD + k*8 + lr + 4]);
            #pragma unroll
            for (int ni = 0; ni < 8; ni++) {
                unsigned b0 = __float_as_uint(Ks[(ni*8 + lq)*FK_LD + k*8 + lr]);
                unsigned b1 = __float_as_uint(Ks[(ni*8 + lq)*FK_LD + k*8 + lr + 4]);
                mma_tf32(sacc[ni], af, b0, b1);
            }
        }

        // ---- online softmax; P kept in sacc (registers), tf32-rounded ----
        int cbase = kt*64 + 2*lr;
        float mx0 = NEGINF, mx1 = NEGINF;
        #pragma unroll
        for (int ni = 0; ni < 8; ni++) {
            int c0 = cbase + ni*8, c1 = c0 + 1;
            float s00 = (c0 <= gr0) ? sacc[ni][0]*0.125f : NEGINF;
            float s01 = (c1 <= gr0) ? sacc[ni][1]*0.125f : NEGINF;
            float s10 = (c0 <= gr1) ? sacc[ni][2]*0.125f : NEGINF;
            float s11 = (c1 <= gr1) ? sacc[ni][3]*0.125f : NEGINF;
            sacc[ni][0] = s00; sacc[ni][1] = s01;
            sacc[ni][2] = s10; sacc[ni][3] = s11;
            mx0 = fmaxf(mx0, fmaxf(s00, s01));
            mx1 = fmaxf(mx1, fmaxf(s10, s11));
        }
        mx0 = fmaxf(mx0, __shfl_xor_sync(0xffffffffu, mx0, 1));
        mx0 = fmaxf(mx0, __shfl_xor_sync(0xffffffffu, mx0, 2));
        mx1 = fmaxf(mx1, __shfl_xor_sync(0xffffffffu, mx1, 1));
        mx1 = fmaxf(mx1, __shfl_xor_sync(0xffffffffu, mx1, 2));
        float mn0 = fmaxf(m0, mx0), mn1 = fmaxf(m1, mx1);
        float al0 = __expf(m0 - mn0), al1 = __expf(m1 - mn1);
        float ps0 = 0.f, ps1 = 0.f;
        #pragma unroll
        for (int ni = 0; ni < 8; ni++) {
            float p00 = __expf(sacc[ni][0] - mn0);
            float p01 = __expf(sacc[ni][1] - mn0);
            float p10 = __expf(sacc[ni][2] - mn1);
            float p11 = __expf(sacc[ni][3] - mn1);
            ps0 += p00 + p01;
            ps1 += p10 + p11;
            sacc[ni][0] = f2tf32(p00);
            sacc[ni][1] = f2tf32(p01);
            sacc[ni][2] = f2tf32(p10);
            sacc[ni][3] = f2tf32(p11);
        }
        ps0 += __shfl_xor_sync(0xffffffffu, ps0, 1);
        ps0 += __shfl_xor_sync(0xffffffffu, ps0, 2);
        ps1 += __shfl_xor_sync(0xffffffffu, ps1, 1);
        ps1 += __shfl_xor_sync(0xffffffffu, ps1, 2);
        l0 = l0*al0 + ps0;  m0 = mn0;
        l1 = l1*al1 + ps1;  m1 = mn1;
        #pragma unroll
        for (int ni = 0; ni < 8; ni++) {
            o[ni][0] *= al0; o[ni][1] *= al0;
            o[ni][2] *= al1; o[ni][3] *= al1;
        }

        // ---- O += P V : P A-fragments built by lane shuffle (no smem P) ----
        // have:  p00=P[lq][kblk*8+2lr], p01=+1, p10/p11 same cols row lq+8
        // need:  af0=P[lq][kblk*8+lr], af1=row lq+8, af2/af3 at col lr+4
        int srcA = (lane & 28) | (lr >> 1);   // lq*4 + lr/2
        int srcB = srcA + 2;
        bool odd = (lr & 1);
        #pragma unroll
        for (int k = 0; k < 8; k++) {
            float v00a = __shfl_sync(0xffffffffu, sacc[k][0], srcA);
            float v01a = __shfl_sync(0xffffffffu, sacc[k][1], srcA);
            float v10a = __shfl_sync(0xffffffffu, sacc[k][2], srcA);
            float v11a = __shfl_sync(0xffffffffu, sacc[k][3], srcA);
            float v00b = __shfl_sync(0xffffffffu, sacc[k][0], srcB);
            float v01b = __shfl_sync(0xffffffffu, sacc[k][1], srcB);
            float v10b = __shfl_sync(0xffffffffu, sacc[k][2], srcB);
            float v11b = __shfl_sync(0xffffffffu, sacc[k][3], srcB);
            unsigned af[4];
            af[0] = __float_as_uint(odd ? v01a : v00a);
            af[1] = __float_as_uint(odd ? v11a : v10a);
            af[2] = __float_as_uint(odd ? v01b : v00b);
            af[3] = __float_as_uint(odd ? v11b : v10b);
            #pragma unroll
            for (int ni = 0; ni < 8; ni++) {
                unsigned b0 = __float_as_uint(Vs[(k*8 + lr)*FV_LD + ni*8 + lq]);
                unsigned b1 = __float_as_uint(Vs[(k*8 + lr + 4)*FV_LD + ni*8 + lq]);
                mma_tf32(o[ni], af, b0, b1);
            }
        }
        __syncthreads();   // (2) Ks/Vs consumed; safe to overwrite next iter
    }

    if (MOSA) {
        int tok0 = d_idx[bn*KSEL + gr0];
        int tok1 = d_idx[bn*KSEL + gr1];
        float s0 = d_gates[bn*KSEL + gr0] / l0;
        float s1 = d_gates[bn*KSEL + gr1] / l1;
        #pragma unroll
        for (int ni = 0; ni < 8; ni++) {
            int c = n*64 + ni*8 + 2*lr;
            *(float2*)&d_Y[((size_t)(b*TT + tok0))*1024 + c] =
                make_float2(o[ni][0]*s0, o[ni][1]*s0);
            *(float2*)&d_Y[((size_t)(b*TT + tok1))*1024 + c] =
                make_float2(o[ni][2]*s1, o[ni][3]*s1);
        }
    } else {
        float s0 = 1.f/l0, s1 = 1.f/l1;
        #pragma unroll
        for (int ni = 0; ni < 8; ni++) {
            int c = 512 + n*64 + ni*8 + 2*lr;
            *(float2*)&d_Y[((size_t)(b*TT + gr0))*1024 + c] =
                make_float2(o[ni][0]*s0, o[ni][1]*s0);
            *(float2*)&d_Y[((size_t)(b*TT + gr1))*1024 + c] =
                make_float2(o[ni][2]*s1, o[ni][3]*s1);
        }
    }
}

// ---------------- launch: fork-join graph ----------------
extern "C" void kernel_launch(void* const* d_in, const int* in_sizes, int n_in,
                              void* d_out, int out_size) {
    const float* X     = (const float*)d_in[0];
    const float* rw    = (const float*)d_in[1];
    const float* mwqkv = (const float*)d_in[2];
    const float* mwo   = (const float*)d_in[3];
    const float* dwqkv = (const float*)d_in[4];
    const float* dwo   = (const float*)d_in[5];
    float* out = (float*)d_out;

    static cudaStream_t sB = nullptr;
    static cudaEvent_t eFork = nullptr, eJoin = nullptr;
    if (sB == nullptr) {
        cudaStreamCreateWithFlags(&sB, cudaStreamNonBlocking);
        cudaEventCreateWithFlags(&eFork, cudaEventDisableTiming);
        cudaEventCreateWithFlags(&eJoin, cudaEventDisableTiming);
        cudaFuncSetAttribute(flash_fa2_kernel<false>,
            cudaFuncAttributeMaxDynamicSharedMemorySize, FL_SMEM_BYTES);
        cudaFuncSetAttribute(flash_fa2_kernel<true>,
            cudaFuncAttributeMaxDynamicSharedMemorySize, FL_SMEM_BYTES);
    }

    cudaEventRecord(eFork, 0);
    cudaStreamWaitEvent(sB, eFork, 0);

    // ---- branch A (default stream): mosa chain + mosa half of final ----
    zeroY_kernel<<<ZERO_BLOCKS, 256>>>();
    router_kernel<<<dim3(TT, BB), 256>>>(X, rw);
    topk_kernel<<<BB*NHM, 1024>>>();
    mosa_qkv_wmma_kernel<<<dim3(3, 4, 2*BB*NHM), 256>>>(X, mwqkv);
    mosa_rope_kernel<<<256, 256>>>();
    flash_fa2_kernel<true><<<dim3(2, NHM, BB), 256, FL_SMEM_BYTES>>>();
    final_half_kernel<false><<<dim3(8, 32), 256>>>(mwo, out, 0);   // out = Ym@mwo

    // ---- branch B (side stream): dense chain ----
    dense_qkv_wmma_kernel<<<dim3(12, 32), 256, 0, sB>>>(X, dwqkv);
    dense_rope_kernel<<<2048, 256, 0, sB>>>();
    flash_fa2_kernel<false><<<dim3(16, NHD, BB), 256, FL_SMEM_BYTES, sB>>>();

    // join, then add dense half of final
    cudaEventRecord(eJoin, sB);
    cudaStreamWaitEvent(0, eJoin, 0);
    final_half_kernel<true><<<dim3(8, 32), 256>>>(dwo, out, 512);  // out += Yd@dwo
}

// round 17
// speedup vs baseline: 2.2063x; 1.0188x over previous
#include <cuda_runtime.h>
#include <mma.h>
#include <math.h>

using namespace nvcuda;

#define BB   2
#define TT   2048
#define HH   1024
#define HPP  64
#define NHM  8
#define NHD  8
#define KSEL 256
#define QKV3 192
#define NEGINF (-3.0e38f)

__device__ __align__(128) float d_scores[BB*NHM*TT];
__device__ __align__(128) int   d_idx   [BB*NHM*KSEL];
__device__ __align__(128) float d_gates [BB*NHM*KSEL];
__device__ __align__(128) float d_mqkv  [BB*NHM*KSEL*QKV3];
__device__ __align__(128) float d_dqkv  [(size_t)BB*TT*NHD*QKV3];
__device__ __align__(128) float d_Y     [(size_t)BB*TT*1024];

__device__ __forceinline__ float f2tf32(float f) {
    unsigned u; asm("cvt.rna.tf32.f32 %0, %1;" : "=r"(u) : "f"(f));
    return __uint_as_float(u);
}

__device__ __forceinline__ void mma_tf32(float* c, const unsigned* a,
                                         unsigned b0, unsigned b1) {
    asm volatile("mma.sync.aligned.m16n8k8.row.col.f32.tf32.tf32.f32 "
        "{%0,%1,%2,%3}, {%4,%5,%6,%7}, {%8,%9}, {%0,%1,%2,%3};"
        : "+f"(c[0]), "+f"(c[1]), "+f"(c[2]), "+f"(c[3])
        : "r"(a[0]), "r"(a[1]), "r"(a[2]), "r"(a[3]), "r"(b0), "r"(b1));
}

// ---------------- zero: mosa half of Y + d_mqkv ----------------
#define ZERO_BLOCKS 2816
__global__ void zeroY_kernel() {
    int i = blockIdx.x*blockDim.x + threadIdx.x;
    const int NY = BB*TT*128;
    const int NM = BB*NHM*KSEL*QKV3/4;
    if (i < NY) {
        int r = i >> 7, c = i & 127;
        *(float4*)&d_Y[(size_t)r*1024 + c*4] = make_float4(0.f,0.f,0.f,0.f);
    } else if (i - NY < NM) {
        ((float4*)d_mqkv)[i - NY] = make_float4(0.f,0.f,0.f,0.f);
    }
}

// ---------------- router ----------------
__global__ void router_kernel(const float* __restrict__ X,
                              const float* __restrict__ rw) {
    __shared__ float Xs[HH];
    int t = blockIdx.x, b = blockIdx.y;
    const float* xr = X + ((size_t)b*TT + t)*HH;
    for (int i = threadIdx.x; i < HH; i += blockDim.x) Xs[i] = xr[i];
    __syncthreads();
    int w = threadIdx.x >> 5, lane = threadIdx.x & 31;
    float s = 0.f;
    for (int h = lane; h < HH; h += 32) s += Xs[h] * rw[h*NHM + w];
    #pragma unroll
    for (int o = 16; o; o >>= 1) s += __shfl_down_sync(0xffffffffu, s, o);
    if (lane == 0) d_scores[((size_t)b*NHM + w)*TT + t] = s;
}

// ---------------- top-k via radix select + ordered compaction ----------------
__global__ __launch_bounds__(1024) void topk_kernel() {
    __shared__ unsigned keys[TT];
    __shared__ int hist[256];
    __shared__ int warpsum[32];
    __shared__ int bcast[2];
    int bn = blockIdx.x, tid = threadIdx.x;
    int lane = tid & 31, wid = tid >> 5;
    const float* sc = d_scores + (size_t)bn*TT;

    for (int t = tid; t < TT; t += 1024) {
        unsigned u = __float_as_uint(sc[t]);
        u ^= (u & 0x80000000u) ? 0xFFFFFFFFu : 0x80000000u;
        keys[t] = u;
    }
    __syncthreads();

    unsigned prefix = 0;
    int need = KSEL;
    #pragma unroll 1
    for (int level = 0; level < 4; level++) {
        int shift = 24 - level*8;
        if (tid < 256) hist[tid] = 0;
        __syncthreads();
        for (int t = tid; t < TT; t += 1024) {
            unsigned k = keys[t];
            bool match = (level == 0) || ((k >> (shift + 8)) == (prefix >> (shift + 8)));
            if (match) atomicAdd(&hist[(k >> shift) & 255], 1);
        }
        __syncthreads();
        if (tid == 0) {
            int cum = 0, bsel = 0;
            for (int b = 255; b >= 0; b--) {
                int c = hist[b];
                if (cum + c >= need) { bsel = b; break; }
                cum += c;
            }
            bcast[0] = bsel;
            bcast[1] = need - cum;
        }
        __syncthreads();
        int bsel = bcast[0];
        need = bcast[1];
        prefix |= ((unsigned)bsel) << shift;
        __syncthreads();
    }
    unsigned thr = prefix;

    int t0 = tid*2, t1 = tid*2 + 1;
    unsigned k0 = keys[t0], k1 = keys[t1];
    int eq0 = (k0 == thr), eq1 = (k1 == thr);
    int gt0 = (k0 > thr),  gt1 = (k1 > thr);

    int mysum = eq0 + eq1;
    int incl = mysum;
    #pragma unroll
    for (int o = 1; o < 32; o <<= 1) {
        int v = __shfl_up_sync(0xffffffffu, incl, o);
        if (lane >= o) incl += v;
    }
    if (lane == 31) warpsum[wid] = incl;
    __syncthreads();
    if (wid == 0) {
        int v = warpsum[lane];
        int iv = v;
        #pragma unroll
        for (int o = 1; o < 32; o <<= 1) {
            int x = __shfl_up_sync(0xffffffffu, iv, o);
            if (lane >= o) iv += x;
        }
        warpsum[lane] = iv - v;
    }
    __syncthreads();
    int exb = warpsum[wid] + (incl - mysum);
    int sel0 = gt0 || (eq0 && exb < need);
    int sel1 = gt1 || (eq1 && (exb + eq0) < need);
    __syncthreads();

    int mysum2 = sel0 + sel1;
    int incl2 = mysum2;
    #pragma unroll
    for (int o = 1; o < 32; o <<= 1) {
        int v = __shfl_up_sync(0xffffffffu, incl2, o);
        if (lane >= o) incl2 += v;
    }
    if (lane == 31) warpsum[wid] = incl2;
    __syncthreads();
    if (wid == 0) {
        int v = warpsum[lane];
        int iv = v;
        #pragma unroll
        for (int o = 1; o < 32; o <<= 1) {
            int x = __shfl_up_sync(0xffffffffu, iv, o);
            if (lane >= o) iv += x;
        }
        warpsum[lane] = iv - v;
    }
    __syncthreads();
    int pos = warpsum[wid] + (incl2 - mysum2);
    if (sel0) {
        d_idx[bn*KSEL + pos] = t0;
        d_gates[bn*KSEL + pos] = 1.f/(1.f + expf(-sc[t0]));
    }
    pos += sel0;
    if (sel1) {
        d_idx[bn*KSEL + pos] = t1;
        d_gates[bn*KSEL + pos] = 1.f/(1.f + expf(-sc[t1]));
    }
}

// ---------------- MoSA qkv: tf32 wmma, split-K x2, atomicAdd epilogue --------
#define MQ_AS 20
#define MQ_BS 68
__global__ __launch_bounds__(256) void mosa_qkv_wmma_kernel(
        const float* __restrict__ X, const float* __restrict__ W) {
    __shared__ __align__(16) float As[2][64*MQ_AS];
    __shared__ __align__(16) float Bs[2][16*MQ_BS];
    __shared__ __align__(16) float stg[8][256];
    int z = blockIdx.z, bn = z >> 1, half = z & 1;
    int b = bn >> 3, n = bn & 7;
    int mt = blockIdx.y, nt = blockIdx.x;
    int tid = threadIdx.x, lane = tid & 31;
    int warp = tid >> 5, wm = warp >> 2, wn = warp & 3;
    int arow = tid >> 2, a4 = (tid & 3)*4;
    int brow = tid >> 4, bcol = (tid & 15)*4;
    int tok = d_idx[bn*KSEL + mt*64 + arow];
    const float* Ap = X + ((size_t)b*TT + tok)*HH + half*512 + a4;
    const float* Bp = W + (size_t)n*QKV3 + nt*64 + bcol;
    int krow0 = half*512;

    float4 a_st, b_st;
    auto load_tile = [&](int k0) {
        a_st = *(const float4*)(Ap + k0);
        b_st = *(const float4*)(Bp + (size_t)(krow0 + k0 + brow)*(NHM*QKV3));
    };
    auto store_tile = [&](int bi) {
        float* A_ = As[bi]; float* B_ = Bs[bi];
        A_[arow*MQ_AS + a4+0] = f2tf32(a_st.x);
        A_[arow*MQ_AS + a4+1] = f2tf32(a_st.y);
        A_[arow*MQ_AS + a4+2] = f2tf32(a_st.z);
        A_[arow*MQ_AS + a4+3] = f2tf32(a_st.w);
        B_[brow*MQ_BS + bcol+0] = f2tf32(b_st.x);
        B_[brow*MQ_BS + bcol+1] = f2tf32(b_st.y);
        B_[brow*MQ_BS + bcol+2] = f2tf32(b_st.z);
        B_[brow*MQ_BS + bcol+3] = f2tf32(b_st.w);
    };

    wmma::fragment<wmma::accumulator, 16, 16, 8, float> acc[2];
    wmma::fill_fragment(acc[0], 0.f);
    wmma::fill_fragment(acc[1], 0.f);

    load_tile(0); store_tile(0); __syncthreads();

    const int KT = 512/16;
    #pragma unroll 1
    for (int kt = 0; kt < KT; kt++) {
        bool more = (kt + 1 < KT);
        if (more) load_tile((kt+1)*16);
        int bi = kt & 1;
        #pragma unroll
        for (int ks = 0; ks < 2; ks++) {
            wmma::fragment<wmma::matrix_b, 16, 16, 8,
                           wmma::precision::tf32, wmma::row_major> bf;
            wmma::load_matrix_sync(bf, &Bs[bi][(ks*8)*MQ_BS + wn*16], MQ_BS);
            #pragma unroll
            for (int mi = 0; mi < 2; mi++) {
                wmma::fragment<wmma::matrix_a, 16, 16, 8,
                               wmma::precision::tf32, wmma::row_major> af;
                wmma::load_matrix_sync(af, &As[bi][(wm*32 + mi*16)*MQ_AS + ks*8], MQ_AS);
                wmma::mma_sync(acc[mi], af, bf, acc[mi]);
            }
        }
        if (more) { store_tile(bi ^ 1); __syncthreads(); }
    }
    float* wst = stg[warp];
    #pragma unroll
    for (int mi = 0; mi < 2; mi++) {
        wmma::store_matrix_sync(wst, acc[mi], 16, wmma::mem_row_major);
        __syncwarp();
        float* dst = &d_mqkv[((size_t)bn*KSEL + mt*64 + wm*32 + mi*16)*QKV3
                             + nt*64 + wn*16];
        #pragma unroll
        for (int e = 0; e < 8; e++) {
            int idx = lane*8 + e;
            int r = idx >> 4, c = idx & 15;
            atomicAdd(&dst[(size_t)r*QKV3 + c], wst[idx]);
        }
        __syncwarp();
    }
}

// ================= tf32 WMMA GEMM (double-buffered) ==========================
#define AS_STRIDE 20
#define BS_STRIDE 136

__global__ __launch_bounds__(256) void dense_qkv_wmma_kernel(
        const float* __restrict__ A, const float* __restrict__ B)
{
    __shared__ __align__(16) float As[2][128*AS_STRIDE];
    __shared__ __align__(16) float Bs[2][16*BS_STRIDE];
    const int K = HH, lda = HH, ldb = NHD*QKV3, ldc = NHD*QKV3;
    int tid = threadIdx.x;
    int warp = tid >> 5;
    int wm = warp >> 1, wn = warp & 1;
    int row0 = blockIdx.y*128, col0 = blockIdx.x*128;
    int arow = tid >> 2, acol = (tid & 3)*4;
    int brow = tid >> 5, bcol = (tid & 31)*4;

    const float* Ag = A + (size_t)(row0 + arow)*lda + acol;
    const float* Bg = B + col0 + bcol;

    float4 a0, a1, b0, b1;
    auto load_tile = [&](int k0) {
        a0 = *(const float4*)(Ag + k0);
        a1 = *(const float4*)(Ag + (size_t)64*lda + k0);
        b0 = *(const float4*)(Bg + (size_t)(k0 + brow)*ldb);
        b1 = *(const float4*)(Bg + (size_t)(k0 + brow + 8)*ldb);
    };
    auto store_tile = [&](int bi) {
        float* A_ = As[bi]; float* B_ = Bs[bi];
        A_[arow*AS_STRIDE + acol+0] = f2tf32(a0.x);
        A_[arow*AS_STRIDE + acol+1] = f2tf32(a0.y);
        A_[arow*AS_STRIDE + acol+2] = f2tf32(a0.z);
        A_[arow*AS_STRIDE + acol+3] = f2tf32(a0.w);
        A_[(arow+64)*AS_STRIDE + acol+0] = f2tf32(a1.x);
        A_[(arow+64)*AS_STRIDE + acol+1] = f2tf32(a1.y);
        A_[(arow+64)*AS_STRIDE + acol+2] = f2tf32(a1.z);
        A_[(arow+64)*AS_STRIDE + acol+3] = f2tf32(a1.w);
        B_[brow*BS_STRIDE + bcol+0] = f2tf32(b0.x);
        B_[brow*BS_STRIDE + bcol+1] = f2tf32(b0.y);
        B_[brow*BS_STRIDE + bcol+2] = f2tf32(b0.z);
        B_[brow*BS_STRIDE + bcol+3] = f2tf32(b0.w);
        B_[(brow+8)*BS_STRIDE + bcol+0] = f2tf32(b1.x);
        B_[(brow+8)*BS_STRIDE + bcol+1] = f2tf32(b1.y);
        B_[(brow+8)*BS_STRIDE + bcol+2] = f2tf32(b1.z);
        B_[(brow+8)*BS_STRIDE + bcol+3] = f2tf32(b1.w);
    };

    wmma::fragment<wmma::accumulator, 16, 16, 8, float> acc[2][4];
    #pragma unroll
    for (int mi = 0; mi < 2; mi++)
        #pragma unroll
        for (int ni = 0; ni < 4; ni++)
            wmma::fill_fragment(acc[mi][ni], 0.0f);

    load_tile(0); store_tile(0); __syncthreads();

    #pragma unroll 1
    for (int kt = 0; kt < K/16; kt++) {
        bool more = (kt + 1 < K/16);
        if (more) load_tile((kt+1)*16);
        int bi = kt & 1;
        #pragma unroll
        for (int ks = 0; ks < 2; ks++) {
            wmma::fragment<wmma::matrix_a, 16, 16, 8,
                           wmma::precision::tf32, wmma::row_major> af[2];
            wmma::fragment<wmma::matrix_b, 16, 16, 8,
                           wmma::precision::tf32, wmma::row_major> bf[4];
            #pragma unroll
            for (int mi = 0; mi < 2; mi++)
                wmma::load_matrix_sync(af[mi],
                    &As[bi][(wm*32 + mi*16)*AS_STRIDE + ks*8], AS_STRIDE);
            #pragma unroll
            for (int ni = 0; ni < 4; ni++)
                wmma::load_matrix_sync(bf[ni],
                    &Bs[bi][(ks*8)*BS_STRIDE + wn*64 + ni*16], BS_STRIDE);
            #pragma unroll
            for (int mi = 0; mi < 2; mi++)
                #pragma unroll
                for (int ni = 0; ni < 4; ni++)
                    wmma::mma_sync(acc[mi][ni], af[mi], bf[ni], acc[mi][ni]);
        }
        if (more) { store_tile(bi ^ 1); __syncthreads(); }
    }
    #pragma unroll
    for (int mi = 0; mi < 2; mi++)
        #pragma unroll
        for (int ni = 0; ni < 4; ni++)
            wmma::store_matrix_sync(
                &d_dqkv[(size_t)(row0 + wm*32 + mi*16)*ldc + col0 + wn*64 + ni*16],
                acc[mi][ni], ldc, wmma::mem_row_major);
}

// final GEMM halves: out (+)= Y[:, ycol0:ycol0+512] @ W[512,1024]
template<bool ADD>
__global__ __launch_bounds__(256) void final_half_kernel(
        const float* __restrict__ W, float* __restrict__ out, int ycol0)
{
    __shared__ __align__(16) float As[2][128*AS_STRIDE];
    __shared__ __align__(16) float Bs[2][16*BS_STRIDE];
    const int K = 512, lda = 1024, ldb = 1024, ldc = 1024;
    int tid = threadIdx.x;
    int warp = tid >> 5;
    int wm = warp >> 1, wn = warp & 1;
    int row0 = blockIdx.y*128, col0 = blockIdx.x*128;
    int arow = tid >> 2, acol = (tid & 3)*4;
    int brow = tid >> 5, bcol = (tid & 31)*4;

    const float* Ag = d_Y + (size_t)(row0 + arow)*lda + ycol0 + acol;
    const float* Bg = W + col0 + bcol;

    float4 a0, a1, b0, b1;
    auto load_tile = [&](int k0) {
        a0 = *(const float4*)(Ag + k0);
        a1 = *(const float4*)(Ag + (size_t)64*lda + k0);
        b0 = *(const float4*)(Bg + (size_t)(k0 + brow)*ldb);
        b1 = *(const float4*)(Bg + (size_t)(k0 + brow + 8)*ldb);
    };
    auto store_tile = [&](int bi) {
        float* A_ = As[bi]; float* B_ = Bs[bi];
        A_[arow*AS_STRIDE + acol+0] = f2tf32(a0.x);
        A_[arow*AS_STRIDE + acol+1] = f2tf32(a0.y);
        A_[arow*AS_STRIDE + acol+2] = f2tf32(a0.z);
        A_[arow*AS_STRIDE + acol+3] = f2tf32(a0.w);
        A_[(arow+64)*AS_STRIDE + acol+0] = f2tf32(a1.x);
        A_[(arow+64)*AS_STRIDE + acol+1] = f2tf32(a1.y);
        A_[(arow+64)*AS_STRIDE + acol+2] = f2tf32(a1.z);
        A_[(arow+64)*AS_STRIDE + acol+3] = f2tf32(a1.w);
        B_[brow*BS_STRIDE + bcol+0] = f2tf32(b0.x);
        B_[brow*BS_STRIDE + bcol+1] = f2tf32(b0.y);
        B_[brow*BS_STRIDE + bcol+2] = f2tf32(b0.z);
        B_[brow*BS_STRIDE + bcol+3] = f2tf32(b0.w);
        B_[(brow+8)*BS_STRIDE + bcol+0] = f2tf32(b1.x);
        B_[(brow+8)*BS_STRIDE + bcol+1] = f2tf32(b1.y);
        B_[(brow+8)*BS_STRIDE + bcol+2] = f2tf32(b1.z);
        B_[(brow+8)*BS_STRIDE + bcol+3] = f2tf32(b1.w);
    };

    wmma::fragment<wmma::accumulator, 16, 16, 8, float> acc[2][4];
    #pragma unroll
    for (int mi = 0; mi < 2; mi++)
        #pragma unroll
        for (int ni = 0; ni < 4; ni++)
            wmma::fill_fragment(acc[mi][ni], 0.0f);

    load_tile(0); store_tile(0); __syncthreads();

    #pragma unroll 1
    for (int kt = 0; kt < K/16; kt++) {
        bool more = (kt + 1 < K/16);
        if (more) load_tile((kt+1)*16);
        int bi = kt & 1;
        #pragma unroll
        for (int ks = 0; ks < 2; ks++) {
            wmma::fragment<wmma::matrix_a, 16, 16, 8,
                           wmma::precision::tf32, wmma::row_major> af[2];
            wmma::fragment<wmma::matrix_b, 16, 16, 8,
                           wmma::precision::tf32, wmma::row_major> bf[4];
            #pragma unroll
            for (int mi = 0; mi < 2; mi++)
                wmma::load_matrix_sync(af[mi],
                    &As[bi][(wm*32 + mi*16)*AS_STRIDE + ks*8], AS_STRIDE);
            #pragma unroll
            for (int ni = 0; ni < 4; ni++)
                wmma::load_matrix_sync(bf[ni],
                    &Bs[bi][(ks*8)*BS_STRIDE + wn*64 + ni*16], BS_STRIDE);
            #pragma unroll
            for (int mi = 0; mi < 2; mi++)
                #pragma unroll
                for (int ni = 0; ni < 4; ni++)
                    wmma::mma_sync(acc[mi][ni], af[mi], bf[ni], acc[mi][ni]);
        }
        if (more) { store_tile(bi ^ 1); __syncthreads(); }
    }
    #pragma unroll
    for (int mi = 0; mi < 2; mi++)
        #pragma unroll
        for (int ni = 0; ni < 4; ni++) {
            float* ptr = &out[(size_t)(row0 + wm*32 + mi*16)*ldc
                              + col0 + wn*64 + ni*16];
            if (ADD) {
                wmma::fragment<wmma::accumulator, 16, 16, 8, float> prev;
                wmma::load_matrix_sync(prev, ptr, ldc, wmma::mem_row_major);
                #pragma unroll
                for (int e = 0; e < prev.num_elements; e++)
                    acc[mi][ni].x[e] += prev.x[e];
            }
            wmma::store_matrix_sync(ptr, acc[mi][ni], ldc, wmma::mem_row_major);
        }
}

// ---------------- RoPE ----------------
__device__ __forceinline__ float inv_freq(int j) {
    return (float)exp(-(double)j * (9.210340371976184 / 16.0));
}

__global__ void mosa_rope_kernel() {
    int g = blockIdx.x*blockDim.x + threadIdx.x;
    int j  = g & 15;
    int kk = (g >> 4) & 255;
    int bn = g >> 12;
    float pos = (float)d_idx[bn*KSEL + kk];
    float ang = pos * inv_freq(j);
    float s, c; sincosf(ang, &s, &c);
    float* p = d_mqkv + ((size_t)bn*KSEL + kk)*QKV3;
    float x1 = p[j], x2 = p[16+j];
    p[j] = x1*c - x2*s;  p[16+j] = x1*s + x2*c;
    x1 = p[64+j]; x2 = p[80+j];
    p[64+j] = x1*c - x2*s; p[80+j] = x1*s + x2*c;
}

__global__ void dense_rope_kernel() {
    int g = blockIdx.x*blockDim.x + threadIdx.x;
    int j = g & 15;
    int n = (g >> 4) & 7;
    int t = (g >> 7) & 2047;
    int b = g >> 18;
    float ang = (float)t * inv_freq(j);
    float s, c; sincosf(ang, &s, &c);
    float* p = d_dqkv + ((size_t)(b*TT + t))*(NHD*QKV3) + n*QKV3;
    float x1 = p[j], x2 = p[16+j];
    p[j] = x1*c - x2*s;  p[16+j] = x1*s + x2*c;
    x1 = p[64+j]; x2 = p[80+j];
    p[64+j] = x1*c - x2*s; p[80+j] = x1*s + x2*c;
}

// ==== FA2 flash v3: Q in regs, cp.async double-buffered K/V, 1 sync/iter =====
#define FK_LD 68
#define FV_LD 76
#define KV_FLOATS (64*FK_LD + 64*FV_LD)     // 9216 floats = 36KB per buffer
#define FL_SMEM_BYTES (2*KV_FLOATS*4)       // 72KB

template<bool MOSA>
__global__ __launch_bounds__(256, 2) void flash_fa2_kernel() {
    extern __shared__ float sm[];           // [2][KV_FLOATS]; buf0 doubles as Q stage

    int qt = MOSA ? blockIdx.x : (gridDim.x - 1 - blockIdx.x);
    int n = blockIdx.y, b = blockIdx.z;
    int bn = b*NHM + n;
    int tid = threadIdx.x;
    int w = tid >> 5, lane = tid & 31;
    int lq = lane >> 2, lr = lane & 3;
    const int RS = MOSA ? QKV3 : NHD*QKV3;
    const float* src = MOSA ? d_mqkv : d_dqkv;
    int row0 = w*16;
    int gr0 = qt*128 + row0 + lq;
    int gr1 = gr0 + 8;

    // ---- stage Q (RN-converted) through buffer0, extract per-warp fragments
    for (int s = tid; s < 2048; s += 256) {
        int r = s >> 4, c4 = (s & 15)*4;
        size_t base = MOSA ? ((size_t)(bn*KSEL + qt*128 + r))*QKV3
                           : ((size_t)(b*TT + qt*128 + r))*RS + n*QKV3;
        float4 v = *(const float4*)(src + base + c4);
        sm[r*FK_LD + c4+0] = f2tf32(v.x);
        sm[r*FK_LD + c4+1] = f2tf32(v.y);
        sm[r*FK_LD + c4+2] = f2tf32(v.z);
        sm[r*FK_LD + c4+3] = f2tf32(v.w);
    }
    __syncthreads();
    unsigned qf[8][4];
    #pragma unroll
    for (int k = 0; k < 8; k++) {
        qf[k][0] = __float_as_uint(sm[(row0 + lq)*FK_LD + k*8 + lr]);
        qf[k][1] = __float_as_uint(sm[(row0 + 8 + lq)*FK_LD + k*8 + lr]);
        qf[k][2] = __float_as_uint(sm[(row0 + lq)*FK_LD + k*8 + lr + 4]);
        qf[k][3] = __float_as_uint(sm[(row0 + 8 + lq)*FK_LD + k*8 + lr + 4]);
    }
    __syncthreads();   // Q reads done before cp.async overwrites buffer0

    // ---- cp.async K/V tile loader (raw fp32; tf32 MMA reads high bits) ----
    auto issue_kv = [&](int kt, int bi) {
        float* Ks = sm + bi*KV_FLOATS;
        float* Vs = Ks + 64*FK_LD;
        #pragma unroll
        for (int i = 0; i < 4; i++) {
            int s = tid + i*256;
            int r = s >> 4, c4 = (s & 15)*4;
            size_t base = MOSA ? ((size_t)(bn*KSEL + kt*64 + r))*QKV3
                               : ((size_t)(b*TT + kt*64 + r))*RS + n*QKV3;
            unsigned kd = (unsigned)__cvta_generic_to_shared(&Ks[r*FK_LD + c4]);
            unsigned vd = (unsigned)__cvta_generic_to_shared(&Vs[r*FV_LD + c4]);
            asm volatile("cp.async.cg.shared.global [%0], [%1], 16;"
                         :: "r"(kd), "l"(src + base + 64 + c4));
            asm volatile("cp.async.cg.shared.global [%0], [%1], 16;"
                         :: "r"(vd), "l"(src + base + 128 + c4));
        }
        asm volatile("cp.async.commit_group;");
    };

    float o[8][4];
    #pragma unroll
    for (int ni = 0; ni < 8; ni++)
        #pragma unroll
        for (int e = 0; e < 4; e++) o[ni][e] = 0.f;
    float m0 = NEGINF, m1 = NEGINF, l0 = 0.f, l1 = 0.f;

    int nkt = 2*qt + 2;
    issue_kv(0, 0);
    for (int kt = 0; kt < nkt; kt++) {
        asm volatile("cp.async.wait_group 0;" ::: "memory");
        __syncthreads();   // tile kt visible to all; prev-iter compute done
        if (kt + 1 < nkt) issue_kv(kt+1, (kt+1) & 1);

        const float* Ks = sm + (kt & 1)*KV_FLOATS;
        const float* Vs = Ks + 64*FK_LD;

        // ---- S = Q K^T (Q from registers) ----
        float sacc[8][4];
        #pragma unroll
        for (int ni = 0; ni < 8; ni++)
            #pragma unroll
            for (int e = 0; e < 4; e++) sacc[ni][e] = 0.f;
        #pragma unroll
        for (int k = 0; k < 8; k++) {
            #pragma unroll
            for (int ni = 0; ni < 8; ni++) {
                unsigned b0 = __float_as_uint(Ks[(ni*8 + lq)*FK_LD + k*8 + lr]);
                unsigned b1 = __float_as_uint(Ks[(ni*8 + lq)*FK_LD + k*8 + lr + 4]);
                mma_tf32(sacc[ni], qf[k], b0, b1);
            }
        }

        // ---- online softmax; P kept in registers, tf32-rounded ----
        int cbase = kt*64 + 2*lr;
        float mx0 = NEGINF, mx1 = NEGINF;
        #pragma unroll
        for (int ni = 0; ni < 8; ni++) {
            int c0 = cbase + ni*8, c1 = c0 + 1;
            float s00 = (c0 <= gr0) ? sacc[ni][0]*0.125f : NEGINF;
            float s01 = (c1 <= gr0) ? sacc[ni][1]*0.125f : NEGINF;
            float s10 = (c0 <= gr1) ? sacc[ni][2]*0.125f : NEGINF;
            float s11 = (c1 <= gr1) ? sacc[ni][3]*0.125f : NEGINF;
            sacc[ni][0] = s00; sacc[ni][1] = s01;
            sacc[ni][2] = s10; sacc[ni][3] = s11;
            mx0 = fmaxf(mx0, fmaxf(s00, s01));
            mx1 = fmaxf(mx1, fmaxf(s10, s11));
        }
        mx0 = fmaxf(mx0, __shfl_xor_sync(0xffffffffu, mx0, 1));
        mx0 = fmaxf(mx0, __shfl_xor_sync(0xffffffffu, mx0, 2));
        mx1 = fmaxf(mx1, __shfl_xor_sync(0xffffffffu, mx1, 1));
        mx1 = fmaxf(mx1, __shfl_xor_sync(0xffffffffu, mx1, 2));
        float mn0 = fmaxf(m0, mx0), mn1 = fmaxf(m1, mx1);
        float al0 = __expf(m0 - mn0), al1 = __expf(m1 - mn1);
        float ps0 = 0.f, ps1 = 0.f;
        #pragma unroll
        for (int ni = 0; ni < 8; ni++) {
            float p00 = __expf(sacc[ni][0] - mn0);
            float p01 = __expf(sacc[ni][1] - mn0);
            float p10 = __expf(sacc[ni][2] - mn1);
            float p11 = __expf(sacc[ni][3] - mn1);
            ps0 += p00 + p01;
            ps1 += p10 + p11;
            sacc[ni][0] = f2tf32(p00);
            sacc[ni][1] = f2tf32(p01);
            sacc[ni][2] = f2tf32(p10);
            sacc[ni][3] = f2tf32(p11);
        }
        ps0 += __shfl_xor_sync(0xffffffffu, ps0, 1);
        ps0 += __shfl_xor_sync(0xffffffffu, ps0, 2);
        ps1 += __shfl_xor_sync(0xffffffffu, ps1, 1);
        ps1 += __shfl_xor_sync(0xffffffffu, ps1, 2);
        l0 = l0*al0 + ps0;  m0 = mn0;
        l1 = l1*al1 + ps1;  m1 = mn1;
        #pragma unroll
        for (int ni = 0; ni < 8; ni++) {
            o[ni][0] *= al0; o[ni][1] *= al0;
            o[ni][2] *= al1; o[ni][3] *= al1;
        }

        // ---- O += P V : P A-fragments built by lane shuffle ----
        int srcA = (lane & 28) | (lr >> 1);
        int srcB = srcA + 2;
        bool odd = (lr & 1);
        #pragma unroll
        for (int k = 0; k < 8; k++) {
            float v00a = __shfl_sync(0xffffffffu, sacc[k][0], srcA);
            float v01a = __shfl_sync(0xffffffffu, sacc[k][1], srcA);
            float v10a = __shfl_sync(0xffffffffu, sacc[k][2], srcA);
            float v11a = __shfl_sync(0xffffffffu, sacc[k][3], srcA);
            float v00b = __shfl_sync(0xffffffffu, sacc[k][0], srcB);
            float v01b = __shfl_sync(0xffffffffu, sacc[k][1], srcB);
            float v10b = __shfl_sync(0xffffffffu, sacc[k][2], srcB);
            float v11b = __shfl_sync(0xffffffffu, sacc[k][3], srcB);
            unsigned af[4];
            af[0] = __float_as_uint(odd ? v01a : v00a);
            af[1] = __float_as_uint(odd ? v11a : v10a);
            af[2] = __float_as_uint(odd ? v01b : v00b);
            af[3] = __float_as_uint(odd ? v11b : v10b);
            #pragma unroll
            for (int ni = 0; ni < 8; ni++) {
                unsigned b0 = __float_as_uint(Vs[(k*8 + lr)*FV_LD + ni*8 + lq]);
                unsigned b1 = __float_as_uint(Vs[(k*8 + lr + 4)*FV_LD + ni*8 + lq]);
                mma_tf32(o[ni], af, b0, b1);
            }
        }
        // buffer (kt&1) is only rewritten by issue at iter kt+1, which is
        // after that iteration's top-of-loop sync => no trailing sync needed.
    }

    if (MOSA) {
        int tok0 = d_idx[bn*KSEL + gr0];
        int tok1 = d_idx[bn*KSEL + gr1];
        float s0 = d_gates[bn*KSEL + gr0] / l0;
        float s1 = d_gates[bn*KSEL + gr1] / l1;
        #pragma unroll
        for (int ni = 0; ni < 8; ni++) {
            int c = n*64 + ni*8 + 2*lr;
            *(float2*)&d_Y[((size_t)(b*TT + tok0))*1024 + c] =
                make_float2(o[ni][0]*s0, o[ni][1]*s0);
            *(float2*)&d_Y[((size_t)(b*TT + tok1))*1024 + c] =
                make_float2(o[ni][2]*s1, o[ni][3]*s1);
        }
    } else {
        float s0 = 1.f/l0, s1 = 1.f/l1;
        #pragma unroll
        for (int ni = 0; ni < 8; ni++) {
            int c = 512 + n*64 + ni*8 + 2*lr;
            *(float2*)&d_Y[((size_t)(b*TT + gr0))*1024 + c] =
                make_float2(o[ni][0]*s0, o[ni][1]*s0);
            *(float2*)&d_Y[((size_t)(b*TT + gr1))*1024 + c] =
                make_float2(o[ni][2]*s1, o[ni][3]*s1);
        }
    }
}

// ---------------- launch: fork-join graph ----------------
extern "C" void kernel_launch(void* const* d_in, const int* in_sizes, int n_in,
                              void* d_out, int out_size) {
    const float* X     = (const float*)d_in[0];
    const float* rw    = (const float*)d_in[1];
    const float* mwqkv = (const float*)d_in[2];
    const float* mwo   = (const float*)d_in[3];
    const float* dwqkv = (const float*)d_in[4];
    const float* dwo   = (const float*)d_in[5];
    float* out = (float*)d_out;

    static cudaStream_t sB = nullptr;
    static cudaEvent_t eFork = nullptr, eJoin = nullptr;
    if (sB == nullptr) {
        cudaStreamCreateWithFlags(&sB, cudaStreamNonBlocking);
        cudaEventCreateWithFlags(&eFork, cudaEventDisableTiming);
        cudaEventCreateWithFlags(&eJoin, cudaEventDisableTiming);
        cudaFuncSetAttribute(flash_fa2_kernel<false>,
            cudaFuncAttributeMaxDynamicSharedMemorySize, FL_SMEM_BYTES);
        cudaFuncSetAttribute(flash_fa2_kernel<true>,
            cudaFuncAttributeMaxDynamicSharedMemorySize, FL_SMEM_BYTES);
    }

    cudaEventRecord(eFork, 0);
    cudaStreamWaitEvent(sB, eFork, 0);

    // ---- branch A (default stream): mosa chain + mosa half of final ----
    zeroY_kernel<<<ZERO_BLOCKS, 256>>>();
    router_kernel<<<dim3(TT, BB), 256>>>(X, rw);
    topk_kernel<<<BB*NHM, 1024>>>();
    mosa_qkv_wmma_kernel<<<dim3(3, 4, 2*BB*NHM), 256>>>(X, mwqkv);
    mosa_rope_kernel<<<256, 256>>>();
    flash_fa2_kernel<true><<<dim3(2, NHM, BB), 256, FL_SMEM_BYTES>>>();
    final_half_kernel<false><<<dim3(8, 32), 256>>>(mwo, out, 0);   // out = Ym@mwo

    // ---- branch B (side stream): dense chain ----
    dense_qkv_wmma_kernel<<<dim3(12, 32), 256, 0, sB>>>(X, dwqkv);
    dense_rope_kernel<<<2048, 256, 0, sB>>>();
    flash_fa2_kernel<false><<<dim3(16, NHD, BB), 256, FL_SMEM_BYTES, sB>>>();

    // join, then add dense half of final
    cudaEventRecord(eJoin, sB);
    cudaStreamWaitEvent(0, eJoin, 0);
    final_half_kernel<true><<<dim3(8, 32), 256>>>(dwo, out, 512);  // out += Yd@dwo
}